// round 7
// baseline (speedup 1.0000x reference)
#include <cuda_runtime.h>
#include <cuda_bf16.h>
#include <mma.h>
#include <cstdint>
#include <math.h>

using namespace nvcuda;

#define B_  2
#define S_  2048
#define D_  1024
#define H_  16
#define HD_ 64
#define NQ (B_*S_*D_)     // 4194304 (one of q/k/v)
#define NW (D_*D_)        // 1048576 (one weight)
#define NP (B_*H_*S_*HD_) // 4194304 (projected tensor)

// Pre-split inputs: [q,k,v, wq,wk,wv] hi and lo bf16.
__device__ __nv_bfloat16 g_Ih[3*NQ + 3*NW];
__device__ __nv_bfloat16 g_Il[3*NQ + 3*NW];
// Projected Q/K/V, split bf16, [b,h,s,hd]:
__device__ __nv_bfloat16 g_Qh[NP], g_Ql[NP];
__device__ __nv_bfloat16 g_Kh[NP], g_Kl[NP];
__device__ __nv_bfloat16 g_Vh[NP], g_Vl[NP];
__device__ float g_V[NP];   // fp32 V for suffix sums
__device__ float g_S[NP];   // SufV[bh][q][d] = sum_{k>q} V[bh][k][d]

// ---------------------------------------------------------------------------
// helpers
// ---------------------------------------------------------------------------
__device__ __forceinline__ uint32_t smem_u32(const void* p) {
    uint32_t a;
    asm("{ .reg .u64 t; cvta.to.shared.u64 t, %1; cvt.u32.u64 %0, t; }"
        : "=r"(a) : "l"(p));
    return a;
}
#define CP_ASYNC16(dst, src) \
    asm volatile("cp.async.cg.shared.global [%0], [%1], 16;" :: "r"(dst), "l"(src))
#define CP_COMMIT() asm volatile("cp.async.commit_group;")
#define CP_WAIT(n)  asm volatile("cp.async.wait_group %0;" :: "n"(n))

__device__ __forceinline__ void split4(float4 a, uint2& hv, uint2& lv) {
    __nv_bfloat16 h0 = __float2bfloat16(a.x);
    __nv_bfloat16 h1 = __float2bfloat16(a.y);
    __nv_bfloat16 h2 = __float2bfloat16(a.z);
    __nv_bfloat16 h3 = __float2bfloat16(a.w);
    __nv_bfloat16 l0 = __float2bfloat16(a.x - __bfloat162float(h0));
    __nv_bfloat16 l1 = __float2bfloat16(a.y - __bfloat162float(h1));
    __nv_bfloat16 l2 = __float2bfloat16(a.z - __bfloat162float(h2));
    __nv_bfloat16 l3 = __float2bfloat16(a.w - __bfloat162float(h3));
    hv = make_uint2(((uint32_t)__bfloat16_as_ushort(h1) << 16) | __bfloat16_as_ushort(h0),
                    ((uint32_t)__bfloat16_as_ushort(h3) << 16) | __bfloat16_as_ushort(h2));
    lv = make_uint2(((uint32_t)__bfloat16_as_ushort(l1) << 16) | __bfloat16_as_ushort(l0),
                    ((uint32_t)__bfloat16_as_ushort(l3) << 16) | __bfloat16_as_ushort(l2));
}

// Fast exp on the FMA pipe; rel err ~2.4e-6.
__device__ __forceinline__ float fexp(float s) {
    float x = s * 1.4426950408889634f;
    float j = x + 12582912.0f;
    float xi = j - 12582912.0f;
    float f = x - xi;
    int e = __float_as_int(j) - 0x4B400000;
    float p = 1.3333558e-3f;
    p = fmaf(p, f, 9.6181291e-3f);
    p = fmaf(p, f, 5.5504109e-2f);
    p = fmaf(p, f, 2.4022651e-1f);
    p = fmaf(p, f, 6.9314718e-1f);
    p = fmaf(p, f, 1.0f);
    return p * __int_as_float((e + 127) << 23);
}

// ---------------------------------------------------------------------------
// Pre-split all 6 input tensors into bf16 hi/lo (memory-bound).
// ---------------------------------------------------------------------------
__global__ __launch_bounds__(256) void presplit_kernel(
    const float* __restrict__ q, const float* __restrict__ k,
    const float* __restrict__ v, const float* __restrict__ wq,
    const float* __restrict__ wk, const float* __restrict__ wv)
{
    const int t = blockIdx.y;
    const float* src = (t == 0) ? q : (t == 1) ? k : (t == 2) ? v
                     : (t == 3) ? wq : (t == 4) ? wk : wv;
    const size_t off = (t < 3) ? (size_t)t * NQ : 3 * (size_t)NQ + (size_t)(t - 3) * NW;
    const int n4 = ((t < 3) ? NQ : NW) >> 2;
    uint2* dh = (uint2*)(g_Ih + off);
    uint2* dl = (uint2*)(g_Il + off);
    for (int i = blockIdx.x * blockDim.x + threadIdx.x; i < n4;
         i += gridDim.x * blockDim.x) {
        float4 a = ((const float4*)src)[i];
        uint2 hv, lv; split4(a, hv, lv);
        dh[i] = hv; dl[i] = lv;
    }
}

// ===========================================================================
// Projection GEMM on HMMA, inputs pre-split, cp.async double-buffered.
//   out = Ah.Wh^T + Ah.Wl^T + Al.Wh^T (fp32 acc). Tile 128x128, BK=32.
// Epilogue splits outputs to bf16 hi/lo [b,h,s,hd] (+ fp32 V for z==2).
// ===========================================================================
#define BK 32
#define LDA 40                       // bf16 per smem row (32 + 8 pad); 80B rows
#define ARR_B (128 * LDA * 2)        // 10240 bytes per tile array
#define STAGE_B (4 * ARR_B)          // 40960 bytes per stage
#define PROJ_SMEM (2 * STAGE_B)      // 81920

__global__ __launch_bounds__(256) void proj_wmma_kernel()
{
    extern __shared__ char smem[];
    const int z = blockIdx.z;
    const __nv_bfloat16* Ah_g = g_Ih + (size_t)z * NQ;
    const __nv_bfloat16* Al_g = g_Il + (size_t)z * NQ;
    const __nv_bfloat16* Wh_g = g_Ih + 3 * (size_t)NQ + (size_t)z * NW;
    const __nv_bfloat16* Wl_g = g_Il + 3 * (size_t)NQ + (size_t)z * NW;

    const int tid = threadIdx.x;
    const int wid = tid >> 5;
    const int warp_m = wid >> 1;
    const int warp_n = wid & 1;
    const int m0 = blockIdx.y * 128;
    const int n0 = blockIdx.x * 128;
    const uint32_t sbase = smem_u32(smem);

    // chunk mapping for cp.async: 512 16B-chunks per array, 2 per thread.
    const int ci0 = tid, ci1 = tid + 256;
    const int r0 = ci0 >> 2, c0 = ci0 & 3;
    const int r1 = ci1 >> 2, c1 = ci1 & 3;

    auto issue = [&](int stage, int c) {
        const int k0 = c * BK;
        uint32_t sb = sbase + stage * STAGE_B;
        const __nv_bfloat16* gp[4] = {
            Ah_g + (size_t)(m0 + 0) * D_ + k0,
            Al_g + (size_t)(m0 + 0) * D_ + k0,
            Wh_g + (size_t)(n0 + 0) * D_ + k0,
            Wl_g + (size_t)(n0 + 0) * D_ + k0 };
        #pragma unroll
        for (int a = 0; a < 4; a++) {
            CP_ASYNC16(sb + a * ARR_B + r0 * 80 + c0 * 16,
                       gp[a] + (size_t)r0 * D_ + c0 * 8);
            CP_ASYNC16(sb + a * ARR_B + r1 * 80 + c1 * 16,
                       gp[a] + (size_t)r1 * D_ + c1 * 8);
        }
        CP_COMMIT();
    };

    wmma::fragment<wmma::accumulator, 16, 16, 16, float> acc[2][4];
    #pragma unroll
    for (int i = 0; i < 2; i++)
        #pragma unroll
        for (int j = 0; j < 4; j++) wmma::fill_fragment(acc[i][j], 0.0f);

    issue(0, 0);

    for (int c = 0; c < D_ / BK; c++) {
        if (c < D_ / BK - 1) { issue((c + 1) & 1, c + 1); CP_WAIT(1); }
        else                 { CP_WAIT(0); }
        __syncthreads();

        const char* st = smem + (c & 1) * STAGE_B;
        const __nv_bfloat16* Ahs = (const __nv_bfloat16*)(st);
        const __nv_bfloat16* Als = (const __nv_bfloat16*)(st + ARR_B);
        const __nv_bfloat16* Whs = (const __nv_bfloat16*)(st + 2 * ARR_B);
        const __nv_bfloat16* Wls = (const __nv_bfloat16*)(st + 3 * ARR_B);

        #pragma unroll
        for (int kk = 0; kk < BK; kk += 16) {
            wmma::fragment<wmma::matrix_a, 16, 16, 16, __nv_bfloat16, wmma::row_major> aH[2], aL[2];
            wmma::fragment<wmma::matrix_b, 16, 16, 16, __nv_bfloat16, wmma::col_major> bH[4], bL[4];
            #pragma unroll
            for (int i = 0; i < 2; i++) {
                wmma::load_matrix_sync(aH[i], &Ahs[(warp_m * 32 + i * 16) * LDA + kk], LDA);
                wmma::load_matrix_sync(aL[i], &Als[(warp_m * 32 + i * 16) * LDA + kk], LDA);
            }
            #pragma unroll
            for (int j = 0; j < 4; j++) {
                wmma::load_matrix_sync(bH[j], &Whs[(warp_n * 64 + j * 16) * LDA + kk], LDA);
                wmma::load_matrix_sync(bL[j], &Wls[(warp_n * 64 + j * 16) * LDA + kk], LDA);
            }
            #pragma unroll
            for (int i = 0; i < 2; i++)
                #pragma unroll
                for (int j = 0; j < 4; j++) {
                    wmma::mma_sync(acc[i][j], aH[i], bH[j], acc[i][j]);
                    wmma::mma_sync(acc[i][j], aH[i], bL[j], acc[i][j]);
                    wmma::mma_sync(acc[i][j], aL[i], bH[j], acc[i][j]);
                }
        }
        __syncthreads();
    }

    // Epilogue: stage fp32 result in smem, split to bf16 hi/lo gmem.
    float* st = (float*)smem;   // 128 x 132
    #pragma unroll
    for (int i = 0; i < 2; i++)
        #pragma unroll
        for (int j = 0; j < 4; j++)
            wmma::store_matrix_sync(&st[(warp_m * 32 + i * 16) * 132 + warp_n * 64 + j * 16],
                                    acc[i][j], 132, wmma::mem_row_major);
    __syncthreads();

    __nv_bfloat16* outh = (z == 0) ? g_Qh : (z == 1) ? g_Kh : g_Vh;
    __nv_bfloat16* outl = (z == 0) ? g_Ql : (z == 1) ? g_Kl : g_Vl;
    const int b = m0 >> 11;
    #pragma unroll
    for (int it = 0; it < 16; it++) {
        int idx = it * 256 + tid;        // 0..4095 float4 slots
        int r = idx >> 5, c4 = idx & 31;
        float4 val = *reinterpret_cast<const float4*>(&st[r * 132 + c4 * 4]);
        uint2 hv, lv; split4(val, hv, lv);
        int m = m0 + r;
        int s = m & (S_ - 1);
        int n = n0 + c4 * 4;
        int h = n >> 6, d0 = n & 63;
        size_t o = ((size_t)(b * H_ + h) * S_ + s) * HD_ + d0;
        *reinterpret_cast<uint2*>(outh + o) = hv;
        *reinterpret_cast<uint2*>(outl + o) = lv;
        if (z == 2) *reinterpret_cast<float4*>(g_V + o) = val;
    }
}

// ---------------------------------------------------------------------------
// Fused suffix sums of V: one block per bh, 1024 threads (64 d x 16 groups).
// ---------------------------------------------------------------------------
__global__ __launch_bounds__(1024) void suffix_kernel()
{
    __shared__ float part[16][64];
    const int bh = blockIdx.x;
    const int d = threadIdx.x & 63;
    const int g = threadIdx.x >> 6;
    const float* Vp = g_V + (size_t)bh * S_ * HD_ + d;
    float* Sp = g_S + (size_t)bh * S_ * HD_ + d;
    const int row0 = g * 128;

    float acc = 0.f;
    #pragma unroll 8
    for (int s = 0; s < 128; s++) acc += Vp[(size_t)(row0 + s) * HD_];
    part[g][d] = acc;
    __syncthreads();

    float base = 0.f;
    #pragma unroll
    for (int gg = g + 1; gg < 16; gg++) base += part[gg][d];
    for (int s = 127; s >= 0; s--) {
        Sp[(size_t)(row0 + s) * HD_] = base;
        base += Vp[(size_t)(row0 + s) * HD_];
    }
}

// ===========================================================================
// Attention on wmma bf16, all operands pre-split (pure copies into smem):
//   S = Qh.Kh + Qh.Kl + Ql.Kh ; P = exp(S/8) masked ; split P
//   O += Ph.Vh + Ph.Vl + Pl.Vh
// Zero-mask reference => m=0 stabilizer + analytic tail via SufV.
// qt order reversed (heavy blocks first) for wave balance.
// ===========================================================================
#define ATT_LD 72
#define SS_LD  68
#define ATT_SMEM (8*64*ATT_LD*2 + 64*SS_LD*4 + 64*4 + 128)

__global__ __launch_bounds__(256) void attn_wmma_kernel(float* __restrict__ out)
{
    extern __shared__ char smem_raw[];
    __nv_bfloat16* Qh = (__nv_bfloat16*)smem_raw;
    __nv_bfloat16* Ql = Qh + 64 * ATT_LD;
    __nv_bfloat16* Kh = Ql + 64 * ATT_LD;
    __nv_bfloat16* Kl = Kh + 64 * ATT_LD;
    __nv_bfloat16* Ph = Kl + 64 * ATT_LD;
    __nv_bfloat16* Pl = Ph + 64 * ATT_LD;
    __nv_bfloat16* Vh = Pl + 64 * ATT_LD;
    __nv_bfloat16* Vl = Vh + 64 * ATT_LD;
    float* Ss = (float*)(Vl + 64 * ATT_LD);
    float* Zs = Ss + 64 * SS_LD;

    const int tid = threadIdx.x;
    const int wid = tid >> 5;
    const int qt = (int)gridDim.x - 1 - (int)blockIdx.x;   // heavy first
    const int bh = blockIdx.y;
    const size_t bho = (size_t)bh * S_ * HD_;

    // chunk mapping: 512 16B-chunks per 64x64 bf16 tile, 2 per thread.
    const int r0 = tid >> 3, c0 = tid & 7;
    const int r1 = (tid + 256) >> 3, c1 = (tid + 256) & 7;

    // Load Q tile (hi/lo), pure copy.
    {
        const __nv_bfloat16* qh = g_Qh + bho + (size_t)qt * 64 * HD_;
        const __nv_bfloat16* ql = g_Ql + bho + (size_t)qt * 64 * HD_;
        *(uint4*)((char*)Qh + r0 * 144 + c0 * 16) = *(const uint4*)(qh + r0 * 64 + c0 * 8);
        *(uint4*)((char*)Qh + r1 * 144 + c1 * 16) = *(const uint4*)(qh + r1 * 64 + c1 * 8);
        *(uint4*)((char*)Ql + r0 * 144 + c0 * 16) = *(const uint4*)(ql + r0 * 64 + c0 * 8);
        *(uint4*)((char*)Ql + r1 * 144 + c1 * 16) = *(const uint4*)(ql + r1 * 64 + c1 * 8);
    }
    if (tid < 64) Zs[tid] = 0.f;

    wmma::fragment<wmma::accumulator, 16, 16, 16, float> ofrag[2];
    wmma::fill_fragment(ofrag[0], 0.f);
    wmma::fill_fragment(ofrag[1], 0.f);

    const int qrow = (wid >> 1) * 16;
    const int kcol = (wid & 1) * 32;
    __syncthreads();

    for (int kt = 0; kt <= qt; kt++) {
        // Load K, V tiles (hi/lo), pure copies.
        {
            const size_t to = bho + (size_t)kt * 64 * HD_;
            const __nv_bfloat16* kh = g_Kh + to;
            const __nv_bfloat16* kl = g_Kl + to;
            const __nv_bfloat16* vh = g_Vh + to;
            const __nv_bfloat16* vl = g_Vl + to;
            *(uint4*)((char*)Kh + r0 * 144 + c0 * 16) = *(const uint4*)(kh + r0 * 64 + c0 * 8);
            *(uint4*)((char*)Kh + r1 * 144 + c1 * 16) = *(const uint4*)(kh + r1 * 64 + c1 * 8);
            *(uint4*)((char*)Kl + r0 * 144 + c0 * 16) = *(const uint4*)(kl + r0 * 64 + c0 * 8);
            *(uint4*)((char*)Kl + r1 * 144 + c1 * 16) = *(const uint4*)(kl + r1 * 64 + c1 * 8);
            *(uint4*)((char*)Vh + r0 * 144 + c0 * 16) = *(const uint4*)(vh + r0 * 64 + c0 * 8);
            *(uint4*)((char*)Vh + r1 * 144 + c1 * 16) = *(const uint4*)(vh + r1 * 64 + c1 * 8);
            *(uint4*)((char*)Vl + r0 * 144 + c0 * 16) = *(const uint4*)(vl + r0 * 64 + c0 * 8);
            *(uint4*)((char*)Vl + r1 * 144 + c1 * 16) = *(const uint4*)(vl + r1 * 64 + c1 * 8);
        }
        __syncthreads();

        // S = Q.K^T, split 3-term.
        wmma::fragment<wmma::accumulator, 16, 16, 16, float> sfrag[2];
        wmma::fill_fragment(sfrag[0], 0.f);
        wmma::fill_fragment(sfrag[1], 0.f);
        #pragma unroll
        for (int kk = 0; kk < 64; kk += 16) {
            wmma::fragment<wmma::matrix_a, 16, 16, 16, __nv_bfloat16, wmma::row_major> aH, aL;
            wmma::load_matrix_sync(aH, &Qh[qrow * ATT_LD + kk], ATT_LD);
            wmma::load_matrix_sync(aL, &Ql[qrow * ATT_LD + kk], ATT_LD);
            #pragma unroll
            for (int c = 0; c < 2; c++) {
                wmma::fragment<wmma::matrix_b, 16, 16, 16, __nv_bfloat16, wmma::col_major> bH, bL;
                wmma::load_matrix_sync(bH, &Kh[(kcol + c * 16) * ATT_LD + kk], ATT_LD);
                wmma::load_matrix_sync(bL, &Kl[(kcol + c * 16) * ATT_LD + kk], ATT_LD);
                wmma::mma_sync(sfrag[c], aH, bH, sfrag[c]);
                wmma::mma_sync(sfrag[c], aH, bL, sfrag[c]);
                wmma::mma_sync(sfrag[c], aL, bH, sfrag[c]);
            }
        }
        wmma::store_matrix_sync(&Ss[qrow * SS_LD + kcol], sfrag[0], SS_LD, wmma::mem_row_major);
        wmma::store_matrix_sync(&Ss[qrow * SS_LD + kcol + 16], sfrag[1], SS_LD, wmma::mem_row_major);
        __syncthreads();

        // p = exp(s/8) (masked -> 0); accumulate Z; write split P.
        {
            const int r = tid >> 2;
            const int c0e = (tid & 3) * 16;
            const int qglob = qt * 64 + r;
            const int kglob0 = kt * 64 + c0e;
            const bool diag = (kt == qt);
            float rs = 0.f;
            #pragma unroll
            for (int j = 0; j < 16; j++) {
                float s = Ss[r * SS_LD + c0e + j] * 0.125f;
                bool okv = !diag || (kglob0 + j <= qglob);
                float p = okv ? fexp(s) : 0.f;
                rs += p;
                __nv_bfloat16 ph = __float2bfloat16(p);
                __nv_bfloat16 pl = __float2bfloat16(p - __bfloat162float(ph));
                Ph[r * ATT_LD + c0e + j] = ph;
                Pl[r * ATT_LD + c0e + j] = pl;
            }
            rs += __shfl_xor_sync(0xffffffffu, rs, 1);
            rs += __shfl_xor_sync(0xffffffffu, rs, 2);
            if ((tid & 3) == 0) Zs[r] += rs;
        }
        __syncthreads();

        // O += Ph.Vh + Ph.Vl + Pl.Vh
        #pragma unroll
        for (int kk = 0; kk < 64; kk += 16) {
            wmma::fragment<wmma::matrix_a, 16, 16, 16, __nv_bfloat16, wmma::row_major> apH, apL;
            wmma::load_matrix_sync(apH, &Ph[qrow * ATT_LD + kk], ATT_LD);
            wmma::load_matrix_sync(apL, &Pl[qrow * ATT_LD + kk], ATT_LD);
            #pragma unroll
            for (int c = 0; c < 2; c++) {
                wmma::fragment<wmma::matrix_b, 16, 16, 16, __nv_bfloat16, wmma::row_major> bvH, bvL;
                wmma::load_matrix_sync(bvH, &Vh[kk * ATT_LD + kcol + c * 16], ATT_LD);
                wmma::load_matrix_sync(bvL, &Vl[kk * ATT_LD + kcol + c * 16], ATT_LD);
                wmma::mma_sync(ofrag[c], apH, bvH, ofrag[c]);
                wmma::mma_sync(ofrag[c], apH, bvL, ofrag[c]);
                wmma::mma_sync(ofrag[c], apL, bvH, ofrag[c]);
            }
        }
        __syncthreads();
    }

    // Stage O, then epilogue: add suffix tail, normalize, store.
    wmma::store_matrix_sync(&Ss[qrow * SS_LD + kcol], ofrag[0], SS_LD, wmma::mem_row_major);
    wmma::store_matrix_sync(&Ss[qrow * SS_LD + kcol + 16], ofrag[1], SS_LD, wmma::mem_row_major);
    __syncthreads();

    const int b = bh / H_, h = bh % H_;
    const float* Sufp = g_S + bho;
    {
        const int r = tid >> 2;
        const int c0e = (tid & 3) * 16;
        const int q = qt * 64 + r;
        float Zr = Zs[r] + (float)(S_ - 1 - q);
        float inv = 1.f / Zr;
        float* dst = out + ((size_t)(b * S_ + q)) * D_ + h * HD_ + c0e;
        const float* suf = &Sufp[(size_t)q * HD_ + c0e];
        #pragma unroll
        for (int j = 0; j < 16; j += 4) {
            float4 sv = *reinterpret_cast<const float4*>(&suf[j]);
            float4 ov = make_float4(
                (Ss[r * SS_LD + c0e + j + 0] + sv.x) * inv,
                (Ss[r * SS_LD + c0e + j + 1] + sv.y) * inv,
                (Ss[r * SS_LD + c0e + j + 2] + sv.z) * inv,
                (Ss[r * SS_LD + c0e + j + 3] + sv.w) * inv);
            *reinterpret_cast<float4*>(&dst[j]) = ov;
        }
    }
}

// ---------------------------------------------------------------------------
extern "C" void kernel_launch(void* const* d_in, const int* in_sizes, int n_in,
                              void* d_out, int out_size)
{
    const float* q  = (const float*)d_in[0];
    const float* k  = (const float*)d_in[1];
    const float* v  = (const float*)d_in[2];
    const float* wq = (const float*)d_in[3];
    const float* wk = (const float*)d_in[4];
    const float* wv = (const float*)d_in[5];
    float* out = (float*)d_out;

    presplit_kernel<<<dim3(256, 6), 256>>>(q, k, v, wq, wk, wv);

    cudaFuncSetAttribute(proj_wmma_kernel,
                         cudaFuncAttributeMaxDynamicSharedMemorySize, PROJ_SMEM);
    proj_wmma_kernel<<<dim3(D_ / 128, (B_ * S_) / 128, 3), 256, PROJ_SMEM>>>();

    suffix_kernel<<<B_ * H_, 1024>>>();

    cudaFuncSetAttribute(attn_wmma_kernel,
                         cudaFuncAttributeMaxDynamicSharedMemorySize, ATT_SMEM);
    attn_wmma_kernel<<<dim3(S_ / 64, B_ * H_), 256, ATT_SMEM>>>(out);
}

// round 8
// speedup vs baseline: 1.6254x; 1.6254x over previous
#include <cuda_runtime.h>
#include <cuda_bf16.h>
#include <mma.h>
#include <cstdint>
#include <math.h>

using namespace nvcuda;

#define B_  2
#define S_  2048
#define D_  1024
#define H_  16
#define HD_ 64
#define NQ (B_*S_*D_)
#define NW (D_*D_)
#define NP (B_*H_*S_*HD_)

// Pre-split inputs: [q,k,v, wq,wk,wv] hi and lo bf16.
__device__ __nv_bfloat16 g_Ih[3*NQ + 3*NW];
__device__ __nv_bfloat16 g_Il[3*NQ + 3*NW];
// Projected Q/K/V, split bf16, [b,h,s,hd]:
__device__ __nv_bfloat16 g_Qh[NP], g_Ql[NP];
__device__ __nv_bfloat16 g_Kh[NP], g_Kl[NP];
__device__ __nv_bfloat16 g_Vh[NP], g_Vl[NP];
__device__ float g_V[NP];   // fp32 V for suffix sums
__device__ float g_S[NP];   // SufV[bh][q][d] = sum_{k>q} V[bh][k][d]

// ---------------------------------------------------------------------------
__device__ __forceinline__ uint32_t smem_u32(const void* p) {
    uint32_t a;
    asm("{ .reg .u64 t; cvta.to.shared.u64 t, %1; cvt.u32.u64 %0, t; }"
        : "=r"(a) : "l"(p));
    return a;
}
#define CP_ASYNC16(dst, src) \
    asm volatile("cp.async.cg.shared.global [%0], [%1], 16;" :: "r"(dst), "l"(src))
#define CP_COMMIT() asm volatile("cp.async.commit_group;")
#define CP_WAIT(n)  asm volatile("cp.async.wait_group %0;" :: "n"(n))

__device__ __forceinline__ void split4(float4 a, uint2& hv, uint2& lv) {
    __nv_bfloat16 h0 = __float2bfloat16(a.x);
    __nv_bfloat16 h1 = __float2bfloat16(a.y);
    __nv_bfloat16 h2 = __float2bfloat16(a.z);
    __nv_bfloat16 h3 = __float2bfloat16(a.w);
    __nv_bfloat16 l0 = __float2bfloat16(a.x - __bfloat162float(h0));
    __nv_bfloat16 l1 = __float2bfloat16(a.y - __bfloat162float(h1));
    __nv_bfloat16 l2 = __float2bfloat16(a.z - __bfloat162float(h2));
    __nv_bfloat16 l3 = __float2bfloat16(a.w - __bfloat162float(h3));
    hv = make_uint2(((uint32_t)__bfloat16_as_ushort(h1) << 16) | __bfloat16_as_ushort(h0),
                    ((uint32_t)__bfloat16_as_ushort(h3) << 16) | __bfloat16_as_ushort(h2));
    lv = make_uint2(((uint32_t)__bfloat16_as_ushort(l1) << 16) | __bfloat16_as_ushort(l0),
                    ((uint32_t)__bfloat16_as_ushort(l3) << 16) | __bfloat16_as_ushort(l2));
}

// Fast exp on the FMA pipe; rel err ~2.4e-6.
__device__ __forceinline__ float fexp(float s) {
    float x = s * 1.4426950408889634f;
    float j = x + 12582912.0f;
    float xi = j - 12582912.0f;
    float f = x - xi;
    int e = __float_as_int(j) - 0x4B400000;
    float p = 1.3333558e-3f;
    p = fmaf(p, f, 9.6181291e-3f);
    p = fmaf(p, f, 5.5504109e-2f);
    p = fmaf(p, f, 2.4022651e-1f);
    p = fmaf(p, f, 6.9314718e-1f);
    p = fmaf(p, f, 1.0f);
    return p * __int_as_float((e + 127) << 23);
}

// ---------------------------------------------------------------------------
// Pre-split all 6 input tensors into bf16 hi/lo (memory-bound).
// ---------------------------------------------------------------------------
__global__ __launch_bounds__(256) void presplit_kernel(
    const float* __restrict__ q, const float* __restrict__ k,
    const float* __restrict__ v, const float* __restrict__ wq,
    const float* __restrict__ wk, const float* __restrict__ wv)
{
    const int t = blockIdx.y;
    const float* src = (t == 0) ? q : (t == 1) ? k : (t == 2) ? v
                     : (t == 3) ? wq : (t == 4) ? wk : wv;
    const size_t off = (t < 3) ? (size_t)t * NQ : 3 * (size_t)NQ + (size_t)(t - 3) * NW;
    const int n4 = ((t < 3) ? NQ : NW) >> 2;
    uint2* dh = (uint2*)(g_Ih + off);
    uint2* dl = (uint2*)(g_Il + off);
    for (int i = blockIdx.x * blockDim.x + threadIdx.x; i < n4;
         i += gridDim.x * blockDim.x) {
        float4 a = ((const float4*)src)[i];
        uint2 hv, lv; split4(a, hv, lv);
        dh[i] = hv; dl[i] = lv;
    }
}

// ===========================================================================
// Projection GEMM on HMMA, inputs pre-split, cp.async double-buffered.
// ===========================================================================
#define BK 32
#define LDA 40
#define ARR_B (128 * LDA * 2)
#define STAGE_B (4 * ARR_B)
#define PROJ_SMEM (2 * STAGE_B)

__global__ __launch_bounds__(256) void proj_wmma_kernel()
{
    extern __shared__ char smem[];
    const int z = blockIdx.z;
    const __nv_bfloat16* Ah_g = g_Ih + (size_t)z * NQ;
    const __nv_bfloat16* Al_g = g_Il + (size_t)z * NQ;
    const __nv_bfloat16* Wh_g = g_Ih + 3 * (size_t)NQ + (size_t)z * NW;
    const __nv_bfloat16* Wl_g = g_Il + 3 * (size_t)NQ + (size_t)z * NW;

    const int tid = threadIdx.x;
    const int wid = tid >> 5;
    const int warp_m = wid >> 1;
    const int warp_n = wid & 1;
    const int m0 = blockIdx.y * 128;
    const int n0 = blockIdx.x * 128;
    const uint32_t sbase = smem_u32(smem);

    const int r0 = tid >> 2, c0 = tid & 3;
    const int r1 = (tid + 256) >> 2, c1 = (tid + 256) & 3;

    auto issue = [&](int stage, int c) {
        const int k0 = c * BK;
        uint32_t sb = sbase + stage * STAGE_B;
        const __nv_bfloat16* gp[4] = {
            Ah_g + (size_t)m0 * D_ + k0, Al_g + (size_t)m0 * D_ + k0,
            Wh_g + (size_t)n0 * D_ + k0, Wl_g + (size_t)n0 * D_ + k0 };
        #pragma unroll
        for (int a = 0; a < 4; a++) {
            CP_ASYNC16(sb + a * ARR_B + r0 * 80 + c0 * 16,
                       gp[a] + (size_t)r0 * D_ + c0 * 8);
            CP_ASYNC16(sb + a * ARR_B + r1 * 80 + c1 * 16,
                       gp[a] + (size_t)r1 * D_ + c1 * 8);
        }
        CP_COMMIT();
    };

    wmma::fragment<wmma::accumulator, 16, 16, 16, float> acc[2][4];
    #pragma unroll
    for (int i = 0; i < 2; i++)
        #pragma unroll
        for (int j = 0; j < 4; j++) wmma::fill_fragment(acc[i][j], 0.0f);

    issue(0, 0);

    for (int c = 0; c < D_ / BK; c++) {
        if (c < D_ / BK - 1) { issue((c + 1) & 1, c + 1); CP_WAIT(1); }
        else                 { CP_WAIT(0); }
        __syncthreads();

        const char* st = smem + (c & 1) * STAGE_B;
        const __nv_bfloat16* Ahs = (const __nv_bfloat16*)(st);
        const __nv_bfloat16* Als = (const __nv_bfloat16*)(st + ARR_B);
        const __nv_bfloat16* Whs = (const __nv_bfloat16*)(st + 2 * ARR_B);
        const __nv_bfloat16* Wls = (const __nv_bfloat16*)(st + 3 * ARR_B);

        #pragma unroll
        for (int kk = 0; kk < BK; kk += 16) {
            wmma::fragment<wmma::matrix_a, 16, 16, 16, __nv_bfloat16, wmma::row_major> aH[2], aL[2];
            wmma::fragment<wmma::matrix_b, 16, 16, 16, __nv_bfloat16, wmma::col_major> bH[4], bL[4];
            #pragma unroll
            for (int i = 0; i < 2; i++) {
                wmma::load_matrix_sync(aH[i], &Ahs[(warp_m * 32 + i * 16) * LDA + kk], LDA);
                wmma::load_matrix_sync(aL[i], &Als[(warp_m * 32 + i * 16) * LDA + kk], LDA);
            }
            #pragma unroll
            for (int j = 0; j < 4; j++) {
                wmma::load_matrix_sync(bH[j], &Whs[(warp_n * 64 + j * 16) * LDA + kk], LDA);
                wmma::load_matrix_sync(bL[j], &Wls[(warp_n * 64 + j * 16) * LDA + kk], LDA);
            }
            #pragma unroll
            for (int i = 0; i < 2; i++)
                #pragma unroll
                for (int j = 0; j < 4; j++) {
                    wmma::mma_sync(acc[i][j], aH[i], bH[j], acc[i][j]);
                    wmma::mma_sync(acc[i][j], aH[i], bL[j], acc[i][j]);
                    wmma::mma_sync(acc[i][j], aL[i], bH[j], acc[i][j]);
                }
        }
        __syncthreads();
    }

    // Epilogue: stage fp32 result, split to bf16 hi/lo gmem.
    float* st = (float*)smem;   // 128 x 132
    #pragma unroll
    for (int i = 0; i < 2; i++)
        #pragma unroll
        for (int j = 0; j < 4; j++)
            wmma::store_matrix_sync(&st[(warp_m * 32 + i * 16) * 132 + warp_n * 64 + j * 16],
                                    acc[i][j], 132, wmma::mem_row_major);
    __syncthreads();

    __nv_bfloat16* outh = (z == 0) ? g_Qh : (z == 1) ? g_Kh : g_Vh;
    __nv_bfloat16* outl = (z == 0) ? g_Ql : (z == 1) ? g_Kl : g_Vl;
    const int b = m0 >> 11;
    #pragma unroll
    for (int it = 0; it < 16; it++) {
        int idx = it * 256 + tid;
        int r = idx >> 5, c4 = idx & 31;
        float4 val = *reinterpret_cast<const float4*>(&st[r * 132 + c4 * 4]);
        uint2 hv, lv; split4(val, hv, lv);
        int m = m0 + r;
        int s = m & (S_ - 1);
        int n = n0 + c4 * 4;
        int h = n >> 6, d0 = n & 63;
        size_t o = ((size_t)(b * H_ + h) * S_ + s) * HD_ + d0;
        *reinterpret_cast<uint2*>(outh + o) = hv;
        *reinterpret_cast<uint2*>(outl + o) = lv;
        if (z == 2) *reinterpret_cast<float4*>(g_V + o) = val;
    }
}

// ---------------------------------------------------------------------------
// Fused suffix sums of V: one block per bh, 1024 threads.
// ---------------------------------------------------------------------------
__global__ __launch_bounds__(1024) void suffix_kernel()
{
    __shared__ float part[16][64];
    const int bh = blockIdx.x;
    const int d = threadIdx.x & 63;
    const int g = threadIdx.x >> 6;
    const float* Vp = g_V + (size_t)bh * S_ * HD_ + d;
    float* Sp = g_S + (size_t)bh * S_ * HD_ + d;
    const int row0 = g * 128;

    float acc = 0.f;
    #pragma unroll 8
    for (int s = 0; s < 128; s++) acc += Vp[(size_t)(row0 + s) * HD_];
    part[g][d] = acc;
    __syncthreads();

    float base = 0.f;
    #pragma unroll
    for (int gg = g + 1; gg < 16; gg++) base += part[gg][d];
    for (int s = 127; s >= 0; s--) {
        Sp[(size_t)(row0 + s) * HD_] = base;
        base += Vp[(size_t)(row0 + s) * HD_];
    }
}

// ===========================================================================
// Attention on wmma bf16; cp.async loads + K/V prefetch overlap:
//   S = Qh.Kh + Qh.Kl + Ql.Kh ; P = exp(S/8) masked, split ;
//   O += Ph.Vh + Ph.Vl + Pl.Vh ;  Z/O tail analytic via SufV (m=0 stabilizer).
// ===========================================================================
#define ATT_LD 72
#define SS_LD  68
#define TILE_ROWB 144                 // bytes per smem tile row
#define ATT_SMEM (8*64*ATT_LD*2 + 64*SS_LD*4 + 64*4 + 128)

__global__ __launch_bounds__(256) void attn_wmma_kernel(float* __restrict__ out)
{
    extern __shared__ char smem_raw[];
    __nv_bfloat16* Qh = (__nv_bfloat16*)smem_raw;
    __nv_bfloat16* Ql = Qh + 64 * ATT_LD;
    __nv_bfloat16* Kh = Ql + 64 * ATT_LD;
    __nv_bfloat16* Kl = Kh + 64 * ATT_LD;
    __nv_bfloat16* Ph = Kl + 64 * ATT_LD;
    __nv_bfloat16* Pl = Ph + 64 * ATT_LD;
    __nv_bfloat16* Vh = Pl + 64 * ATT_LD;
    __nv_bfloat16* Vl = Vh + 64 * ATT_LD;
    float* Ss = (float*)(Vl + 64 * ATT_LD);
    float* Zs = Ss + 64 * SS_LD;

    const int tid = threadIdx.x;
    const int wid = tid >> 5;
    const int qt = blockIdx.x;
    const int bh = blockIdx.y;
    const size_t bho = (size_t)bh * S_ * HD_;

    const uint32_t sQh = smem_u32(Qh), sQl = smem_u32(Ql);
    const uint32_t sKh = smem_u32(Kh), sKl = smem_u32(Kl);
    const uint32_t sVh = smem_u32(Vh), sVl = smem_u32(Vl);

    // cp.async chunk mapping: 512 16B chunks per tile, 2 per thread.
    const int r0 = tid >> 3, c0 = tid & 7;
    const int r1 = (tid + 256) >> 3, c1 = (tid + 256) & 7;

    auto issue_pair = [&](uint32_t dh, uint32_t dl,
                          const __nv_bfloat16* gh, const __nv_bfloat16* gl) {
        CP_ASYNC16(dh + r0 * TILE_ROWB + c0 * 16, gh + r0 * 64 + c0 * 8);
        CP_ASYNC16(dh + r1 * TILE_ROWB + c1 * 16, gh + r1 * 64 + c1 * 8);
        CP_ASYNC16(dl + r0 * TILE_ROWB + c0 * 16, gl + r0 * 64 + c0 * 8);
        CP_ASYNC16(dl + r1 * TILE_ROWB + c1 * 16, gl + r1 * 64 + c1 * 8);
    };

    // Prologue: Q, K0, V0.
    issue_pair(sQh, sQl, g_Qh + bho + (size_t)qt * 64 * HD_,
                           g_Ql + bho + (size_t)qt * 64 * HD_);
    issue_pair(sKh, sKl, g_Kh + bho, g_Kl + bho);
    issue_pair(sVh, sVl, g_Vh + bho, g_Vl + bho);
    CP_COMMIT();

    if (tid < 64) Zs[tid] = 0.f;

    wmma::fragment<wmma::accumulator, 16, 16, 16, float> ofrag[2];
    wmma::fill_fragment(ofrag[0], 0.f);
    wmma::fill_fragment(ofrag[1], 0.f);

    const int qrow = (wid >> 1) * 16;
    const int kcol = (wid & 1) * 32;

    for (int kt = 0; kt <= qt; kt++) {
        CP_WAIT(0);
        __syncthreads();

        // S = Q.K^T, split 3-term.
        wmma::fragment<wmma::accumulator, 16, 16, 16, float> sfrag[2];
        wmma::fill_fragment(sfrag[0], 0.f);
        wmma::fill_fragment(sfrag[1], 0.f);
        #pragma unroll
        for (int kk = 0; kk < 64; kk += 16) {
            wmma::fragment<wmma::matrix_a, 16, 16, 16, __nv_bfloat16, wmma::row_major> aH, aL;
            wmma::load_matrix_sync(aH, &Qh[qrow * ATT_LD + kk], ATT_LD);
            wmma::load_matrix_sync(aL, &Ql[qrow * ATT_LD + kk], ATT_LD);
            #pragma unroll
            for (int c = 0; c < 2; c++) {
                wmma::fragment<wmma::matrix_b, 16, 16, 16, __nv_bfloat16, wmma::col_major> bH, bL;
                wmma::load_matrix_sync(bH, &Kh[(kcol + c * 16) * ATT_LD + kk], ATT_LD);
                wmma::load_matrix_sync(bL, &Kl[(kcol + c * 16) * ATT_LD + kk], ATT_LD);
                wmma::mma_sync(sfrag[c], aH, bH, sfrag[c]);
                wmma::mma_sync(sfrag[c], aH, bL, sfrag[c]);
                wmma::mma_sync(sfrag[c], aL, bH, sfrag[c]);
            }
        }
        wmma::store_matrix_sync(&Ss[qrow * SS_LD + kcol], sfrag[0], SS_LD, wmma::mem_row_major);
        wmma::store_matrix_sync(&Ss[qrow * SS_LD + kcol + 16], sfrag[1], SS_LD, wmma::mem_row_major);
        __syncthreads();

        // K is dead now: prefetch next K during exp + PV.
        if (kt < qt) {
            const size_t to = bho + (size_t)(kt + 1) * 64 * HD_;
            issue_pair(sKh, sKl, g_Kh + to, g_Kl + to);
            CP_COMMIT();
        }

        // exp phase (vectorized): p = exp(s/8) masked; Z; split P.
        {
            const int r = tid >> 2;
            const int c0e = (tid & 3) * 16;
            const int qglob = qt * 64 + r;
            const int kglob0 = kt * 64 + c0e;
            const bool diag = (kt == qt);
            float p[16];
            float rs = 0.f;
            #pragma unroll
            for (int ii = 0; ii < 4; ii++) {
                float4 s4 = *reinterpret_cast<const float4*>(&Ss[r * SS_LD + c0e + ii * 4]);
                float sv[4] = {s4.x, s4.y, s4.z, s4.w};
                #pragma unroll
                for (int jj = 0; jj < 4; jj++) {
                    int j = ii * 4 + jj;
                    bool okv = !diag || (kglob0 + j <= qglob);
                    float pv = okv ? fexp(sv[jj] * 0.125f) : 0.f;
                    p[j] = pv;
                    rs += pv;
                }
            }
            uint32_t hw[8], lw[8];
            #pragma unroll
            for (int j = 0; j < 8; j++) {
                __nv_bfloat16 h0 = __float2bfloat16(p[2*j]);
                __nv_bfloat16 h1 = __float2bfloat16(p[2*j+1]);
                __nv_bfloat16 l0 = __float2bfloat16(p[2*j]   - __bfloat162float(h0));
                __nv_bfloat16 l1 = __float2bfloat16(p[2*j+1] - __bfloat162float(h1));
                hw[j] = ((uint32_t)__bfloat16_as_ushort(h1) << 16) | __bfloat16_as_ushort(h0);
                lw[j] = ((uint32_t)__bfloat16_as_ushort(l1) << 16) | __bfloat16_as_ushort(l0);
            }
            char* phb = (char*)Ph + r * TILE_ROWB + c0e * 2;
            char* plb = (char*)Pl + r * TILE_ROWB + c0e * 2;
            *(uint4*)(phb)      = make_uint4(hw[0], hw[1], hw[2], hw[3]);
            *(uint4*)(phb + 16) = make_uint4(hw[4], hw[5], hw[6], hw[7]);
            *(uint4*)(plb)      = make_uint4(lw[0], lw[1], lw[2], lw[3]);
            *(uint4*)(plb + 16) = make_uint4(lw[4], lw[5], lw[6], lw[7]);

            rs += __shfl_xor_sync(0xffffffffu, rs, 1);
            rs += __shfl_xor_sync(0xffffffffu, rs, 2);
            if ((tid & 3) == 0) Zs[r] += rs;
        }
        __syncthreads();

        // O += Ph.Vh + Ph.Vl + Pl.Vh
        #pragma unroll
        for (int kk = 0; kk < 64; kk += 16) {
            wmma::fragment<wmma::matrix_a, 16, 16, 16, __nv_bfloat16, wmma::row_major> apH, apL;
            wmma::load_matrix_sync(apH, &Ph[qrow * ATT_LD + kk], ATT_LD);
            wmma::load_matrix_sync(apL, &Pl[qrow * ATT_LD + kk], ATT_LD);
            #pragma unroll
            for (int c = 0; c < 2; c++) {
                wmma::fragment<wmma::matrix_b, 16, 16, 16, __nv_bfloat16, wmma::row_major> bvH, bvL;
                wmma::load_matrix_sync(bvH, &Vh[kk * ATT_LD + kcol + c * 16], ATT_LD);
                wmma::load_matrix_sync(bvL, &Vl[kk * ATT_LD + kcol + c * 16], ATT_LD);
                wmma::mma_sync(ofrag[c], apH, bvH, ofrag[c]);
                wmma::mma_sync(ofrag[c], apH, bvL, ofrag[c]);
                wmma::mma_sync(ofrag[c], apL, bvH, ofrag[c]);
            }
        }
        __syncthreads();

        // V is dead now: prefetch next V.
        if (kt < qt) {
            const size_t to = bho + (size_t)(kt + 1) * 64 * HD_;
            issue_pair(sVh, sVl, g_Vh + to, g_Vl + to);
            CP_COMMIT();
        }
    }

    // Stage O, epilogue: suffix tail, normalize, store.
    wmma::store_matrix_sync(&Ss[qrow * SS_LD + kcol], ofrag[0], SS_LD, wmma::mem_row_major);
    wmma::store_matrix_sync(&Ss[qrow * SS_LD + kcol + 16], ofrag[1], SS_LD, wmma::mem_row_major);
    __syncthreads();

    const int b = bh / H_, h = bh % H_;
    const float* Sufp = g_S + bho;
    {
        const int r = tid >> 2;
        const int c0e = (tid & 3) * 16;
        const int q = qt * 64 + r;
        float Zr = Zs[r] + (float)(S_ - 1 - q);
        float inv = 1.f / Zr;
        float* dst = out + ((size_t)(b * S_ + q)) * D_ + h * HD_ + c0e;
        const float* suf = &Sufp[(size_t)q * HD_ + c0e];
        #pragma unroll
        for (int j = 0; j < 16; j += 4) {
            float4 sv = *reinterpret_cast<const float4*>(&suf[j]);
            float4 ov = make_float4(
                (Ss[r * SS_LD + c0e + j + 0] + sv.x) * inv,
                (Ss[r * SS_LD + c0e + j + 1] + sv.y) * inv,
                (Ss[r * SS_LD + c0e + j + 2] + sv.z) * inv,
                (Ss[r * SS_LD + c0e + j + 3] + sv.w) * inv);
            *reinterpret_cast<float4*>(&dst[j]) = ov;
        }
    }
}

// ---------------------------------------------------------------------------
extern "C" void kernel_launch(void* const* d_in, const int* in_sizes, int n_in,
                              void* d_out, int out_size)
{
    const float* q  = (const float*)d_in[0];
    const float* k  = (const float*)d_in[1];
    const float* v  = (const float*)d_in[2];
    const float* wq = (const float*)d_in[3];
    const float* wk = (const float*)d_in[4];
    const float* wv = (const float*)d_in[5];
    float* out = (float*)d_out;

    presplit_kernel<<<dim3(256, 6), 256>>>(q, k, v, wq, wk, wv);

    cudaFuncSetAttribute(proj_wmma_kernel,
                         cudaFuncAttributeMaxDynamicSharedMemorySize, PROJ_SMEM);
    proj_wmma_kernel<<<dim3(D_ / 128, (B_ * S_) / 128, 3), 256, PROJ_SMEM>>>();

    suffix_kernel<<<B_ * H_, 1024>>>();

    cudaFuncSetAttribute(attn_wmma_kernel,
                         cudaFuncAttributeMaxDynamicSharedMemorySize, ATT_SMEM);
    attn_wmma_kernel<<<dim3(S_ / 64, B_ * H_), 256, ATT_SMEM>>>(out);
}

// round 10
// speedup vs baseline: 1.9352x; 1.1906x over previous
#include <cuda_runtime.h>
#include <cuda_bf16.h>
#include <mma.h>
#include <cstdint>
#include <math.h>

using namespace nvcuda;

#define B_  2
#define S_  2048
#define D_  1024
#define H_  16
#define HD_ 64
#define NQ (B_*S_*D_)
#define NW (D_*D_)
#define NP (B_*H_*S_*HD_)

__device__ __nv_bfloat16 g_Ih[3*NQ + 3*NW];
__device__ __nv_bfloat16 g_Il[3*NQ + 3*NW];
__device__ __nv_bfloat16 g_Qh[NP], g_Ql[NP];
__device__ __nv_bfloat16 g_Kh[NP], g_Kl[NP];
__device__ __nv_bfloat16 g_Vh[NP], g_Vl[NP];
__device__ float g_V[NP];
__device__ float g_S[NP];

// ---------------------------------------------------------------------------
__device__ __forceinline__ uint32_t smem_u32(const void* p) {
    uint32_t a;
    asm("{ .reg .u64 t; cvta.to.shared.u64 t, %1; cvt.u32.u64 %0, t; }"
        : "=r"(a) : "l"(p));
    return a;
}
#define CP_ASYNC16(dst, src) \
    asm volatile("cp.async.cg.shared.global [%0], [%1], 16;" :: "r"(dst), "l"(src))
#define CP_COMMIT() asm volatile("cp.async.commit_group;")
#define CP_WAIT(n)  asm volatile("cp.async.wait_group %0;" :: "n"(n))

#define LDSM_X4(r0,r1,r2,r3, addr) \
    asm volatile("ldmatrix.sync.aligned.m8n8.x4.shared.b16 {%0,%1,%2,%3}, [%4];" \
        : "=r"(r0),"=r"(r1),"=r"(r2),"=r"(r3) : "r"(addr))
#define LDSM_X4_T(r0,r1,r2,r3, addr) \
    asm volatile("ldmatrix.sync.aligned.m8n8.x4.trans.shared.b16 {%0,%1,%2,%3}, [%4];" \
        : "=r"(r0),"=r"(r1),"=r"(r2),"=r"(r3) : "r"(addr))
#define MMA16816(c, a, b0, b1) \
    asm volatile("mma.sync.aligned.m16n8k16.row.col.f32.bf16.bf16.f32 " \
        "{%0,%1,%2,%3},{%4,%5,%6,%7},{%8,%9},{%0,%1,%2,%3};" \
        : "+f"((c)[0]),"+f"((c)[1]),"+f"((c)[2]),"+f"((c)[3]) \
        : "r"((a)[0]),"r"((a)[1]),"r"((a)[2]),"r"((a)[3]),"r"(b0),"r"(b1))

__device__ __forceinline__ uint32_t pack_bf16x2(float lo, float hi) {
    __nv_bfloat162 t = __floats2bfloat162_rn(lo, hi);
    return *reinterpret_cast<uint32_t*>(&t);
}

__device__ __forceinline__ void split4(float4 a, uint2& hv, uint2& lv) {
    __nv_bfloat16 h0 = __float2bfloat16(a.x);
    __nv_bfloat16 h1 = __float2bfloat16(a.y);
    __nv_bfloat16 h2 = __float2bfloat16(a.z);
    __nv_bfloat16 h3 = __float2bfloat16(a.w);
    __nv_bfloat16 l0 = __float2bfloat16(a.x - __bfloat162float(h0));
    __nv_bfloat16 l1 = __float2bfloat16(a.y - __bfloat162float(h1));
    __nv_bfloat16 l2 = __float2bfloat16(a.z - __bfloat162float(h2));
    __nv_bfloat16 l3 = __float2bfloat16(a.w - __bfloat162float(h3));
    hv = make_uint2(((uint32_t)__bfloat16_as_ushort(h1) << 16) | __bfloat16_as_ushort(h0),
                    ((uint32_t)__bfloat16_as_ushort(h3) << 16) | __bfloat16_as_ushort(h2));
    lv = make_uint2(((uint32_t)__bfloat16_as_ushort(l1) << 16) | __bfloat16_as_ushort(l0),
                    ((uint32_t)__bfloat16_as_ushort(l3) << 16) | __bfloat16_as_ushort(l2));
}

__device__ __forceinline__ float fexp(float s) {
    float x = s * 1.4426950408889634f;
    float j = x + 12582912.0f;
    float xi = j - 12582912.0f;
    float f = x - xi;
    int e = __float_as_int(j) - 0x4B400000;
    float p = 1.3333558e-3f;
    p = fmaf(p, f, 9.6181291e-3f);
    p = fmaf(p, f, 5.5504109e-2f);
    p = fmaf(p, f, 2.4022651e-1f);
    p = fmaf(p, f, 6.9314718e-1f);
    p = fmaf(p, f, 1.0f);
    return p * __int_as_float((e + 127) << 23);
}

// ---------------------------------------------------------------------------
__global__ __launch_bounds__(256) void presplit_kernel(
    const float* __restrict__ q, const float* __restrict__ k,
    const float* __restrict__ v, const float* __restrict__ wq,
    const float* __restrict__ wk, const float* __restrict__ wv)
{
    const int t = blockIdx.y;
    const float* src = (t == 0) ? q : (t == 1) ? k : (t == 2) ? v
                     : (t == 3) ? wq : (t == 4) ? wk : wv;
    const size_t off = (t < 3) ? (size_t)t * NQ : 3 * (size_t)NQ + (size_t)(t - 3) * NW;
    const int n4 = ((t < 3) ? NQ : NW) >> 2;
    uint2* dh = (uint2*)(g_Ih + off);
    uint2* dl = (uint2*)(g_Il + off);
    for (int i = blockIdx.x * blockDim.x + threadIdx.x; i < n4;
         i += gridDim.x * blockDim.x) {
        float4 a = ((const float4*)src)[i];
        uint2 hv, lv; split4(a, hv, lv);
        dh[i] = hv; dl[i] = lv;
    }
}

// ===========================================================================
// Projection GEMM (unchanged from R8 WIN).
// ===========================================================================
#define BK 32
#define LDA 40
#define ARR_B (128 * LDA * 2)
#define STAGE_B (4 * ARR_B)
#define PROJ_SMEM (2 * STAGE_B)

__global__ __launch_bounds__(256) void proj_wmma_kernel()
{
    extern __shared__ char smem[];
    const int z = blockIdx.z;
    const __nv_bfloat16* Ah_g = g_Ih + (size_t)z * NQ;
    const __nv_bfloat16* Al_g = g_Il + (size_t)z * NQ;
    const __nv_bfloat16* Wh_g = g_Ih + 3 * (size_t)NQ + (size_t)z * NW;
    const __nv_bfloat16* Wl_g = g_Il + 3 * (size_t)NQ + (size_t)z * NW;

    const int tid = threadIdx.x;
    const int wid = tid >> 5;
    const int warp_m = wid >> 1;
    const int warp_n = wid & 1;
    const int m0 = blockIdx.y * 128;
    const int n0 = blockIdx.x * 128;
    const uint32_t sbase = smem_u32(smem);

    const int r0 = tid >> 2, c0 = tid & 3;
    const int r1 = (tid + 256) >> 2, c1 = (tid + 256) & 3;

    auto issue = [&](int stage, int c) {
        const int k0 = c * BK;
        uint32_t sb = sbase + stage * STAGE_B;
        const __nv_bfloat16* gp[4] = {
            Ah_g + (size_t)m0 * D_ + k0, Al_g + (size_t)m0 * D_ + k0,
            Wh_g + (size_t)n0 * D_ + k0, Wl_g + (size_t)n0 * D_ + k0 };
        #pragma unroll
        for (int a = 0; a < 4; a++) {
            CP_ASYNC16(sb + a * ARR_B + r0 * 80 + c0 * 16,
                       gp[a] + (size_t)r0 * D_ + c0 * 8);
            CP_ASYNC16(sb + a * ARR_B + r1 * 80 + c1 * 16,
                       gp[a] + (size_t)r1 * D_ + c1 * 8);
        }
        CP_COMMIT();
    };

    wmma::fragment<wmma::accumulator, 16, 16, 16, float> acc[2][4];
    #pragma unroll
    for (int i = 0; i < 2; i++)
        #pragma unroll
        for (int j = 0; j < 4; j++) wmma::fill_fragment(acc[i][j], 0.0f);

    issue(0, 0);

    for (int c = 0; c < D_ / BK; c++) {
        if (c < D_ / BK - 1) { issue((c + 1) & 1, c + 1); CP_WAIT(1); }
        else                 { CP_WAIT(0); }
        __syncthreads();

        const char* st = smem + (c & 1) * STAGE_B;
        const __nv_bfloat16* Ahs = (const __nv_bfloat16*)(st);
        const __nv_bfloat16* Als = (const __nv_bfloat16*)(st + ARR_B);
        const __nv_bfloat16* Whs = (const __nv_bfloat16*)(st + 2 * ARR_B);
        const __nv_bfloat16* Wls = (const __nv_bfloat16*)(st + 3 * ARR_B);

        #pragma unroll
        for (int kk = 0; kk < BK; kk += 16) {
            wmma::fragment<wmma::matrix_a, 16, 16, 16, __nv_bfloat16, wmma::row_major> aH[2], aL[2];
            wmma::fragment<wmma::matrix_b, 16, 16, 16, __nv_bfloat16, wmma::col_major> bH[4], bL[4];
            #pragma unroll
            for (int i = 0; i < 2; i++) {
                wmma::load_matrix_sync(aH[i], &Ahs[(warp_m * 32 + i * 16) * LDA + kk], LDA);
                wmma::load_matrix_sync(aL[i], &Als[(warp_m * 32 + i * 16) * LDA + kk], LDA);
            }
            #pragma unroll
            for (int j = 0; j < 4; j++) {
                wmma::load_matrix_sync(bH[j], &Whs[(warp_n * 64 + j * 16) * LDA + kk], LDA);
                wmma::load_matrix_sync(bL[j], &Wls[(warp_n * 64 + j * 16) * LDA + kk], LDA);
            }
            #pragma unroll
            for (int i = 0; i < 2; i++)
                #pragma unroll
                for (int j = 0; j < 4; j++) {
                    wmma::mma_sync(acc[i][j], aH[i], bH[j], acc[i][j]);
                    wmma::mma_sync(acc[i][j], aH[i], bL[j], acc[i][j]);
                    wmma::mma_sync(acc[i][j], aL[i], bH[j], acc[i][j]);
                }
        }
        __syncthreads();
    }

    float* st = (float*)smem;
    #pragma unroll
    for (int i = 0; i < 2; i++)
        #pragma unroll
        for (int j = 0; j < 4; j++)
            wmma::store_matrix_sync(&st[(warp_m * 32 + i * 16) * 132 + warp_n * 64 + j * 16],
                                    acc[i][j], 132, wmma::mem_row_major);
    __syncthreads();

    __nv_bfloat16* outh = (z == 0) ? g_Qh : (z == 1) ? g_Kh : g_Vh;
    __nv_bfloat16* outl = (z == 0) ? g_Ql : (z == 1) ? g_Kl : g_Vl;
    const int b = m0 >> 11;
    #pragma unroll
    for (int it = 0; it < 16; it++) {
        int idx = it * 256 + tid;
        int r = idx >> 5, c4 = idx & 31;
        float4 val = *reinterpret_cast<const float4*>(&st[r * 132 + c4 * 4]);
        uint2 hv, lv; split4(val, hv, lv);
        int m = m0 + r;
        int s = m & (S_ - 1);
        int n = n0 + c4 * 4;
        int h = n >> 6, d0 = n & 63;
        size_t o = ((size_t)(b * H_ + h) * S_ + s) * HD_ + d0;
        *reinterpret_cast<uint2*>(outh + o) = hv;
        *reinterpret_cast<uint2*>(outl + o) = lv;
        if (z == 2) *reinterpret_cast<float4*>(g_V + o) = val;
    }
}

// ---------------------------------------------------------------------------
__global__ __launch_bounds__(1024) void suffix_kernel()
{
    __shared__ float part[16][64];
    const int bh = blockIdx.x;
    const int d = threadIdx.x & 63;
    const int g = threadIdx.x >> 6;
    const float* Vp = g_V + (size_t)bh * S_ * HD_ + d;
    float* Sp = g_S + (size_t)bh * S_ * HD_ + d;
    const int row0 = g * 128;

    float acc = 0.f;
    #pragma unroll 8
    for (int s = 0; s < 128; s++) acc += Vp[(size_t)(row0 + s) * HD_];
    part[g][d] = acc;
    __syncthreads();

    float base = 0.f;
    #pragma unroll
    for (int gg = g + 1; gg < 16; gg++) base += part[gg][d];
    for (int s = 127; s >= 0; s--) {
        Sp[(size_t)(row0 + s) * HD_] = base;
        base += Vp[(size_t)(row0 + s) * HD_];
    }
}

// ===========================================================================
// Register-resident flash attention via mma.sync.m16n8k16 (R9 design,
// FIXED cp.async chunk maps: 8 chunks/row, 2048 chunks per Q / KV stage).
// ===========================================================================
#define ROWB 144
#define KTILE_B (64 * ROWB)
#define Q_B (128 * ROWB)
#define STG_B (4 * KTILE_B)
#define ATT_SMEM (2 * Q_B + 2 * STG_B)

__global__ __launch_bounds__(256, 2) void attn_mma_kernel(float* __restrict__ out)
{
    extern __shared__ char smem_raw[];
    const uint32_t sb = smem_u32(smem_raw);
    const uint32_t sQh = sb, sQl = sb + Q_B;
    const uint32_t sStage0 = sb + 2 * Q_B;

    const int tid = threadIdx.x;
    const int wid = tid >> 5;
    const int lane = tid & 31;
    const int qt = (int)gridDim.x - 1 - (int)blockIdx.x;
    const int bh = blockIdx.y;
    const size_t bho = (size_t)bh * S_ * HD_;
    const int qbase = qt * 128;
    const int m0 = wid * 16;

    // Q: 2 arrays x 1024 chunks (128 rows x 8 chunks). 8 per thread.
    {
        #pragma unroll
        for (int i = 0; i < 8; i++) {
            int id = i * 256 + tid;            // 0..2047
            int arr = id >> 10;
            int rem = id & 1023;
            int r = rem >> 3, c = rem & 7;
            const __nv_bfloat16* g = (arr ? g_Ql : g_Qh) + bho + (size_t)(qbase + r) * 64 + c * 8;
            CP_ASYNC16((arr ? sQl : sQh) + r * ROWB + c * 16, g);
        }
        CP_COMMIT();
    }
    // KV stage: 4 arrays x 512 chunks (64 rows x 8 chunks). 8 per thread.
    auto issue_kv = [&](int stage, int kt) {
        uint32_t st = sStage0 + stage * STG_B;
        const size_t to = bho + (size_t)kt * 64 * HD_;
        const __nv_bfloat16* gp[4] = { g_Kh + to, g_Kl + to, g_Vh + to, g_Vl + to };
        #pragma unroll
        for (int i = 0; i < 8; i++) {
            int id = i * 256 + tid;            // 0..2047
            int arr = id >> 9;
            int rem = id & 511;
            int r = rem >> 3, c = rem & 7;
            CP_ASYNC16(st + arr * KTILE_B + r * ROWB + c * 16, gp[arr] + (size_t)r * 64 + c * 8);
        }
        CP_COMMIT();
    };
    issue_kv(0, 0);

    const int rA = ((lane >> 3) & 1) * 8 + (lane & 7);
    const int cA = ((lane >> 4) & 1) * 8;
    const int rK = ((lane >> 4) & 1) * 8 + (lane & 7);
    const int cK = ((lane >> 3) & 1) * 8;

    CP_WAIT(1);
    __syncthreads();

    uint32_t qh[4][4];
    #pragma unroll
    for (int kc = 0; kc < 4; kc++)
        LDSM_X4(qh[kc][0], qh[kc][1], qh[kc][2], qh[kc][3],
                sQh + (m0 + rA) * ROWB + (kc * 16 + cA) * 2);

    float oc[8][4];
    #pragma unroll
    for (int i = 0; i < 8; i++)
        #pragma unroll
        for (int j = 0; j < 4; j++) oc[i][j] = 0.f;
    float z0 = 0.f, z1 = 0.f;

    const int rowg0 = qbase + m0 + (lane >> 2);
    const int rowg1 = rowg0 + 8;
    const int ktmax = 2 * qt + 1;

    for (int kt = 0; kt <= ktmax; kt++) {
        CP_WAIT(0);
        __syncthreads();
        if (kt < ktmax) issue_kv((kt + 1) & 1, kt + 1);

        const uint32_t st = sStage0 + (kt & 1) * STG_B;
        const uint32_t stKh = st, stKl = st + KTILE_B;
        const uint32_t stVh = st + 2 * KTILE_B, stVl = st + 3 * KTILE_B;

        // ---- S = Q.K^T (3-term split) ----
        float sc[8][4];
        #pragma unroll
        for (int i = 0; i < 8; i++)
            #pragma unroll
            for (int j = 0; j < 4; j++) sc[i][j] = 0.f;

        #pragma unroll
        for (int kc = 0; kc < 4; kc++) {
            uint32_t ql_[4];
            LDSM_X4(ql_[0], ql_[1], ql_[2], ql_[3],
                    sQl + (m0 + rA) * ROWB + (kc * 16 + cA) * 2);
            #pragma unroll
            for (int ng = 0; ng < 4; ng++) {
                uint32_t bh0, bh1, bh2, bh3, bl0, bl1, bl2, bl3;
                LDSM_X4(bh0, bh1, bh2, bh3, stKh + (ng * 16 + rK) * ROWB + (kc * 16 + cK) * 2);
                LDSM_X4(bl0, bl1, bl2, bl3, stKl + (ng * 16 + rK) * ROWB + (kc * 16 + cK) * 2);
                MMA16816(sc[2 * ng],     qh[kc], bh0, bh1);
                MMA16816(sc[2 * ng],     qh[kc], bl0, bl1);
                MMA16816(sc[2 * ng],     ql_,    bh0, bh1);
                MMA16816(sc[2 * ng + 1], qh[kc], bh2, bh3);
                MMA16816(sc[2 * ng + 1], qh[kc], bl2, bl3);
                MMA16816(sc[2 * ng + 1], ql_,    bh2, bh3);
            }
        }

        // ---- exp/mask/Z in regs; repack P into A-frags ----
        uint32_t pah[4][4], pal[4][4];
        const int colb = kt * 64 + 2 * (lane & 3);
        #pragma unroll
        for (int nt = 0; nt < 8; nt++) {
            int col0 = colb + nt * 8;
            float p00 = (col0     <= rowg0) ? fexp(sc[nt][0] * 0.125f) : 0.f;
            float p01 = (col0 + 1 <= rowg0) ? fexp(sc[nt][1] * 0.125f) : 0.f;
            float p10 = (col0     <= rowg1) ? fexp(sc[nt][2] * 0.125f) : 0.f;
            float p11 = (col0 + 1 <= rowg1) ? fexp(sc[nt][3] * 0.125f) : 0.f;
            z0 += p00 + p01;
            z1 += p10 + p11;
            float h00 = __bfloat162float(__float2bfloat16(p00));
            float h01 = __bfloat162float(__float2bfloat16(p01));
            float h10 = __bfloat162float(__float2bfloat16(p10));
            float h11 = __bfloat162float(__float2bfloat16(p11));
            int kc = nt >> 1, hf = (nt & 1) * 2;
            pah[kc][hf + 0] = pack_bf16x2(h00, h01);
            pah[kc][hf + 1] = pack_bf16x2(h10, h11);
            pal[kc][hf + 0] = pack_bf16x2(p00 - h00, p01 - h01);
            pal[kc][hf + 1] = pack_bf16x2(p10 - h10, p11 - h11);
        }

        // ---- O += P.V (3-term split) ----
        #pragma unroll
        for (int kc = 0; kc < 4; kc++) {
            #pragma unroll
            for (int dg = 0; dg < 4; dg++) {
                uint32_t vh0, vh1, vh2, vh3, vl0, vl1, vl2, vl3;
                LDSM_X4_T(vh0, vh1, vh2, vh3, stVh + (kc * 16 + rA) * ROWB + (dg * 16 + cA) * 2);
                LDSM_X4_T(vl0, vl1, vl2, vl3, stVl + (kc * 16 + rA) * ROWB + (dg * 16 + cA) * 2);
                MMA16816(oc[2 * dg],     pah[kc], vh0, vh1);
                MMA16816(oc[2 * dg],     pah[kc], vl0, vl1);
                MMA16816(oc[2 * dg],     pal[kc], vh0, vh1);
                MMA16816(oc[2 * dg + 1], pah[kc], vh2, vh3);
                MMA16816(oc[2 * dg + 1], pah[kc], vl2, vl3);
                MMA16816(oc[2 * dg + 1], pal[kc], vh2, vh3);
            }
        }
    }

    // ---- Z reduce, analytic tail, store ----
    z0 += __shfl_xor_sync(0xffffffffu, z0, 1);
    z0 += __shfl_xor_sync(0xffffffffu, z0, 2);
    z1 += __shfl_xor_sync(0xffffffffu, z1, 1);
    z1 += __shfl_xor_sync(0xffffffffu, z1, 2);
    float inv0 = 1.f / (z0 + (float)(S_ - 1 - rowg0));
    float inv1 = 1.f / (z1 + (float)(S_ - 1 - rowg1));

    const int b = bh / H_, h = bh % H_;
    const float* Sufp = g_S + bho;
    #pragma unroll
    for (int nt = 0; nt < 8; nt++) {
        int d = nt * 8 + 2 * (lane & 3);
        float2 s0 = *reinterpret_cast<const float2*>(&Sufp[(size_t)rowg0 * 64 + d]);
        float2 s1 = *reinterpret_cast<const float2*>(&Sufp[(size_t)rowg1 * 64 + d]);
        float2 o0 = make_float2((oc[nt][0] + s0.x) * inv0, (oc[nt][1] + s0.y) * inv0);
        float2 o1 = make_float2((oc[nt][2] + s1.x) * inv1, (oc[nt][3] + s1.y) * inv1);
        *reinterpret_cast<float2*>(&out[((size_t)(b * S_ + rowg0)) * D_ + h * 64 + d]) = o0;
        *reinterpret_cast<float2*>(&out[((size_t)(b * S_ + rowg1)) * D_ + h * 64 + d]) = o1;
    }
}

// ---------------------------------------------------------------------------
extern "C" void kernel_launch(void* const* d_in, const int* in_sizes, int n_in,
                              void* d_out, int out_size)
{
    const float* q  = (const float*)d_in[0];
    const float* k  = (const float*)d_in[1];
    const float* v  = (const float*)d_in[2];
    const float* wq = (const float*)d_in[3];
    const float* wk = (const float*)d_in[4];
    const float* wv = (const float*)d_in[5];
    float* out = (float*)d_out;

    presplit_kernel<<<dim3(256, 6), 256>>>(q, k, v, wq, wk, wv);

    cudaFuncSetAttribute(proj_wmma_kernel,
                         cudaFuncAttributeMaxDynamicSharedMemorySize, PROJ_SMEM);
    proj_wmma_kernel<<<dim3(D_ / 128, (B_ * S_) / 128, 3), 256, PROJ_SMEM>>>();

    suffix_kernel<<<B_ * H_, 1024>>>();

    cudaFuncSetAttribute(attn_mma_kernel,
                         cudaFuncAttributeMaxDynamicSharedMemorySize, ATT_SMEM);
    attn_mma_kernel<<<dim3(S_ / 128, B_ * H_), 256, ATT_SMEM>>>(out);
}

// round 11
// speedup vs baseline: 1.9619x; 1.0138x over previous
#include <cuda_runtime.h>
#include <cuda_bf16.h>
#include <mma.h>
#include <cstdint>
#include <math.h>

using namespace nvcuda;

#define B_  2
#define S_  2048
#define D_  1024
#define H_  16
#define HD_ 64
#define NQ (B_*S_*D_)
#define NW (D_*D_)
#define NP (B_*H_*S_*HD_)

__device__ __nv_bfloat16 g_Ih[3*NQ + 3*NW];
__device__ __nv_bfloat16 g_Il[3*NQ + 3*NW];
__device__ __nv_bfloat16 g_Qh[NP], g_Ql[NP];
__device__ __nv_bfloat16 g_Kh[NP], g_Kl[NP];
__device__ __nv_bfloat16 g_Vh[NP], g_Vl[NP];
__device__ float g_V[NP];
__device__ float g_S[NP];

// ---------------------------------------------------------------------------
__device__ __forceinline__ uint32_t smem_u32(const void* p) {
    uint32_t a;
    asm("{ .reg .u64 t; cvta.to.shared.u64 t, %1; cvt.u32.u64 %0, t; }"
        : "=r"(a) : "l"(p));
    return a;
}
#define CP_ASYNC16(dst, src) \
    asm volatile("cp.async.cg.shared.global [%0], [%1], 16;" :: "r"(dst), "l"(src))
#define CP_COMMIT() asm volatile("cp.async.commit_group;")
#define CP_WAIT(n)  asm volatile("cp.async.wait_group %0;" :: "n"(n))

#define LDSM_X4(r0,r1,r2,r3, addr) \
    asm volatile("ldmatrix.sync.aligned.m8n8.x4.shared.b16 {%0,%1,%2,%3}, [%4];" \
        : "=r"(r0),"=r"(r1),"=r"(r2),"=r"(r3) : "r"(addr))
#define LDSM_X4_T(r0,r1,r2,r3, addr) \
    asm volatile("ldmatrix.sync.aligned.m8n8.x4.trans.shared.b16 {%0,%1,%2,%3}, [%4];" \
        : "=r"(r0),"=r"(r1),"=r"(r2),"=r"(r3) : "r"(addr))
#define MMA16816(c, a, b0, b1) \
    asm volatile("mma.sync.aligned.m16n8k16.row.col.f32.bf16.bf16.f32 " \
        "{%0,%1,%2,%3},{%4,%5,%6,%7},{%8,%9},{%0,%1,%2,%3};" \
        : "+f"((c)[0]),"+f"((c)[1]),"+f"((c)[2]),"+f"((c)[3]) \
        : "r"((a)[0]),"r"((a)[1]),"r"((a)[2]),"r"((a)[3]),"r"(b0),"r"(b1))

__device__ __forceinline__ uint32_t pack_bf16x2(float lo, float hi) {
    __nv_bfloat162 t = __floats2bfloat162_rn(lo, hi);
    return *reinterpret_cast<uint32_t*>(&t);
}

__device__ __forceinline__ void split4(float4 a, uint2& hv, uint2& lv) {
    __nv_bfloat16 h0 = __float2bfloat16(a.x);
    __nv_bfloat16 h1 = __float2bfloat16(a.y);
    __nv_bfloat16 h2 = __float2bfloat16(a.z);
    __nv_bfloat16 h3 = __float2bfloat16(a.w);
    __nv_bfloat16 l0 = __float2bfloat16(a.x - __bfloat162float(h0));
    __nv_bfloat16 l1 = __float2bfloat16(a.y - __bfloat162float(h1));
    __nv_bfloat16 l2 = __float2bfloat16(a.z - __bfloat162float(h2));
    __nv_bfloat16 l3 = __float2bfloat16(a.w - __bfloat162float(h3));
    hv = make_uint2(((uint32_t)__bfloat16_as_ushort(h1) << 16) | __bfloat16_as_ushort(h0),
                    ((uint32_t)__bfloat16_as_ushort(h3) << 16) | __bfloat16_as_ushort(h2));
    lv = make_uint2(((uint32_t)__bfloat16_as_ushort(l1) << 16) | __bfloat16_as_ushort(l0),
                    ((uint32_t)__bfloat16_as_ushort(l3) << 16) | __bfloat16_as_ushort(l2));
}

__device__ __forceinline__ float fexp(float s) {
    float x = s * 1.4426950408889634f;
    float j = x + 12582912.0f;
    float xi = j - 12582912.0f;
    float f = x - xi;
    int e = __float_as_int(j) - 0x4B400000;
    float p = 1.3333558e-3f;
    p = fmaf(p, f, 9.6181291e-3f);
    p = fmaf(p, f, 5.5504109e-2f);
    p = fmaf(p, f, 2.4022651e-1f);
    p = fmaf(p, f, 6.9314718e-1f);
    p = fmaf(p, f, 1.0f);
    return p * __int_as_float((e + 127) << 23);
}

// ---------------------------------------------------------------------------
__global__ __launch_bounds__(256) void presplit_kernel(
    const float* __restrict__ q, const float* __restrict__ k,
    const float* __restrict__ v, const float* __restrict__ wq,
    const float* __restrict__ wk, const float* __restrict__ wv)
{
    const int t = blockIdx.y;
    const float* src = (t == 0) ? q : (t == 1) ? k : (t == 2) ? v
                     : (t == 3) ? wq : (t == 4) ? wk : wv;
    const size_t off = (t < 3) ? (size_t)t * NQ : 3 * (size_t)NQ + (size_t)(t - 3) * NW;
    const int n4 = ((t < 3) ? NQ : NW) >> 2;
    uint2* dh = (uint2*)(g_Ih + off);
    uint2* dl = (uint2*)(g_Il + off);
    for (int i = blockIdx.x * blockDim.x + threadIdx.x; i < n4;
         i += gridDim.x * blockDim.x) {
        float4 a = ((const float4*)src)[i];
        uint2 hv, lv; split4(a, hv, lv);
        dh[i] = hv; dl[i] = lv;
    }
}

// ===========================================================================
// Projection GEMM (unchanged from R8 WIN).
// ===========================================================================
#define BK 32
#define LDA 40
#define ARR_B (128 * LDA * 2)
#define STAGE_B (4 * ARR_B)
#define PROJ_SMEM (2 * STAGE_B)

__global__ __launch_bounds__(256) void proj_wmma_kernel()
{
    extern __shared__ char smem[];
    const int z = blockIdx.z;
    const __nv_bfloat16* Ah_g = g_Ih + (size_t)z * NQ;
    const __nv_bfloat16* Al_g = g_Il + (size_t)z * NQ;
    const __nv_bfloat16* Wh_g = g_Ih + 3 * (size_t)NQ + (size_t)z * NW;
    const __nv_bfloat16* Wl_g = g_Il + 3 * (size_t)NQ + (size_t)z * NW;

    const int tid = threadIdx.x;
    const int wid = tid >> 5;
    const int warp_m = wid >> 1;
    const int warp_n = wid & 1;
    const int m0 = blockIdx.y * 128;
    const int n0 = blockIdx.x * 128;
    const uint32_t sbase = smem_u32(smem);

    const int r0 = tid >> 2, c0 = tid & 3;
    const int r1 = (tid + 256) >> 2, c1 = (tid + 256) & 3;

    auto issue = [&](int stage, int c) {
        const int k0 = c * BK;
        uint32_t sb = sbase + stage * STAGE_B;
        const __nv_bfloat16* gp[4] = {
            Ah_g + (size_t)m0 * D_ + k0, Al_g + (size_t)m0 * D_ + k0,
            Wh_g + (size_t)n0 * D_ + k0, Wl_g + (size_t)n0 * D_ + k0 };
        #pragma unroll
        for (int a = 0; a < 4; a++) {
            CP_ASYNC16(sb + a * ARR_B + r0 * 80 + c0 * 16,
                       gp[a] + (size_t)r0 * D_ + c0 * 8);
            CP_ASYNC16(sb + a * ARR_B + r1 * 80 + c1 * 16,
                       gp[a] + (size_t)r1 * D_ + c1 * 8);
        }
        CP_COMMIT();
    };

    wmma::fragment<wmma::accumulator, 16, 16, 16, float> acc[2][4];
    #pragma unroll
    for (int i = 0; i < 2; i++)
        #pragma unroll
        for (int j = 0; j < 4; j++) wmma::fill_fragment(acc[i][j], 0.0f);

    issue(0, 0);

    for (int c = 0; c < D_ / BK; c++) {
        if (c < D_ / BK - 1) { issue((c + 1) & 1, c + 1); CP_WAIT(1); }
        else                 { CP_WAIT(0); }
        __syncthreads();

        const char* st = smem + (c & 1) * STAGE_B;
        const __nv_bfloat16* Ahs = (const __nv_bfloat16*)(st);
        const __nv_bfloat16* Als = (const __nv_bfloat16*)(st + ARR_B);
        const __nv_bfloat16* Whs = (const __nv_bfloat16*)(st + 2 * ARR_B);
        const __nv_bfloat16* Wls = (const __nv_bfloat16*)(st + 3 * ARR_B);

        #pragma unroll
        for (int kk = 0; kk < BK; kk += 16) {
            wmma::fragment<wmma::matrix_a, 16, 16, 16, __nv_bfloat16, wmma::row_major> aH[2], aL[2];
            wmma::fragment<wmma::matrix_b, 16, 16, 16, __nv_bfloat16, wmma::col_major> bH[4], bL[4];
            #pragma unroll
            for (int i = 0; i < 2; i++) {
                wmma::load_matrix_sync(aH[i], &Ahs[(warp_m * 32 + i * 16) * LDA + kk], LDA);
                wmma::load_matrix_sync(aL[i], &Als[(warp_m * 32 + i * 16) * LDA + kk], LDA);
            }
            #pragma unroll
            for (int j = 0; j < 4; j++) {
                wmma::load_matrix_sync(bH[j], &Whs[(warp_n * 64 + j * 16) * LDA + kk], LDA);
                wmma::load_matrix_sync(bL[j], &Wls[(warp_n * 64 + j * 16) * LDA + kk], LDA);
            }
            #pragma unroll
            for (int i = 0; i < 2; i++)
                #pragma unroll
                for (int j = 0; j < 4; j++) {
                    wmma::mma_sync(acc[i][j], aH[i], bH[j], acc[i][j]);
                    wmma::mma_sync(acc[i][j], aH[i], bL[j], acc[i][j]);
                    wmma::mma_sync(acc[i][j], aL[i], bH[j], acc[i][j]);
                }
        }
        __syncthreads();
    }

    float* st = (float*)smem;
    #pragma unroll
    for (int i = 0; i < 2; i++)
        #pragma unroll
        for (int j = 0; j < 4; j++)
            wmma::store_matrix_sync(&st[(warp_m * 32 + i * 16) * 132 + warp_n * 64 + j * 16],
                                    acc[i][j], 132, wmma::mem_row_major);
    __syncthreads();

    __nv_bfloat16* outh = (z == 0) ? g_Qh : (z == 1) ? g_Kh : g_Vh;
    __nv_bfloat16* outl = (z == 0) ? g_Ql : (z == 1) ? g_Kl : g_Vl;
    const int b = m0 >> 11;
    #pragma unroll
    for (int it = 0; it < 16; it++) {
        int idx = it * 256 + tid;
        int r = idx >> 5, c4 = idx & 31;
        float4 val = *reinterpret_cast<const float4*>(&st[r * 132 + c4 * 4]);
        uint2 hv, lv; split4(val, hv, lv);
        int m = m0 + r;
        int s = m & (S_ - 1);
        int n = n0 + c4 * 4;
        int h = n >> 6, d0 = n & 63;
        size_t o = ((size_t)(b * H_ + h) * S_ + s) * HD_ + d0;
        *reinterpret_cast<uint2*>(outh + o) = hv;
        *reinterpret_cast<uint2*>(outl + o) = lv;
        if (z == 2) *reinterpret_cast<float4*>(g_V + o) = val;
    }
}

// ---------------------------------------------------------------------------
__global__ __launch_bounds__(1024) void suffix_kernel()
{
    __shared__ float part[16][64];
    const int bh = blockIdx.x;
    const int d = threadIdx.x & 63;
    const int g = threadIdx.x >> 6;
    const float* Vp = g_V + (size_t)bh * S_ * HD_ + d;
    float* Sp = g_S + (size_t)bh * S_ * HD_ + d;
    const int row0 = g * 128;

    float acc = 0.f;
    #pragma unroll 8
    for (int s = 0; s < 128; s++) acc += Vp[(size_t)(row0 + s) * HD_];
    part[g][d] = acc;
    __syncthreads();

    float base = 0.f;
    #pragma unroll
    for (int gg = g + 1; gg < 16; gg++) base += part[gg][d];
    for (int s = 127; s >= 0; s--) {
        Sp[(size_t)(row0 + s) * HD_] = base;
        base += Vp[(size_t)(row0 + s) * HD_];
    }
}

// ===========================================================================
// Register-resident flash attention (R10 WIN), restructured to cut register
// peak: QK+exp done in two n-halves so sc[] is only 16 floats live at a time.
// ===========================================================================
#define ROWB 144
#define KTILE_B (64 * ROWB)
#define Q_B (128 * ROWB)
#define STG_B (4 * KTILE_B)
#define ATT_SMEM (2 * Q_B + 2 * STG_B)

__global__ __launch_bounds__(256, 2) void attn_mma_kernel(float* __restrict__ out)
{
    extern __shared__ char smem_raw[];
    const uint32_t sb = smem_u32(smem_raw);
    const uint32_t sQh = sb, sQl = sb + Q_B;
    const uint32_t sStage0 = sb + 2 * Q_B;

    const int tid = threadIdx.x;
    const int wid = tid >> 5;
    const int lane = tid & 31;
    const int qt = (int)gridDim.x - 1 - (int)blockIdx.x;
    const int bh = blockIdx.y;
    const size_t bho = (size_t)bh * S_ * HD_;
    const int qbase = qt * 128;
    const int m0 = wid * 16;

    // Q: 2 arrays x 1024 chunks. 8 per thread.
    {
        #pragma unroll
        for (int i = 0; i < 8; i++) {
            int id = i * 256 + tid;
            int arr = id >> 10;
            int rem = id & 1023;
            int r = rem >> 3, c = rem & 7;
            const __nv_bfloat16* g = (arr ? g_Ql : g_Qh) + bho + (size_t)(qbase + r) * 64 + c * 8;
            CP_ASYNC16((arr ? sQl : sQh) + r * ROWB + c * 16, g);
        }
        CP_COMMIT();
    }
    auto issue_kv = [&](int stage, int kt) {
        uint32_t st = sStage0 + stage * STG_B;
        const size_t to = bho + (size_t)kt * 64 * HD_;
        const __nv_bfloat16* gp[4] = { g_Kh + to, g_Kl + to, g_Vh + to, g_Vl + to };
        #pragma unroll
        for (int i = 0; i < 8; i++) {
            int id = i * 256 + tid;
            int arr = id >> 9;
            int rem = id & 511;
            int r = rem >> 3, c = rem & 7;
            CP_ASYNC16(st + arr * KTILE_B + r * ROWB + c * 16, gp[arr] + (size_t)r * 64 + c * 8);
        }
        CP_COMMIT();
    };
    issue_kv(0, 0);

    const int rA = ((lane >> 3) & 1) * 8 + (lane & 7);
    const int cA = ((lane >> 4) & 1) * 8;
    const int rK = ((lane >> 4) & 1) * 8 + (lane & 7);
    const int cK = ((lane >> 3) & 1) * 8;

    CP_WAIT(1);
    __syncthreads();

    uint32_t qh[4][4];
    #pragma unroll
    for (int kc = 0; kc < 4; kc++)
        LDSM_X4(qh[kc][0], qh[kc][1], qh[kc][2], qh[kc][3],
                sQh + (m0 + rA) * ROWB + (kc * 16 + cA) * 2);

    float oc[8][4];
    #pragma unroll
    for (int i = 0; i < 8; i++)
        #pragma unroll
        for (int j = 0; j < 4; j++) oc[i][j] = 0.f;
    float z0 = 0.f, z1 = 0.f;

    const int rowg0 = qbase + m0 + (lane >> 2);
    const int rowg1 = rowg0 + 8;
    const int ktmax = 2 * qt + 1;

    for (int kt = 0; kt <= ktmax; kt++) {
        CP_WAIT(0);
        __syncthreads();
        if (kt < ktmax) issue_kv((kt + 1) & 1, kt + 1);

        const uint32_t st = sStage0 + (kt & 1) * STG_B;
        const uint32_t stKh = st, stKl = st + KTILE_B;
        const uint32_t stVh = st + 2 * KTILE_B, stVl = st + 3 * KTILE_B;

        uint32_t pah[4][4], pal[4][4];

        // ---- QK + exp in two n-halves (sc only 16 floats live) ----
        #pragma unroll
        for (int hhf = 0; hhf < 2; hhf++) {
            float sc[4][4];
            #pragma unroll
            for (int i = 0; i < 4; i++)
                #pragma unroll
                for (int j = 0; j < 4; j++) sc[i][j] = 0.f;

            #pragma unroll
            for (int kc = 0; kc < 4; kc++) {
                uint32_t ql_[4];
                LDSM_X4(ql_[0], ql_[1], ql_[2], ql_[3],
                        sQl + (m0 + rA) * ROWB + (kc * 16 + cA) * 2);
                #pragma unroll
                for (int g = 0; g < 2; g++) {
                    int ng = 2 * hhf + g;
                    uint32_t bh0, bh1, bh2, bh3, bl0, bl1, bl2, bl3;
                    LDSM_X4(bh0, bh1, bh2, bh3, stKh + (ng * 16 + rK) * ROWB + (kc * 16 + cK) * 2);
                    LDSM_X4(bl0, bl1, bl2, bl3, stKl + (ng * 16 + rK) * ROWB + (kc * 16 + cK) * 2);
                    MMA16816(sc[2 * g],     qh[kc], bh0, bh1);
                    MMA16816(sc[2 * g],     qh[kc], bl0, bl1);
                    MMA16816(sc[2 * g],     ql_,    bh0, bh1);
                    MMA16816(sc[2 * g + 1], qh[kc], bh2, bh3);
                    MMA16816(sc[2 * g + 1], qh[kc], bl2, bl3);
                    MMA16816(sc[2 * g + 1], ql_,    bh2, bh3);
                }
            }

            // exp/mask/Z + repack this half's P into A-frags (kc 2h, 2h+1).
            const int colb = kt * 64 + 2 * (lane & 3);
            #pragma unroll
            for (int j = 0; j < 4; j++) {
                int nt = 4 * hhf + j;
                int col0 = colb + nt * 8;
                float p00 = (col0     <= rowg0) ? fexp(sc[j][0] * 0.125f) : 0.f;
                float p01 = (col0 + 1 <= rowg0) ? fexp(sc[j][1] * 0.125f) : 0.f;
                float p10 = (col0     <= rowg1) ? fexp(sc[j][2] * 0.125f) : 0.f;
                float p11 = (col0 + 1 <= rowg1) ? fexp(sc[j][3] * 0.125f) : 0.f;
                z0 += p00 + p01;
                z1 += p10 + p11;
                float h00 = __bfloat162float(__float2bfloat16(p00));
                float h01 = __bfloat162float(__float2bfloat16(p01));
                float h10 = __bfloat162float(__float2bfloat16(p10));
                float h11 = __bfloat162float(__float2bfloat16(p11));
                int kcp = 2 * hhf + (j >> 1), hf = (j & 1) * 2;
                pah[kcp][hf + 0] = pack_bf16x2(h00, h01);
                pah[kcp][hf + 1] = pack_bf16x2(h10, h11);
                pal[kcp][hf + 0] = pack_bf16x2(p00 - h00, p01 - h01);
                pal[kcp][hf + 1] = pack_bf16x2(p10 - h10, p11 - h11);
            }
        }

        // ---- O += P.V (3-term split) ----
        #pragma unroll
        for (int kc = 0; kc < 4; kc++) {
            #pragma unroll
            for (int dg = 0; dg < 4; dg++) {
                uint32_t vh0, vh1, vh2, vh3, vl0, vl1, vl2, vl3;
                LDSM_X4_T(vh0, vh1, vh2, vh3, stVh + (kc * 16 + rA) * ROWB + (dg * 16 + cA) * 2);
                LDSM_X4_T(vl0, vl1, vl2, vl3, stVl + (kc * 16 + rA) * ROWB + (dg * 16 + cA) * 2);
                MMA16816(oc[2 * dg],     pah[kc], vh0, vh1);
                MMA16816(oc[2 * dg],     pah[kc], vl0, vl1);
                MMA16816(oc[2 * dg],     pal[kc], vh0, vh1);
                MMA16816(oc[2 * dg + 1], pah[kc], vh2, vh3);
                MMA16816(oc[2 * dg + 1], pah[kc], vl2, vl3);
                MMA16816(oc[2 * dg + 1], pal[kc], vh2, vh3);
            }
        }
    }

    // ---- Z reduce, analytic tail, store ----
    z0 += __shfl_xor_sync(0xffffffffu, z0, 1);
    z0 += __shfl_xor_sync(0xffffffffu, z0, 2);
    z1 += __shfl_xor_sync(0xffffffffu, z1, 1);
    z1 += __shfl_xor_sync(0xffffffffu, z1, 2);
    float inv0 = 1.f / (z0 + (float)(S_ - 1 - rowg0));
    float inv1 = 1.f / (z1 + (float)(S_ - 1 - rowg1));

    const int b = bh / H_, h = bh % H_;
    const float* Sufp = g_S + bho;
    #pragma unroll
    for (int nt = 0; nt < 8; nt++) {
        int d = nt * 8 + 2 * (lane & 3);
        float2 s0 = *reinterpret_cast<const float2*>(&Sufp[(size_t)rowg0 * 64 + d]);
        float2 s1 = *reinterpret_cast<const float2*>(&Sufp[(size_t)rowg1 * 64 + d]);
        float2 o0 = make_float2((oc[nt][0] + s0.x) * inv0, (oc[nt][1] + s0.y) * inv0);
        float2 o1 = make_float2((oc[nt][2] + s1.x) * inv1, (oc[nt][3] + s1.y) * inv1);
        *reinterpret_cast<float2*>(&out[((size_t)(b * S_ + rowg0)) * D_ + h * 64 + d]) = o0;
        *reinterpret_cast<float2*>(&out[((size_t)(b * S_ + rowg1)) * D_ + h * 64 + d]) = o1;
    }
}

// ---------------------------------------------------------------------------
extern "C" void kernel_launch(void* const* d_in, const int* in_sizes, int n_in,
                              void* d_out, int out_size)
{
    const float* q  = (const float*)d_in[0];
    const float* k  = (const float*)d_in[1];
    const float* v  = (const float*)d_in[2];
    const float* wq = (const float*)d_in[3];
    const float* wk = (const float*)d_in[4];
    const float* wv = (const float*)d_in[5];
    float* out = (float*)d_out;

    presplit_kernel<<<dim3(256, 6), 256>>>(q, k, v, wq, wk, wv);

    cudaFuncSetAttribute(proj_wmma_kernel,
                         cudaFuncAttributeMaxDynamicSharedMemorySize, PROJ_SMEM);
    proj_wmma_kernel<<<dim3(D_ / 128, (B_ * S_) / 128, 3), 256, PROJ_SMEM>>>();

    suffix_kernel<<<B_ * H_, 1024>>>();

    cudaFuncSetAttribute(attn_mma_kernel,
                         cudaFuncAttributeMaxDynamicSharedMemorySize, ATT_SMEM);
    attn_mma_kernel<<<dim3(S_ / 128, B_ * H_), 256, ATT_SMEM>>>(out);
}

// round 12
// speedup vs baseline: 2.1323x; 1.0869x over previous
#include <cuda_runtime.h>
#include <cuda_bf16.h>
#include <mma.h>
#include <cstdint>
#include <math.h>

using namespace nvcuda;

#define B_  2
#define S_  2048
#define D_  1024
#define H_  16
#define HD_ 64
#define NQ (B_*S_*D_)
#define NW (D_*D_)
#define NP (B_*H_*S_*HD_)

__device__ __nv_bfloat16 g_Ih[3*NQ + 3*NW];
__device__ __nv_bfloat16 g_Il[3*NQ + 3*NW];
__device__ __nv_bfloat16 g_Qh[NP], g_Ql[NP];
__device__ __nv_bfloat16 g_Kh[NP], g_Kl[NP];
__device__ __nv_bfloat16 g_Vh[NP], g_Vl[NP];
__device__ float g_V[NP];
__device__ float g_S[NP];

// ---------------------------------------------------------------------------
__device__ __forceinline__ uint32_t smem_u32(const void* p) {
    uint32_t a;
    asm("{ .reg .u64 t; cvta.to.shared.u64 t, %1; cvt.u32.u64 %0, t; }"
        : "=r"(a) : "l"(p));
    return a;
}
#define CP_ASYNC16(dst, src) \
    asm volatile("cp.async.cg.shared.global [%0], [%1], 16;" :: "r"(dst), "l"(src))
#define CP_COMMIT() asm volatile("cp.async.commit_group;")
#define CP_WAIT(n)  asm volatile("cp.async.wait_group %0;" :: "n"(n))

#define LDSM_X4(r0,r1,r2,r3, addr) \
    asm volatile("ldmatrix.sync.aligned.m8n8.x4.shared.b16 {%0,%1,%2,%3}, [%4];" \
        : "=r"(r0),"=r"(r1),"=r"(r2),"=r"(r3) : "r"(addr))
#define LDSM_X4_T(r0,r1,r2,r3, addr) \
    asm volatile("ldmatrix.sync.aligned.m8n8.x4.trans.shared.b16 {%0,%1,%2,%3}, [%4];" \
        : "=r"(r0),"=r"(r1),"=r"(r2),"=r"(r3) : "r"(addr))
#define MMA16816(c, a, b0, b1) \
    asm volatile("mma.sync.aligned.m16n8k16.row.col.f32.bf16.bf16.f32 " \
        "{%0,%1,%2,%3},{%4,%5,%6,%7},{%8,%9},{%0,%1,%2,%3};" \
        : "+f"((c)[0]),"+f"((c)[1]),"+f"((c)[2]),"+f"((c)[3]) \
        : "r"((a)[0]),"r"((a)[1]),"r"((a)[2]),"r"((a)[3]),"r"(b0),"r"(b1))

__device__ __forceinline__ uint32_t pack_bf16x2(float lo, float hi) {
    __nv_bfloat162 t = __floats2bfloat162_rn(lo, hi);
    return *reinterpret_cast<uint32_t*>(&t);
}

__device__ __forceinline__ void split4(float4 a, uint2& hv, uint2& lv) {
    __nv_bfloat16 h0 = __float2bfloat16(a.x);
    __nv_bfloat16 h1 = __float2bfloat16(a.y);
    __nv_bfloat16 h2 = __float2bfloat16(a.z);
    __nv_bfloat16 h3 = __float2bfloat16(a.w);
    __nv_bfloat16 l0 = __float2bfloat16(a.x - __bfloat162float(h0));
    __nv_bfloat16 l1 = __float2bfloat16(a.y - __bfloat162float(h1));
    __nv_bfloat16 l2 = __float2bfloat16(a.z - __bfloat162float(h2));
    __nv_bfloat16 l3 = __float2bfloat16(a.w - __bfloat162float(h3));
    hv = make_uint2(((uint32_t)__bfloat16_as_ushort(h1) << 16) | __bfloat16_as_ushort(h0),
                    ((uint32_t)__bfloat16_as_ushort(h3) << 16) | __bfloat16_as_ushort(h2));
    lv = make_uint2(((uint32_t)__bfloat16_as_ushort(l1) << 16) | __bfloat16_as_ushort(l0),
                    ((uint32_t)__bfloat16_as_ushort(l3) << 16) | __bfloat16_as_ushort(l2));
}

__device__ __forceinline__ float fexp(float s) {
    float x = s * 1.4426950408889634f;
    float j = x + 12582912.0f;
    float xi = j - 12582912.0f;
    float f = x - xi;
    int e = __float_as_int(j) - 0x4B400000;
    float p = 1.3333558e-3f;
    p = fmaf(p, f, 9.6181291e-3f);
    p = fmaf(p, f, 5.5504109e-2f);
    p = fmaf(p, f, 2.4022651e-1f);
    p = fmaf(p, f, 6.9314718e-1f);
    p = fmaf(p, f, 1.0f);
    return p * __int_as_float((e + 127) << 23);
}

// ---------------------------------------------------------------------------
__global__ __launch_bounds__(256) void presplit_kernel(
    const float* __restrict__ q, const float* __restrict__ k,
    const float* __restrict__ v, const float* __restrict__ wq,
    const float* __restrict__ wk, const float* __restrict__ wv)
{
    const int t = blockIdx.y;
    const float* src = (t == 0) ? q : (t == 1) ? k : (t == 2) ? v
                     : (t == 3) ? wq : (t == 4) ? wk : wv;
    const size_t off = (t < 3) ? (size_t)t * NQ : 3 * (size_t)NQ + (size_t)(t - 3) * NW;
    const int n4 = ((t < 3) ? NQ : NW) >> 2;
    uint2* dh = (uint2*)(g_Ih + off);
    uint2* dl = (uint2*)(g_Il + off);
    for (int i = blockIdx.x * blockDim.x + threadIdx.x; i < n4;
         i += gridDim.x * blockDim.x) {
        float4 a = ((const float4*)src)[i];
        uint2 hv, lv; split4(a, hv, lv);
        dh[i] = hv; dl[i] = lv;
    }
}

// ===========================================================================
// Projection GEMM (unchanged from R8 WIN).
// ===========================================================================
#define BK 32
#define LDA 40
#define ARR_B (128 * LDA * 2)
#define STAGE_B (4 * ARR_B)
#define PROJ_SMEM (2 * STAGE_B)

__global__ __launch_bounds__(256) void proj_wmma_kernel()
{
    extern __shared__ char smem[];
    const int z = blockIdx.z;
    const __nv_bfloat16* Ah_g = g_Ih + (size_t)z * NQ;
    const __nv_bfloat16* Al_g = g_Il + (size_t)z * NQ;
    const __nv_bfloat16* Wh_g = g_Ih + 3 * (size_t)NQ + (size_t)z * NW;
    const __nv_bfloat16* Wl_g = g_Il + 3 * (size_t)NQ + (size_t)z * NW;

    const int tid = threadIdx.x;
    const int wid = tid >> 5;
    const int warp_m = wid >> 1;
    const int warp_n = wid & 1;
    const int m0 = blockIdx.y * 128;
    const int n0 = blockIdx.x * 128;
    const uint32_t sbase = smem_u32(smem);

    const int r0 = tid >> 2, c0 = tid & 3;
    const int r1 = (tid + 256) >> 2, c1 = (tid + 256) & 3;

    auto issue = [&](int stage, int c) {
        const int k0 = c * BK;
        uint32_t sb = sbase + stage * STAGE_B;
        const __nv_bfloat16* gp[4] = {
            Ah_g + (size_t)m0 * D_ + k0, Al_g + (size_t)m0 * D_ + k0,
            Wh_g + (size_t)n0 * D_ + k0, Wl_g + (size_t)n0 * D_ + k0 };
        #pragma unroll
        for (int a = 0; a < 4; a++) {
            CP_ASYNC16(sb + a * ARR_B + r0 * 80 + c0 * 16,
                       gp[a] + (size_t)r0 * D_ + c0 * 8);
            CP_ASYNC16(sb + a * ARR_B + r1 * 80 + c1 * 16,
                       gp[a] + (size_t)r1 * D_ + c1 * 8);
        }
        CP_COMMIT();
    };

    wmma::fragment<wmma::accumulator, 16, 16, 16, float> acc[2][4];
    #pragma unroll
    for (int i = 0; i < 2; i++)
        #pragma unroll
        for (int j = 0; j < 4; j++) wmma::fill_fragment(acc[i][j], 0.0f);

    issue(0, 0);

    for (int c = 0; c < D_ / BK; c++) {
        if (c < D_ / BK - 1) { issue((c + 1) & 1, c + 1); CP_WAIT(1); }
        else                 { CP_WAIT(0); }
        __syncthreads();

        const char* st = smem + (c & 1) * STAGE_B;
        const __nv_bfloat16* Ahs = (const __nv_bfloat16*)(st);
        const __nv_bfloat16* Als = (const __nv_bfloat16*)(st + ARR_B);
        const __nv_bfloat16* Whs = (const __nv_bfloat16*)(st + 2 * ARR_B);
        const __nv_bfloat16* Wls = (const __nv_bfloat16*)(st + 3 * ARR_B);

        #pragma unroll
        for (int kk = 0; kk < BK; kk += 16) {
            wmma::fragment<wmma::matrix_a, 16, 16, 16, __nv_bfloat16, wmma::row_major> aH[2], aL[2];
            wmma::fragment<wmma::matrix_b, 16, 16, 16, __nv_bfloat16, wmma::col_major> bH[4], bL[4];
            #pragma unroll
            for (int i = 0; i < 2; i++) {
                wmma::load_matrix_sync(aH[i], &Ahs[(warp_m * 32 + i * 16) * LDA + kk], LDA);
                wmma::load_matrix_sync(aL[i], &Als[(warp_m * 32 + i * 16) * LDA + kk], LDA);
            }
            #pragma unroll
            for (int j = 0; j < 4; j++) {
                wmma::load_matrix_sync(bH[j], &Whs[(warp_n * 64 + j * 16) * LDA + kk], LDA);
                wmma::load_matrix_sync(bL[j], &Wls[(warp_n * 64 + j * 16) * LDA + kk], LDA);
            }
            #pragma unroll
            for (int i = 0; i < 2; i++)
                #pragma unroll
                for (int j = 0; j < 4; j++) {
                    wmma::mma_sync(acc[i][j], aH[i], bH[j], acc[i][j]);
                    wmma::mma_sync(acc[i][j], aH[i], bL[j], acc[i][j]);
                    wmma::mma_sync(acc[i][j], aL[i], bH[j], acc[i][j]);
                }
        }
        __syncthreads();
    }

    float* st = (float*)smem;
    #pragma unroll
    for (int i = 0; i < 2; i++)
        #pragma unroll
        for (int j = 0; j < 4; j++)
            wmma::store_matrix_sync(&st[(warp_m * 32 + i * 16) * 132 + warp_n * 64 + j * 16],
                                    acc[i][j], 132, wmma::mem_row_major);
    __syncthreads();

    __nv_bfloat16* outh = (z == 0) ? g_Qh : (z == 1) ? g_Kh : g_Vh;
    __nv_bfloat16* outl = (z == 0) ? g_Ql : (z == 1) ? g_Kl : g_Vl;
    const int b = m0 >> 11;
    #pragma unroll
    for (int it = 0; it < 16; it++) {
        int idx = it * 256 + tid;
        int r = idx >> 5, c4 = idx & 31;
        float4 val = *reinterpret_cast<const float4*>(&st[r * 132 + c4 * 4]);
        uint2 hv, lv; split4(val, hv, lv);
        int m = m0 + r;
        int s = m & (S_ - 1);
        int n = n0 + c4 * 4;
        int h = n >> 6, d0 = n & 63;
        size_t o = ((size_t)(b * H_ + h) * S_ + s) * HD_ + d0;
        *reinterpret_cast<uint2*>(outh + o) = hv;
        *reinterpret_cast<uint2*>(outl + o) = lv;
        if (z == 2) *reinterpret_cast<float4*>(g_V + o) = val;
    }
}

// ---------------------------------------------------------------------------
__global__ __launch_bounds__(1024) void suffix_kernel()
{
    __shared__ float part[16][64];
    const int bh = blockIdx.x;
    const int d = threadIdx.x & 63;
    const int g = threadIdx.x >> 6;
    const float* Vp = g_V + (size_t)bh * S_ * HD_ + d;
    float* Sp = g_S + (size_t)bh * S_ * HD_ + d;
    const int row0 = g * 128;

    float acc = 0.f;
    #pragma unroll 8
    for (int s = 0; s < 128; s++) acc += Vp[(size_t)(row0 + s) * HD_];
    part[g][d] = acc;
    __syncthreads();

    float base = 0.f;
    #pragma unroll
    for (int gg = g + 1; gg < 16; gg++) base += part[gg][d];
    for (int s = 127; s >= 0; s--) {
        Sp[(size_t)(row0 + s) * HD_] = base;
        base += Vp[(size_t)(row0 + s) * HD_];
    }
}

// ===========================================================================
// Register-resident flash attention (R11 WIN) + causal work pairing:
// each CTA handles q-tiles {15-x, x} -> exactly 34 kt-iterations per CTA,
// grid 256 -> one balanced wave at 2 CTAs/SM.
// ===========================================================================
#define ROWB 144
#define KTILE_B (64 * ROWB)
#define Q_B (128 * ROWB)
#define STG_B (4 * KTILE_B)
#define ATT_SMEM (2 * Q_B + 2 * STG_B)

__global__ __launch_bounds__(256, 2) void attn_mma_kernel(float* __restrict__ out)
{
    extern __shared__ char smem_raw[];
    const uint32_t sb = smem_u32(smem_raw);
    const uint32_t sQh = sb, sQl = sb + Q_B;
    const uint32_t sStage0 = sb + 2 * Q_B;

    const int tid = threadIdx.x;
    const int wid = tid >> 5;
    const int lane = tid & 31;
    const int pair = blockIdx.x;               // 0..7
    const int bh = blockIdx.y;
    const size_t bho = (size_t)bh * S_ * HD_;
    const int m0 = wid * 16;
    const int NT = S_ / 128;                   // 16 q-tiles

    const int rA = ((lane >> 3) & 1) * 8 + (lane & 7);
    const int cA = ((lane >> 4) & 1) * 8;
    const int rK = ((lane >> 4) & 1) * 8 + (lane & 7);
    const int cK = ((lane >> 3) & 1) * 8;

    auto issue_kv = [&](int stage, int kt) {
        uint32_t st = sStage0 + stage * STG_B;
        const size_t to = bho + (size_t)kt * 64 * HD_;
        const __nv_bfloat16* gp[4] = { g_Kh + to, g_Kl + to, g_Vh + to, g_Vl + to };
        #pragma unroll
        for (int i = 0; i < 8; i++) {
            int id = i * 256 + tid;
            int arr = id >> 9;
            int rem = id & 511;
            int r = rem >> 3, c = rem & 7;
            CP_ASYNC16(st + arr * KTILE_B + r * ROWB + c * 16, gp[arr] + (size_t)r * 64 + c * 8);
        }
        CP_COMMIT();
    };

    const int b = bh / H_, h = bh % H_;
    const float* Sufp = g_S + bho;

    #pragma unroll 1
    for (int seg = 0; seg < 2; seg++) {
        const int qt = seg ? pair : (NT - 1 - pair);   // big tile first
        const int qbase = qt * 128;

        __syncthreads();   // smem (Q + stages) free from previous segment

        // Q: 2 arrays x 1024 chunks. 8 per thread.
        #pragma unroll
        for (int i = 0; i < 8; i++) {
            int id = i * 256 + tid;
            int arr = id >> 10;
            int rem = id & 1023;
            int r = rem >> 3, c = rem & 7;
            const __nv_bfloat16* g = (arr ? g_Ql : g_Qh) + bho + (size_t)(qbase + r) * 64 + c * 8;
            CP_ASYNC16((arr ? sQl : sQh) + r * ROWB + c * 16, g);
        }
        CP_COMMIT();
        issue_kv(0, 0);

        CP_WAIT(1);
        __syncthreads();

        uint32_t qh[4][4];
        #pragma unroll
        for (int kc = 0; kc < 4; kc++)
            LDSM_X4(qh[kc][0], qh[kc][1], qh[kc][2], qh[kc][3],
                    sQh + (m0 + rA) * ROWB + (kc * 16 + cA) * 2);

        float oc[8][4];
        #pragma unroll
        for (int i = 0; i < 8; i++)
            #pragma unroll
            for (int j = 0; j < 4; j++) oc[i][j] = 0.f;
        float z0 = 0.f, z1 = 0.f;

        const int rowg0 = qbase + m0 + (lane >> 2);
        const int rowg1 = rowg0 + 8;
        const int ktmax = 2 * qt + 1;

        for (int kt = 0; kt <= ktmax; kt++) {
            CP_WAIT(0);
            __syncthreads();
            if (kt < ktmax) issue_kv((kt + 1) & 1, kt + 1);

            const uint32_t st = sStage0 + (kt & 1) * STG_B;
            const uint32_t stKh = st, stKl = st + KTILE_B;
            const uint32_t stVh = st + 2 * KTILE_B, stVl = st + 3 * KTILE_B;

            uint32_t pah[4][4], pal[4][4];

            // ---- QK + exp in two n-halves ----
            #pragma unroll
            for (int hhf = 0; hhf < 2; hhf++) {
                float sc[4][4];
                #pragma unroll
                for (int i = 0; i < 4; i++)
                    #pragma unroll
                    for (int j = 0; j < 4; j++) sc[i][j] = 0.f;

                #pragma unroll
                for (int kc = 0; kc < 4; kc++) {
                    uint32_t ql_[4];
                    LDSM_X4(ql_[0], ql_[1], ql_[2], ql_[3],
                            sQl + (m0 + rA) * ROWB + (kc * 16 + cA) * 2);
                    #pragma unroll
                    for (int g = 0; g < 2; g++) {
                        int ng = 2 * hhf + g;
                        uint32_t bh0, bh1, bh2, bh3, bl0, bl1, bl2, bl3;
                        LDSM_X4(bh0, bh1, bh2, bh3, stKh + (ng * 16 + rK) * ROWB + (kc * 16 + cK) * 2);
                        LDSM_X4(bl0, bl1, bl2, bl3, stKl + (ng * 16 + rK) * ROWB + (kc * 16 + cK) * 2);
                        MMA16816(sc[2 * g],     qh[kc], bh0, bh1);
                        MMA16816(sc[2 * g],     qh[kc], bl0, bl1);
                        MMA16816(sc[2 * g],     ql_,    bh0, bh1);
                        MMA16816(sc[2 * g + 1], qh[kc], bh2, bh3);
                        MMA16816(sc[2 * g + 1], qh[kc], bl2, bl3);
                        MMA16816(sc[2 * g + 1], ql_,    bh2, bh3);
                    }
                }

                // exp/mask/Z + repack this half's P (hi via bf16x2 cvt + exact
                // bit-unpack; residuals via one more bf16x2 cvt).
                const int colb = kt * 64 + 2 * (lane & 3);
                #pragma unroll
                for (int j = 0; j < 4; j++) {
                    int nt = 4 * hhf + j;
                    int col0 = colb + nt * 8;
                    float p00 = (col0     <= rowg0) ? fexp(sc[j][0] * 0.125f) : 0.f;
                    float p01 = (col0 + 1 <= rowg0) ? fexp(sc[j][1] * 0.125f) : 0.f;
                    float p10 = (col0     <= rowg1) ? fexp(sc[j][2] * 0.125f) : 0.f;
                    float p11 = (col0 + 1 <= rowg1) ? fexp(sc[j][3] * 0.125f) : 0.f;
                    z0 += p00 + p01;
                    z1 += p10 + p11;
                    uint32_t hiw0 = pack_bf16x2(p00, p01);
                    uint32_t hiw1 = pack_bf16x2(p10, p11);
                    float f00 = __uint_as_float(hiw0 << 16);
                    float f01 = __uint_as_float(hiw0 & 0xFFFF0000u);
                    float f10 = __uint_as_float(hiw1 << 16);
                    float f11 = __uint_as_float(hiw1 & 0xFFFF0000u);
                    int kcp = 2 * hhf + (j >> 1), hf = (j & 1) * 2;
                    pah[kcp][hf + 0] = hiw0;
                    pah[kcp][hf + 1] = hiw1;
                    pal[kcp][hf + 0] = pack_bf16x2(p00 - f00, p01 - f01);
                    pal[kcp][hf + 1] = pack_bf16x2(p10 - f10, p11 - f11);
                }
            }

            // ---- O += P.V (3-term split) ----
            #pragma unroll
            for (int kc = 0; kc < 4; kc++) {
                #pragma unroll
                for (int dg = 0; dg < 4; dg++) {
                    uint32_t vh0, vh1, vh2, vh3, vl0, vl1, vl2, vl3;
                    LDSM_X4_T(vh0, vh1, vh2, vh3, stVh + (kc * 16 + rA) * ROWB + (dg * 16 + cA) * 2);
                    LDSM_X4_T(vl0, vl1, vl2, vl3, stVl + (kc * 16 + rA) * ROWB + (dg * 16 + cA) * 2);
                    MMA16816(oc[2 * dg],     pah[kc], vh0, vh1);
                    MMA16816(oc[2 * dg],     pah[kc], vl0, vl1);
                    MMA16816(oc[2 * dg],     pal[kc], vh0, vh1);
                    MMA16816(oc[2 * dg + 1], pah[kc], vh2, vh3);
                    MMA16816(oc[2 * dg + 1], pah[kc], vl2, vl3);
                    MMA16816(oc[2 * dg + 1], pal[kc], vh2, vh3);
                }
            }
        }

        // ---- Z reduce, analytic tail, store ----
        z0 += __shfl_xor_sync(0xffffffffu, z0, 1);
        z0 += __shfl_xor_sync(0xffffffffu, z0, 2);
        z1 += __shfl_xor_sync(0xffffffffu, z1, 1);
        z1 += __shfl_xor_sync(0xffffffffu, z1, 2);
        float inv0 = 1.f / (z0 + (float)(S_ - 1 - rowg0));
        float inv1 = 1.f / (z1 + (float)(S_ - 1 - rowg1));

        #pragma unroll
        for (int nt = 0; nt < 8; nt++) {
            int d = nt * 8 + 2 * (lane & 3);
            float2 s0 = *reinterpret_cast<const float2*>(&Sufp[(size_t)rowg0 * 64 + d]);
            float2 s1 = *reinterpret_cast<const float2*>(&Sufp[(size_t)rowg1 * 64 + d]);
            float2 o0 = make_float2((oc[nt][0] + s0.x) * inv0, (oc[nt][1] + s0.y) * inv0);
            float2 o1 = make_float2((oc[nt][2] + s1.x) * inv1, (oc[nt][3] + s1.y) * inv1);
            *reinterpret_cast<float2*>(&out[((size_t)(b * S_ + rowg0)) * D_ + h * 64 + d]) = o0;
            *reinterpret_cast<float2*>(&out[((size_t)(b * S_ + rowg1)) * D_ + h * 64 + d]) = o1;
        }
    }
}

// ---------------------------------------------------------------------------
extern "C" void kernel_launch(void* const* d_in, const int* in_sizes, int n_in,
                              void* d_out, int out_size)
{
    const float* q  = (const float*)d_in[0];
    const float* k  = (const float*)d_in[1];
    const float* v  = (const float*)d_in[2];
    const float* wq = (const float*)d_in[3];
    const float* wk = (const float*)d_in[4];
    const float* wv = (const float*)d_in[5];
    float* out = (float*)d_out;

    presplit_kernel<<<dim3(256, 6), 256>>>(q, k, v, wq, wk, wv);

    cudaFuncSetAttribute(proj_wmma_kernel,
                         cudaFuncAttributeMaxDynamicSharedMemorySize, PROJ_SMEM);
    proj_wmma_kernel<<<dim3(D_ / 128, (B_ * S_) / 128, 3), 256, PROJ_SMEM>>>();

    suffix_kernel<<<B_ * H_, 1024>>>();

    cudaFuncSetAttribute(attn_mma_kernel,
                         cudaFuncAttributeMaxDynamicSharedMemorySize, ATT_SMEM);
    attn_mma_kernel<<<dim3(S_ / 256, B_ * H_), 256, ATT_SMEM>>>(out);
}

// round 13
// speedup vs baseline: 2.2353x; 1.0483x over previous
#include <cuda_runtime.h>
#include <cuda_bf16.h>
#include <mma.h>
#include <cstdint>
#include <math.h>

using namespace nvcuda;

#define B_  2
#define S_  2048
#define D_  1024
#define H_  16
#define HD_ 64
#define NQ (B_*S_*D_)
#define NW (D_*D_)
#define NP (B_*H_*S_*HD_)

__device__ __nv_bfloat16 g_Ih[3*NQ + 3*NW];
__device__ __nv_bfloat16 g_Il[3*NQ + 3*NW];
__device__ __nv_bfloat16 g_Qh[NP], g_Ql[NP];
__device__ __nv_bfloat16 g_Kh[NP], g_Kl[NP];
__device__ __nv_bfloat16 g_Vh[NP], g_Vl[NP];
__device__ float g_V[NP];
__device__ float g_S[NP];

// ---------------------------------------------------------------------------
__device__ __forceinline__ uint32_t smem_u32(const void* p) {
    uint32_t a;
    asm("{ .reg .u64 t; cvta.to.shared.u64 t, %1; cvt.u32.u64 %0, t; }"
        : "=r"(a) : "l"(p));
    return a;
}
#define CP_ASYNC16(dst, src) \
    asm volatile("cp.async.cg.shared.global [%0], [%1], 16;" :: "r"(dst), "l"(src))
#define CP_COMMIT() asm volatile("cp.async.commit_group;")
#define CP_WAIT(n)  asm volatile("cp.async.wait_group %0;" :: "n"(n))

#define LDSM_X4(r0,r1,r2,r3, addr) \
    asm volatile("ldmatrix.sync.aligned.m8n8.x4.shared.b16 {%0,%1,%2,%3}, [%4];" \
        : "=r"(r0),"=r"(r1),"=r"(r2),"=r"(r3) : "r"(addr))
#define LDSM_X4_T(r0,r1,r2,r3, addr) \
    asm volatile("ldmatrix.sync.aligned.m8n8.x4.trans.shared.b16 {%0,%1,%2,%3}, [%4];" \
        : "=r"(r0),"=r"(r1),"=r"(r2),"=r"(r3) : "r"(addr))
#define MMA16816(c, a, b0, b1) \
    asm volatile("mma.sync.aligned.m16n8k16.row.col.f32.bf16.bf16.f32 " \
        "{%0,%1,%2,%3},{%4,%5,%6,%7},{%8,%9},{%0,%1,%2,%3};" \
        : "+f"((c)[0]),"+f"((c)[1]),"+f"((c)[2]),"+f"((c)[3]) \
        : "r"((a)[0]),"r"((a)[1]),"r"((a)[2]),"r"((a)[3]),"r"(b0),"r"(b1))

__device__ __forceinline__ uint32_t pack_bf16x2(float lo, float hi) {
    __nv_bfloat162 t = __floats2bfloat162_rn(lo, hi);
    return *reinterpret_cast<uint32_t*>(&t);
}

__device__ __forceinline__ void split4(float4 a, uint2& hv, uint2& lv) {
    __nv_bfloat16 h0 = __float2bfloat16(a.x);
    __nv_bfloat16 h1 = __float2bfloat16(a.y);
    __nv_bfloat16 h2 = __float2bfloat16(a.z);
    __nv_bfloat16 h3 = __float2bfloat16(a.w);
    __nv_bfloat16 l0 = __float2bfloat16(a.x - __bfloat162float(h0));
    __nv_bfloat16 l1 = __float2bfloat16(a.y - __bfloat162float(h1));
    __nv_bfloat16 l2 = __float2bfloat16(a.z - __bfloat162float(h2));
    __nv_bfloat16 l3 = __float2bfloat16(a.w - __bfloat162float(h3));
    hv = make_uint2(((uint32_t)__bfloat16_as_ushort(h1) << 16) | __bfloat16_as_ushort(h0),
                    ((uint32_t)__bfloat16_as_ushort(h3) << 16) | __bfloat16_as_ushort(h2));
    lv = make_uint2(((uint32_t)__bfloat16_as_ushort(l1) << 16) | __bfloat16_as_ushort(l0),
                    ((uint32_t)__bfloat16_as_ushort(l3) << 16) | __bfloat16_as_ushort(l2));
}

__device__ __forceinline__ float fexp(float s) {
    float x = s * 1.4426950408889634f;
    float j = x + 12582912.0f;
    float xi = j - 12582912.0f;
    float f = x - xi;
    int e = __float_as_int(j) - 0x4B400000;
    float p = 1.3333558e-3f;
    p = fmaf(p, f, 9.6181291e-3f);
    p = fmaf(p, f, 5.5504109e-2f);
    p = fmaf(p, f, 2.4022651e-1f);
    p = fmaf(p, f, 6.9314718e-1f);
    p = fmaf(p, f, 1.0f);
    return p * __int_as_float((e + 127) << 23);
}

// ---------------------------------------------------------------------------
__global__ __launch_bounds__(256) void presplit_kernel(
    const float* __restrict__ q, const float* __restrict__ k,
    const float* __restrict__ v, const float* __restrict__ wq,
    const float* __restrict__ wk, const float* __restrict__ wv)
{
    const int t = blockIdx.y;
    const float* src = (t == 0) ? q : (t == 1) ? k : (t == 2) ? v
                     : (t == 3) ? wq : (t == 4) ? wk : wv;
    const size_t off = (t < 3) ? (size_t)t * NQ : 3 * (size_t)NQ + (size_t)(t - 3) * NW;
    const int n4 = ((t < 3) ? NQ : NW) >> 2;
    uint2* dh = (uint2*)(g_Ih + off);
    uint2* dl = (uint2*)(g_Il + off);
    for (int i = blockIdx.x * blockDim.x + threadIdx.x; i < n4;
         i += gridDim.x * blockDim.x) {
        float4 a = ((const float4*)src)[i];
        uint2 hv, lv; split4(a, hv, lv);
        dh[i] = hv; dl[i] = lv;
    }
}

// ===========================================================================
// Projection GEMM: wmma bf16 split, cp.async double-buffered, now 2 CTAs/SM
// (regs capped at 128 via launch bounds; only one b-frag pair live at a time).
// ===========================================================================
#define BK 32
#define LDA 40
#define ARR_B (128 * LDA * 2)
#define STAGE_B (4 * ARR_B)
#define PROJ_SMEM (2 * STAGE_B)

__global__ __launch_bounds__(256, 2) void proj_wmma_kernel()
{
    extern __shared__ char smem[];
    const int z = blockIdx.z;
    const __nv_bfloat16* Ah_g = g_Ih + (size_t)z * NQ;
    const __nv_bfloat16* Al_g = g_Il + (size_t)z * NQ;
    const __nv_bfloat16* Wh_g = g_Ih + 3 * (size_t)NQ + (size_t)z * NW;
    const __nv_bfloat16* Wl_g = g_Il + 3 * (size_t)NQ + (size_t)z * NW;

    const int tid = threadIdx.x;
    const int wid = tid >> 5;
    const int warp_m = wid >> 1;
    const int warp_n = wid & 1;
    const int m0 = blockIdx.y * 128;
    const int n0 = blockIdx.x * 128;
    const uint32_t sbase = smem_u32(smem);

    const int r0 = tid >> 2, c0 = tid & 3;
    const int r1 = (tid + 256) >> 2, c1 = (tid + 256) & 3;

    auto issue = [&](int stage, int c) {
        const int k0 = c * BK;
        uint32_t sb = sbase + stage * STAGE_B;
        const __nv_bfloat16* gp[4] = {
            Ah_g + (size_t)m0 * D_ + k0, Al_g + (size_t)m0 * D_ + k0,
            Wh_g + (size_t)n0 * D_ + k0, Wl_g + (size_t)n0 * D_ + k0 };
        #pragma unroll
        for (int a = 0; a < 4; a++) {
            CP_ASYNC16(sb + a * ARR_B + r0 * 80 + c0 * 16,
                       gp[a] + (size_t)r0 * D_ + c0 * 8);
            CP_ASYNC16(sb + a * ARR_B + r1 * 80 + c1 * 16,
                       gp[a] + (size_t)r1 * D_ + c1 * 8);
        }
        CP_COMMIT();
    };

    wmma::fragment<wmma::accumulator, 16, 16, 16, float> acc[2][4];
    #pragma unroll
    for (int i = 0; i < 2; i++)
        #pragma unroll
        for (int j = 0; j < 4; j++) wmma::fill_fragment(acc[i][j], 0.0f);

    issue(0, 0);

    for (int c = 0; c < D_ / BK; c++) {
        if (c < D_ / BK - 1) { issue((c + 1) & 1, c + 1); CP_WAIT(1); }
        else                 { CP_WAIT(0); }
        __syncthreads();

        const char* st = smem + (c & 1) * STAGE_B;
        const __nv_bfloat16* Ahs = (const __nv_bfloat16*)(st);
        const __nv_bfloat16* Als = (const __nv_bfloat16*)(st + ARR_B);
        const __nv_bfloat16* Whs = (const __nv_bfloat16*)(st + 2 * ARR_B);
        const __nv_bfloat16* Wls = (const __nv_bfloat16*)(st + 3 * ARR_B);

        #pragma unroll
        for (int kk = 0; kk < BK; kk += 16) {
            wmma::fragment<wmma::matrix_a, 16, 16, 16, __nv_bfloat16, wmma::row_major> aH[2], aL[2];
            #pragma unroll
            for (int i = 0; i < 2; i++) {
                wmma::load_matrix_sync(aH[i], &Ahs[(warp_m * 32 + i * 16) * LDA + kk], LDA);
                wmma::load_matrix_sync(aL[i], &Als[(warp_m * 32 + i * 16) * LDA + kk], LDA);
            }
            // One (bH,bL) pair live at a time -> peak regs fit 2 CTAs/SM.
            #pragma unroll
            for (int j = 0; j < 4; j++) {
                wmma::fragment<wmma::matrix_b, 16, 16, 16, __nv_bfloat16, wmma::col_major> bH, bL;
                wmma::load_matrix_sync(bH, &Whs[(warp_n * 64 + j * 16) * LDA + kk], LDA);
                wmma::load_matrix_sync(bL, &Wls[(warp_n * 64 + j * 16) * LDA + kk], LDA);
                #pragma unroll
                for (int i = 0; i < 2; i++) {
                    wmma::mma_sync(acc[i][j], aH[i], bH, acc[i][j]);
                    wmma::mma_sync(acc[i][j], aH[i], bL, acc[i][j]);
                    wmma::mma_sync(acc[i][j], aL[i], bH, acc[i][j]);
                }
            }
        }
        __syncthreads();
    }

    float* st = (float*)smem;
    #pragma unroll
    for (int i = 0; i < 2; i++)
        #pragma unroll
        for (int j = 0; j < 4; j++)
            wmma::store_matrix_sync(&st[(warp_m * 32 + i * 16) * 132 + warp_n * 64 + j * 16],
                                    acc[i][j], 132, wmma::mem_row_major);
    __syncthreads();

    __nv_bfloat16* outh = (z == 0) ? g_Qh : (z == 1) ? g_Kh : g_Vh;
    __nv_bfloat16* outl = (z == 0) ? g_Ql : (z == 1) ? g_Kl : g_Vl;
    const int b = m0 >> 11;
    #pragma unroll
    for (int it = 0; it < 16; it++) {
        int idx = it * 256 + tid;
        int r = idx >> 5, c4 = idx & 31;
        float4 val = *reinterpret_cast<const float4*>(&st[r * 132 + c4 * 4]);
        uint2 hv, lv; split4(val, hv, lv);
        int m = m0 + r;
        int s = m & (S_ - 1);
        int n = n0 + c4 * 4;
        int h = n >> 6, d0 = n & 63;
        size_t o = ((size_t)(b * H_ + h) * S_ + s) * HD_ + d0;
        *reinterpret_cast<uint2*>(outh + o) = hv;
        *reinterpret_cast<uint2*>(outl + o) = lv;
        if (z == 2) *reinterpret_cast<float4*>(g_V + o) = val;
    }
}

// ---------------------------------------------------------------------------
__global__ __launch_bounds__(1024) void suffix_kernel()
{
    __shared__ float part[16][64];
    const int bh = blockIdx.x;
    const int d = threadIdx.x & 63;
    const int g = threadIdx.x >> 6;
    const float* Vp = g_V + (size_t)bh * S_ * HD_ + d;
    float* Sp = g_S + (size_t)bh * S_ * HD_ + d;
    const int row0 = g * 128;

    float acc = 0.f;
    #pragma unroll 8
    for (int s = 0; s < 128; s++) acc += Vp[(size_t)(row0 + s) * HD_];
    part[g][d] = acc;
    __syncthreads();

    float base = 0.f;
    #pragma unroll
    for (int gg = g + 1; gg < 16; gg++) base += part[gg][d];
    for (int s = 127; s >= 0; s--) {
        Sp[(size_t)(row0 + s) * HD_] = base;
        base += Vp[(size_t)(row0 + s) * HD_];
    }
}

// ===========================================================================
// Register-resident flash attention (R12 WIN, unchanged).
// ===========================================================================
#define ROWB 144
#define KTILE_B (64 * ROWB)
#define Q_B (128 * ROWB)
#define STG_B (4 * KTILE_B)
#define ATT_SMEM (2 * Q_B + 2 * STG_B)

__global__ __launch_bounds__(256, 2) void attn_mma_kernel(float* __restrict__ out)
{
    extern __shared__ char smem_raw[];
    const uint32_t sb = smem_u32(smem_raw);
    const uint32_t sQh = sb, sQl = sb + Q_B;
    const uint32_t sStage0 = sb + 2 * Q_B;

    const int tid = threadIdx.x;
    const int wid = tid >> 5;
    const int lane = tid & 31;
    const int pair = blockIdx.x;
    const int bh = blockIdx.y;
    const size_t bho = (size_t)bh * S_ * HD_;
    const int m0 = wid * 16;
    const int NT = S_ / 128;

    const int rA = ((lane >> 3) & 1) * 8 + (lane & 7);
    const int cA = ((lane >> 4) & 1) * 8;
    const int rK = ((lane >> 4) & 1) * 8 + (lane & 7);
    const int cK = ((lane >> 3) & 1) * 8;

    auto issue_kv = [&](int stage, int kt) {
        uint32_t st = sStage0 + stage * STG_B;
        const size_t to = bho + (size_t)kt * 64 * HD_;
        const __nv_bfloat16* gp[4] = { g_Kh + to, g_Kl + to, g_Vh + to, g_Vl + to };
        #pragma unroll
        for (int i = 0; i < 8; i++) {
            int id = i * 256 + tid;
            int arr = id >> 9;
            int rem = id & 511;
            int r = rem >> 3, c = rem & 7;
            CP_ASYNC16(st + arr * KTILE_B + r * ROWB + c * 16, gp[arr] + (size_t)r * 64 + c * 8);
        }
        CP_COMMIT();
    };

    const int b = bh / H_, h = bh % H_;
    const float* Sufp = g_S + bho;

    #pragma unroll 1
    for (int seg = 0; seg < 2; seg++) {
        const int qt = seg ? pair : (NT - 1 - pair);
        const int qbase = qt * 128;

        __syncthreads();

        #pragma unroll
        for (int i = 0; i < 8; i++) {
            int id = i * 256 + tid;
            int arr = id >> 10;
            int rem = id & 1023;
            int r = rem >> 3, c = rem & 7;
            const __nv_bfloat16* g = (arr ? g_Ql : g_Qh) + bho + (size_t)(qbase + r) * 64 + c * 8;
            CP_ASYNC16((arr ? sQl : sQh) + r * ROWB + c * 16, g);
        }
        CP_COMMIT();
        issue_kv(0, 0);

        CP_WAIT(1);
        __syncthreads();

        uint32_t qh[4][4];
        #pragma unroll
        for (int kc = 0; kc < 4; kc++)
            LDSM_X4(qh[kc][0], qh[kc][1], qh[kc][2], qh[kc][3],
                    sQh + (m0 + rA) * ROWB + (kc * 16 + cA) * 2);

        float oc[8][4];
        #pragma unroll
        for (int i = 0; i < 8; i++)
            #pragma unroll
            for (int j = 0; j < 4; j++) oc[i][j] = 0.f;
        float z0 = 0.f, z1 = 0.f;

        const int rowg0 = qbase + m0 + (lane >> 2);
        const int rowg1 = rowg0 + 8;
        const int ktmax = 2 * qt + 1;

        for (int kt = 0; kt <= ktmax; kt++) {
            CP_WAIT(0);
            __syncthreads();
            if (kt < ktmax) issue_kv((kt + 1) & 1, kt + 1);

            const uint32_t st = sStage0 + (kt & 1) * STG_B;
            const uint32_t stKh = st, stKl = st + KTILE_B;
            const uint32_t stVh = st + 2 * KTILE_B, stVl = st + 3 * KTILE_B;

            uint32_t pah[4][4], pal[4][4];

            #pragma unroll
            for (int hhf = 0; hhf < 2; hhf++) {
                float sc[4][4];
                #pragma unroll
                for (int i = 0; i < 4; i++)
                    #pragma unroll
                    for (int j = 0; j < 4; j++) sc[i][j] = 0.f;

                #pragma unroll
                for (int kc = 0; kc < 4; kc++) {
                    uint32_t ql_[4];
                    LDSM_X4(ql_[0], ql_[1], ql_[2], ql_[3],
                            sQl + (m0 + rA) * ROWB + (kc * 16 + cA) * 2);
                    #pragma unroll
                    for (int g = 0; g < 2; g++) {
                        int ng = 2 * hhf + g;
                        uint32_t bh0, bh1, bh2, bh3, bl0, bl1, bl2, bl3;
                        LDSM_X4(bh0, bh1, bh2, bh3, stKh + (ng * 16 + rK) * ROWB + (kc * 16 + cK) * 2);
                        LDSM_X4(bl0, bl1, bl2, bl3, stKl + (ng * 16 + rK) * ROWB + (kc * 16 + cK) * 2);
                        MMA16816(sc[2 * g],     qh[kc], bh0, bh1);
                        MMA16816(sc[2 * g],     qh[kc], bl0, bl1);
                        MMA16816(sc[2 * g],     ql_,    bh0, bh1);
                        MMA16816(sc[2 * g + 1], qh[kc], bh2, bh3);
                        MMA16816(sc[2 * g + 1], qh[kc], bl2, bl3);
                        MMA16816(sc[2 * g + 1], ql_,    bh2, bh3);
                    }
                }

                const int colb = kt * 64 + 2 * (lane & 3);
                #pragma unroll
                for (int j = 0; j < 4; j++) {
                    int nt = 4 * hhf + j;
                    int col0 = colb + nt * 8;
                    float p00 = (col0     <= rowg0) ? fexp(sc[j][0] * 0.125f) : 0.f;
                    float p01 = (col0 + 1 <= rowg0) ? fexp(sc[j][1] * 0.125f) : 0.f;
                    float p10 = (col0     <= rowg1) ? fexp(sc[j][2] * 0.125f) : 0.f;
                    float p11 = (col0 + 1 <= rowg1) ? fexp(sc[j][3] * 0.125f) : 0.f;
                    z0 += p00 + p01;
                    z1 += p10 + p11;
                    uint32_t hiw0 = pack_bf16x2(p00, p01);
                    uint32_t hiw1 = pack_bf16x2(p10, p11);
                    float f00 = __uint_as_float(hiw0 << 16);
                    float f01 = __uint_as_float(hiw0 & 0xFFFF0000u);
                    float f10 = __uint_as_float(hiw1 << 16);
                    float f11 = __uint_as_float(hiw1 & 0xFFFF0000u);
                    int kcp = 2 * hhf + (j >> 1), hf = (j & 1) * 2;
                    pah[kcp][hf + 0] = hiw0;
                    pah[kcp][hf + 1] = hiw1;
                    pal[kcp][hf + 0] = pack_bf16x2(p00 - f00, p01 - f01);
                    pal[kcp][hf + 1] = pack_bf16x2(p10 - f10, p11 - f11);
                }
            }

            #pragma unroll
            for (int kc = 0; kc < 4; kc++) {
                #pragma unroll
                for (int dg = 0; dg < 4; dg++) {
                    uint32_t vh0, vh1, vh2, vh3, vl0, vl1, vl2, vl3;
                    LDSM_X4_T(vh0, vh1, vh2, vh3, stVh + (kc * 16 + rA) * ROWB + (dg * 16 + cA) * 2);
                    LDSM_X4_T(vl0, vl1, vl2, vl3, stVl + (kc * 16 + rA) * ROWB + (dg * 16 + cA) * 2);
                    MMA16816(oc[2 * dg],     pah[kc], vh0, vh1);
                    MMA16816(oc[2 * dg],     pah[kc], vl0, vl1);
                    MMA16816(oc[2 * dg],     pal[kc], vh0, vh1);
                    MMA16816(oc[2 * dg + 1], pah[kc], vh2, vh3);
                    MMA16816(oc[2 * dg + 1], pah[kc], vl2, vl3);
                    MMA16816(oc[2 * dg + 1], pal[kc], vh2, vh3);
                }
            }
        }

        z0 += __shfl_xor_sync(0xffffffffu, z0, 1);
        z0 += __shfl_xor_sync(0xffffffffu, z0, 2);
        z1 += __shfl_xor_sync(0xffffffffu, z1, 1);
        z1 += __shfl_xor_sync(0xffffffffu, z1, 2);
        float inv0 = 1.f / (z0 + (float)(S_ - 1 - rowg0));
        float inv1 = 1.f / (z1 + (float)(S_ - 1 - rowg1));

        #pragma unroll
        for (int nt = 0; nt < 8; nt++) {
            int d = nt * 8 + 2 * (lane & 3);
            float2 s0 = *reinterpret_cast<const float2*>(&Sufp[(size_t)rowg0 * 64 + d]);
            float2 s1 = *reinterpret_cast<const float2*>(&Sufp[(size_t)rowg1 * 64 + d]);
            float2 o0 = make_float2((oc[nt][0] + s0.x) * inv0, (oc[nt][1] + s0.y) * inv0);
            float2 o1 = make_float2((oc[nt][2] + s1.x) * inv1, (oc[nt][3] + s1.y) * inv1);
            *reinterpret_cast<float2*>(&out[((size_t)(b * S_ + rowg0)) * D_ + h * 64 + d]) = o0;
            *reinterpret_cast<float2*>(&out[((size_t)(b * S_ + rowg1)) * D_ + h * 64 + d]) = o1;
        }
    }
}

// ---------------------------------------------------------------------------
extern "C" void kernel_launch(void* const* d_in, const int* in_sizes, int n_in,
                              void* d_out, int out_size)
{
    const float* q  = (const float*)d_in[0];
    const float* k  = (const float*)d_in[1];
    const float* v  = (const float*)d_in[2];
    const float* wq = (const float*)d_in[3];
    const float* wk = (const float*)d_in[4];
    const float* wv = (const float*)d_in[5];
    float* out = (float*)d_out;

    presplit_kernel<<<dim3(256, 6), 256>>>(q, k, v, wq, wk, wv);

    cudaFuncSetAttribute(proj_wmma_kernel,
                         cudaFuncAttributeMaxDynamicSharedMemorySize, PROJ_SMEM);
    proj_wmma_kernel<<<dim3(D_ / 128, (B_ * S_) / 128, 3), 256, PROJ_SMEM>>>();

    suffix_kernel<<<B_ * H_, 1024>>>();

    cudaFuncSetAttribute(attn_mma_kernel,
                         cudaFuncAttributeMaxDynamicSharedMemorySize, ATT_SMEM);
    attn_mma_kernel<<<dim3(S_ / 256, B_ * H_), 256, ATT_SMEM>>>(out);
}

// round 14
// speedup vs baseline: 2.3057x; 1.0315x over previous
#include <cuda_runtime.h>
#include <cuda_bf16.h>
#include <mma.h>
#include <cstdint>
#include <math.h>

using namespace nvcuda;

#define B_  2
#define S_  2048
#define D_  1024
#define H_  16
#define HD_ 64
#define NQ (B_*S_*D_)
#define NW (D_*D_)
#define NP (B_*H_*S_*HD_)

__device__ __nv_bfloat16 g_Ih[3*NQ + 3*NW];
__device__ __nv_bfloat16 g_Il[3*NQ + 3*NW];
__device__ __nv_bfloat16 g_Qh[NP], g_Ql[NP];
__device__ __nv_bfloat16 g_Kh[NP], g_Kl[NP];
__device__ __nv_bfloat16 g_Vh[NP], g_Vl[NP];
__device__ float g_V[NP];
__device__ float g_S[NP];

// ---------------------------------------------------------------------------
__device__ __forceinline__ uint32_t smem_u32(const void* p) {
    uint32_t a;
    asm("{ .reg .u64 t; cvta.to.shared.u64 t, %1; cvt.u32.u64 %0, t; }"
        : "=r"(a) : "l"(p));
    return a;
}
#define CP_ASYNC16(dst, src) \
    asm volatile("cp.async.cg.shared.global [%0], [%1], 16;" :: "r"(dst), "l"(src))
#define CP_COMMIT() asm volatile("cp.async.commit_group;")
#define CP_WAIT(n)  asm volatile("cp.async.wait_group %0;" :: "n"(n))

#define LDSM_X4(r0,r1,r2,r3, addr) \
    asm volatile("ldmatrix.sync.aligned.m8n8.x4.shared.b16 {%0,%1,%2,%3}, [%4];" \
        : "=r"(r0),"=r"(r1),"=r"(r2),"=r"(r3) : "r"(addr))
#define LDSM_X4_T(r0,r1,r2,r3, addr) \
    asm volatile("ldmatrix.sync.aligned.m8n8.x4.trans.shared.b16 {%0,%1,%2,%3}, [%4];" \
        : "=r"(r0),"=r"(r1),"=r"(r2),"=r"(r3) : "r"(addr))
#define MMA16816(c, a, b0, b1) \
    asm volatile("mma.sync.aligned.m16n8k16.row.col.f32.bf16.bf16.f32 " \
        "{%0,%1,%2,%3},{%4,%5,%6,%7},{%8,%9},{%0,%1,%2,%3};" \
        : "+f"((c)[0]),"+f"((c)[1]),"+f"((c)[2]),"+f"((c)[3]) \
        : "r"((a)[0]),"r"((a)[1]),"r"((a)[2]),"r"((a)[3]),"r"(b0),"r"(b1))

__device__ __forceinline__ uint32_t pack_bf16x2(float lo, float hi) {
    __nv_bfloat162 t = __floats2bfloat162_rn(lo, hi);
    return *reinterpret_cast<uint32_t*>(&t);
}

__device__ __forceinline__ void split4(float4 a, uint2& hv, uint2& lv) {
    __nv_bfloat16 h0 = __float2bfloat16(a.x);
    __nv_bfloat16 h1 = __float2bfloat16(a.y);
    __nv_bfloat16 h2 = __float2bfloat16(a.z);
    __nv_bfloat16 h3 = __float2bfloat16(a.w);
    __nv_bfloat16 l0 = __float2bfloat16(a.x - __bfloat162float(h0));
    __nv_bfloat16 l1 = __float2bfloat16(a.y - __bfloat162float(h1));
    __nv_bfloat16 l2 = __float2bfloat16(a.z - __bfloat162float(h2));
    __nv_bfloat16 l3 = __float2bfloat16(a.w - __bfloat162float(h3));
    hv = make_uint2(((uint32_t)__bfloat16_as_ushort(h1) << 16) | __bfloat16_as_ushort(h0),
                    ((uint32_t)__bfloat16_as_ushort(h3) << 16) | __bfloat16_as_ushort(h2));
    lv = make_uint2(((uint32_t)__bfloat16_as_ushort(l1) << 16) | __bfloat16_as_ushort(l0),
                    ((uint32_t)__bfloat16_as_ushort(l3) << 16) | __bfloat16_as_ushort(l2));
}

__device__ __forceinline__ float fexp(float s) {
    float x = s * 1.4426950408889634f;
    float j = x + 12582912.0f;
    float xi = j - 12582912.0f;
    float f = x - xi;
    int e = __float_as_int(j) - 0x4B400000;
    float p = 1.3333558e-3f;
    p = fmaf(p, f, 9.6181291e-3f);
    p = fmaf(p, f, 5.5504109e-2f);
    p = fmaf(p, f, 2.4022651e-1f);
    p = fmaf(p, f, 6.9314718e-1f);
    p = fmaf(p, f, 1.0f);
    return p * __int_as_float((e + 127) << 23);
}

// ---------------------------------------------------------------------------
__global__ __launch_bounds__(256) void presplit_kernel(
    const float* __restrict__ q, const float* __restrict__ k,
    const float* __restrict__ v, const float* __restrict__ wq,
    const float* __restrict__ wk, const float* __restrict__ wv)
{
    const int t = blockIdx.y;
    const float* src = (t == 0) ? q : (t == 1) ? k : (t == 2) ? v
                     : (t == 3) ? wq : (t == 4) ? wk : wv;
    const size_t off = (t < 3) ? (size_t)t * NQ : 3 * (size_t)NQ + (size_t)(t - 3) * NW;
    const int n4 = ((t < 3) ? NQ : NW) >> 2;
    uint2* dh = (uint2*)(g_Ih + off);
    uint2* dl = (uint2*)(g_Il + off);
    for (int i = blockIdx.x * blockDim.x + threadIdx.x; i < n4;
         i += gridDim.x * blockDim.x) {
        float4 a = ((const float4*)src)[i];
        uint2 hv, lv; split4(a, hv, lv);
        dh[i] = hv; dl[i] = lv;
    }
}

// ===========================================================================
// Projection GEMM: wmma bf16 split, cp.async double-buffered, 2 CTAs/SM,
// now with 2 b-frag pairs live -> 4 interleaved accumulator chains.
// ===========================================================================
#define BK 32
#define LDA 40
#define ARR_B (128 * LDA * 2)
#define STAGE_B (4 * ARR_B)
#define PROJ_SMEM (2 * STAGE_B)

__global__ __launch_bounds__(256, 2) void proj_wmma_kernel()
{
    extern __shared__ char smem[];
    const int z = blockIdx.z;
    const __nv_bfloat16* Ah_g = g_Ih + (size_t)z * NQ;
    const __nv_bfloat16* Al_g = g_Il + (size_t)z * NQ;
    const __nv_bfloat16* Wh_g = g_Ih + 3 * (size_t)NQ + (size_t)z * NW;
    const __nv_bfloat16* Wl_g = g_Il + 3 * (size_t)NQ + (size_t)z * NW;

    const int tid = threadIdx.x;
    const int wid = tid >> 5;
    const int warp_m = wid >> 1;
    const int warp_n = wid & 1;
    const int m0 = blockIdx.y * 128;
    const int n0 = blockIdx.x * 128;
    const uint32_t sbase = smem_u32(smem);

    const int r0 = tid >> 2, c0 = tid & 3;
    const int r1 = (tid + 256) >> 2, c1 = (tid + 256) & 3;

    auto issue = [&](int stage, int c) {
        const int k0 = c * BK;
        uint32_t sb = sbase + stage * STAGE_B;
        const __nv_bfloat16* gp[4] = {
            Ah_g + (size_t)m0 * D_ + k0, Al_g + (size_t)m0 * D_ + k0,
            Wh_g + (size_t)n0 * D_ + k0, Wl_g + (size_t)n0 * D_ + k0 };
        #pragma unroll
        for (int a = 0; a < 4; a++) {
            CP_ASYNC16(sb + a * ARR_B + r0 * 80 + c0 * 16,
                       gp[a] + (size_t)r0 * D_ + c0 * 8);
            CP_ASYNC16(sb + a * ARR_B + r1 * 80 + c1 * 16,
                       gp[a] + (size_t)r1 * D_ + c1 * 8);
        }
        CP_COMMIT();
    };

    wmma::fragment<wmma::accumulator, 16, 16, 16, float> acc[2][4];
    #pragma unroll
    for (int i = 0; i < 2; i++)
        #pragma unroll
        for (int j = 0; j < 4; j++) wmma::fill_fragment(acc[i][j], 0.0f);

    issue(0, 0);

    for (int c = 0; c < D_ / BK; c++) {
        if (c < D_ / BK - 1) { issue((c + 1) & 1, c + 1); CP_WAIT(1); }
        else                 { CP_WAIT(0); }
        __syncthreads();

        const char* st = smem + (c & 1) * STAGE_B;
        const __nv_bfloat16* Ahs = (const __nv_bfloat16*)(st);
        const __nv_bfloat16* Als = (const __nv_bfloat16*)(st + ARR_B);
        const __nv_bfloat16* Whs = (const __nv_bfloat16*)(st + 2 * ARR_B);
        const __nv_bfloat16* Wls = (const __nv_bfloat16*)(st + 3 * ARR_B);

        #pragma unroll
        for (int kk = 0; kk < BK; kk += 16) {
            wmma::fragment<wmma::matrix_a, 16, 16, 16, __nv_bfloat16, wmma::row_major> aH[2], aL[2];
            #pragma unroll
            for (int i = 0; i < 2; i++) {
                wmma::load_matrix_sync(aH[i], &Ahs[(warp_m * 32 + i * 16) * LDA + kk], LDA);
                wmma::load_matrix_sync(aL[i], &Als[(warp_m * 32 + i * 16) * LDA + kk], LDA);
            }
            // Two (bH,bL) pairs live -> 4 interleaved acc chains.
            #pragma unroll
            for (int jp = 0; jp < 2; jp++) {
                wmma::fragment<wmma::matrix_b, 16, 16, 16, __nv_bfloat16, wmma::col_major> bH0, bL0, bH1, bL1;
                wmma::load_matrix_sync(bH0, &Whs[(warp_n * 64 + (2*jp+0) * 16) * LDA + kk], LDA);
                wmma::load_matrix_sync(bL0, &Wls[(warp_n * 64 + (2*jp+0) * 16) * LDA + kk], LDA);
                wmma::load_matrix_sync(bH1, &Whs[(warp_n * 64 + (2*jp+1) * 16) * LDA + kk], LDA);
                wmma::load_matrix_sync(bL1, &Wls[(warp_n * 64 + (2*jp+1) * 16) * LDA + kk], LDA);
                #pragma unroll
                for (int i = 0; i < 2; i++) {
                    wmma::mma_sync(acc[i][2*jp+0], aH[i], bH0, acc[i][2*jp+0]);
                    wmma::mma_sync(acc[i][2*jp+1], aH[i], bH1, acc[i][2*jp+1]);
                    wmma::mma_sync(acc[i][2*jp+0], aH[i], bL0, acc[i][2*jp+0]);
                    wmma::mma_sync(acc[i][2*jp+1], aH[i], bL1, acc[i][2*jp+1]);
                    wmma::mma_sync(acc[i][2*jp+0], aL[i], bH0, acc[i][2*jp+0]);
                    wmma::mma_sync(acc[i][2*jp+1], aL[i], bH1, acc[i][2*jp+1]);
                }
            }
        }
        __syncthreads();
    }

    float* st = (float*)smem;
    #pragma unroll
    for (int i = 0; i < 2; i++)
        #pragma unroll
        for (int j = 0; j < 4; j++)
            wmma::store_matrix_sync(&st[(warp_m * 32 + i * 16) * 132 + warp_n * 64 + j * 16],
                                    acc[i][j], 132, wmma::mem_row_major);
    __syncthreads();

    __nv_bfloat16* outh = (z == 0) ? g_Qh : (z == 1) ? g_Kh : g_Vh;
    __nv_bfloat16* outl = (z == 0) ? g_Ql : (z == 1) ? g_Kl : g_Vl;
    const int b = m0 >> 11;
    #pragma unroll
    for (int it = 0; it < 16; it++) {
        int idx = it * 256 + tid;
        int r = idx >> 5, c4 = idx & 31;
        float4 val = *reinterpret_cast<const float4*>(&st[r * 132 + c4 * 4]);
        uint2 hv, lv; split4(val, hv, lv);
        int m = m0 + r;
        int s = m & (S_ - 1);
        int n = n0 + c4 * 4;
        int h = n >> 6, d0 = n & 63;
        size_t o = ((size_t)(b * H_ + h) * S_ + s) * HD_ + d0;
        *reinterpret_cast<uint2*>(outh + o) = hv;
        *reinterpret_cast<uint2*>(outl + o) = lv;
        if (z == 2) *reinterpret_cast<float4*>(g_V + o) = val;
    }
}

// ---------------------------------------------------------------------------
__global__ __launch_bounds__(1024) void suffix_kernel()
{
    __shared__ float part[16][64];
    const int bh = blockIdx.x;
    const int d = threadIdx.x & 63;
    const int g = threadIdx.x >> 6;
    const float* Vp = g_V + (size_t)bh * S_ * HD_ + d;
    float* Sp = g_S + (size_t)bh * S_ * HD_ + d;
    const int row0 = g * 128;

    float acc = 0.f;
    #pragma unroll 8
    for (int s = 0; s < 128; s++) acc += Vp[(size_t)(row0 + s) * HD_];
    part[g][d] = acc;
    __syncthreads();

    float base = 0.f;
    #pragma unroll
    for (int gg = g + 1; gg < 16; gg++) base += part[gg][d];
    for (int s = 127; s >= 0; s--) {
        Sp[(size_t)(row0 + s) * HD_] = base;
        base += Vp[(size_t)(row0 + s) * HD_];
    }
}

// ===========================================================================
// Register-resident flash attention (R12/13 WIN) + mask fast-path +
// interleaved MMA chains (per-acc order preserved -> bit-identical).
// ===========================================================================
#define ROWB 144
#define KTILE_B (64 * ROWB)
#define Q_B (128 * ROWB)
#define STG_B (4 * KTILE_B)
#define ATT_SMEM (2 * Q_B + 2 * STG_B)

__global__ __launch_bounds__(256, 2) void attn_mma_kernel(float* __restrict__ out)
{
    extern __shared__ char smem_raw[];
    const uint32_t sb = smem_u32(smem_raw);
    const uint32_t sQh = sb, sQl = sb + Q_B;
    const uint32_t sStage0 = sb + 2 * Q_B;

    const int tid = threadIdx.x;
    const int wid = tid >> 5;
    const int lane = tid & 31;
    const int pair = blockIdx.x;
    const int bh = blockIdx.y;
    const size_t bho = (size_t)bh * S_ * HD_;
    const int m0 = wid * 16;
    const int NT = S_ / 128;

    const int rA = ((lane >> 3) & 1) * 8 + (lane & 7);
    const int cA = ((lane >> 4) & 1) * 8;
    const int rK = ((lane >> 4) & 1) * 8 + (lane & 7);
    const int cK = ((lane >> 3) & 1) * 8;

    auto issue_kv = [&](int stage, int kt) {
        uint32_t st = sStage0 + stage * STG_B;
        const size_t to = bho + (size_t)kt * 64 * HD_;
        const __nv_bfloat16* gp[4] = { g_Kh + to, g_Kl + to, g_Vh + to, g_Vl + to };
        #pragma unroll
        for (int i = 0; i < 8; i++) {
            int id = i * 256 + tid;
            int arr = id >> 9;
            int rem = id & 511;
            int r = rem >> 3, c = rem & 7;
            CP_ASYNC16(st + arr * KTILE_B + r * ROWB + c * 16, gp[arr] + (size_t)r * 64 + c * 8);
        }
        CP_COMMIT();
    };

    const int b = bh / H_, h = bh % H_;
    const float* Sufp = g_S + bho;

    #pragma unroll 1
    for (int seg = 0; seg < 2; seg++) {
        const int qt = seg ? pair : (NT - 1 - pair);
        const int qbase = qt * 128;

        __syncthreads();

        #pragma unroll
        for (int i = 0; i < 8; i++) {
            int id = i * 256 + tid;
            int arr = id >> 10;
            int rem = id & 1023;
            int r = rem >> 3, c = rem & 7;
            const __nv_bfloat16* g = (arr ? g_Ql : g_Qh) + bho + (size_t)(qbase + r) * 64 + c * 8;
            CP_ASYNC16((arr ? sQl : sQh) + r * ROWB + c * 16, g);
        }
        CP_COMMIT();
        issue_kv(0, 0);

        CP_WAIT(1);
        __syncthreads();

        uint32_t qh[4][4];
        #pragma unroll
        for (int kc = 0; kc < 4; kc++)
            LDSM_X4(qh[kc][0], qh[kc][1], qh[kc][2], qh[kc][3],
                    sQh + (m0 + rA) * ROWB + (kc * 16 + cA) * 2);

        float oc[8][4];
        #pragma unroll
        for (int i = 0; i < 8; i++)
            #pragma unroll
            for (int j = 0; j < 4; j++) oc[i][j] = 0.f;
        float z0 = 0.f, z1 = 0.f;

        const int rowg0 = qbase + m0 + (lane >> 2);
        const int rowg1 = rowg0 + 8;
        const int ktmax = 2 * qt + 1;

        for (int kt = 0; kt <= ktmax; kt++) {
            CP_WAIT(0);
            __syncthreads();
            if (kt < ktmax) issue_kv((kt + 1) & 1, kt + 1);

            const uint32_t st = sStage0 + (kt & 1) * STG_B;
            const uint32_t stKh = st, stKl = st + KTILE_B;
            const uint32_t stVh = st + 2 * KTILE_B, stVl = st + 3 * KTILE_B;

            uint32_t pah[4][4], pal[4][4];
            // Tile fully unmasked iff max col (kt*64+63) <= min row (qbase+m0).
            const bool nomask = (kt * 64 + 63 <= qbase + m0);

            #pragma unroll
            for (int hhf = 0; hhf < 2; hhf++) {
                float sc[4][4];
                #pragma unroll
                for (int i = 0; i < 4; i++)
                    #pragma unroll
                    for (int j = 0; j < 4; j++) sc[i][j] = 0.f;

                #pragma unroll
                for (int kc = 0; kc < 4; kc++) {
                    uint32_t ql_[4];
                    LDSM_X4(ql_[0], ql_[1], ql_[2], ql_[3],
                            sQl + (m0 + rA) * ROWB + (kc * 16 + cA) * 2);
                    // Two n8-groups: interleave the two acc chains (per-acc
                    // order HH->HL->LH preserved -> bit-identical).
                    uint32_t b00, b01, b02, b03, b10, b11, b12, b13;
                    int ng0 = 2 * hhf;
                    LDSM_X4(b00, b01, b02, b03, stKh + (ng0 * 16 + rK) * ROWB + (kc * 16 + cK) * 2);
                    LDSM_X4(b10, b11, b12, b13, stKl + (ng0 * 16 + rK) * ROWB + (kc * 16 + cK) * 2);
                    MMA16816(sc[0], qh[kc], b00, b01);
                    MMA16816(sc[1], qh[kc], b02, b03);
                    MMA16816(sc[0], qh[kc], b10, b11);
                    MMA16816(sc[1], qh[kc], b12, b13);
                    MMA16816(sc[0], ql_,    b00, b01);
                    MMA16816(sc[1], ql_,    b02, b03);
                    int ng1 = 2 * hhf + 1;
                    LDSM_X4(b00, b01, b02, b03, stKh + (ng1 * 16 + rK) * ROWB + (kc * 16 + cK) * 2);
                    LDSM_X4(b10, b11, b12, b13, stKl + (ng1 * 16 + rK) * ROWB + (kc * 16 + cK) * 2);
                    MMA16816(sc[2], qh[kc], b00, b01);
                    MMA16816(sc[3], qh[kc], b02, b03);
                    MMA16816(sc[2], qh[kc], b10, b11);
                    MMA16816(sc[3], qh[kc], b12, b13);
                    MMA16816(sc[2], ql_,    b00, b01);
                    MMA16816(sc[3], ql_,    b02, b03);
                }
                // NOTE: sc index mapping here: sc[0],sc[1] = ng0 tiles n8 pair;
                // sc[2],sc[3] = ng1 pair. Same set as before: nt = 4*hhf + j with
                // j in {0,1} -> ng0 cols, {2,3} -> ng1 cols.

                const int colb = kt * 64 + 2 * (lane & 3);
                #pragma unroll
                for (int j = 0; j < 4; j++) {
                    int nt = 4 * hhf + j;
                    int col0 = colb + nt * 8;
                    float p00, p01, p10, p11;
                    if (nomask) {
                        p00 = fexp(sc[j][0] * 0.125f);
                        p01 = fexp(sc[j][1] * 0.125f);
                        p10 = fexp(sc[j][2] * 0.125f);
                        p11 = fexp(sc[j][3] * 0.125f);
                    } else {
                        p00 = (col0     <= rowg0) ? fexp(sc[j][0] * 0.125f) : 0.f;
                        p01 = (col0 + 1 <= rowg0) ? fexp(sc[j][1] * 0.125f) : 0.f;
                        p10 = (col0     <= rowg1) ? fexp(sc[j][2] * 0.125f) : 0.f;
                        p11 = (col0 + 1 <= rowg1) ? fexp(sc[j][3] * 0.125f) : 0.f;
                    }
                    z0 += p00 + p01;
                    z1 += p10 + p11;
                    uint32_t hiw0 = pack_bf16x2(p00, p01);
                    uint32_t hiw1 = pack_bf16x2(p10, p11);
                    float f00 = __uint_as_float(hiw0 << 16);
                    float f01 = __uint_as_float(hiw0 & 0xFFFF0000u);
                    float f10 = __uint_as_float(hiw1 << 16);
                    float f11 = __uint_as_float(hiw1 & 0xFFFF0000u);
                    int kcp = 2 * hhf + (j >> 1), hf = (j & 1) * 2;
                    pah[kcp][hf + 0] = hiw0;
                    pah[kcp][hf + 1] = hiw1;
                    pal[kcp][hf + 0] = pack_bf16x2(p00 - f00, p01 - f01);
                    pal[kcp][hf + 1] = pack_bf16x2(p10 - f10, p11 - f11);
                }
            }

            // ---- O += P.V, interleaved across the dg pair ----
            #pragma unroll
            for (int kc = 0; kc < 4; kc++) {
                #pragma unroll
                for (int dp = 0; dp < 2; dp++) {
                    uint32_t a00, a01, a02, a03, a10, a11, a12, a13;
                    uint32_t c00, c01, c02, c03, c10, c11, c12, c13;
                    int dg0 = 2 * dp, dg1 = 2 * dp + 1;
                    LDSM_X4_T(a00, a01, a02, a03, stVh + (kc * 16 + rA) * ROWB + (dg0 * 16 + cA) * 2);
                    LDSM_X4_T(a10, a11, a12, a13, stVl + (kc * 16 + rA) * ROWB + (dg0 * 16 + cA) * 2);
                    LDSM_X4_T(c00, c01, c02, c03, stVh + (kc * 16 + rA) * ROWB + (dg1 * 16 + cA) * 2);
                    LDSM_X4_T(c10, c11, c12, c13, stVl + (kc * 16 + rA) * ROWB + (dg1 * 16 + cA) * 2);
                    MMA16816(oc[2 * dg0],     pah[kc], a00, a01);
                    MMA16816(oc[2 * dg1],     pah[kc], c00, c01);
                    MMA16816(oc[2 * dg0 + 1], pah[kc], a02, a03);
                    MMA16816(oc[2 * dg1 + 1], pah[kc], c02, c03);
                    MMA16816(oc[2 * dg0],     pah[kc], a10, a11);
                    MMA16816(oc[2 * dg1],     pah[kc], c10, c11);
                    MMA16816(oc[2 * dg0 + 1], pah[kc], a12, a13);
                    MMA16816(oc[2 * dg1 + 1], pah[kc], c12, c13);
                    MMA16816(oc[2 * dg0],     pal[kc], a00, a01);
                    MMA16816(oc[2 * dg1],     pal[kc], c00, c01);
                    MMA16816(oc[2 * dg0 + 1], pal[kc], a02, a03);
                    MMA16816(oc[2 * dg1 + 1], pal[kc], c02, c03);
                }
            }
        }

        z0 += __shfl_xor_sync(0xffffffffu, z0, 1);
        z0 += __shfl_xor_sync(0xffffffffu, z0, 2);
        z1 += __shfl_xor_sync(0xffffffffu, z1, 1);
        z1 += __shfl_xor_sync(0xffffffffu, z1, 2);
        float inv0 = 1.f / (z0 + (float)(S_ - 1 - rowg0));
        float inv1 = 1.f / (z1 + (float)(S_ - 1 - rowg1));

        #pragma unroll
        for (int nt = 0; nt < 8; nt++) {
            int d = nt * 8 + 2 * (lane & 3);
            float2 s0 = *reinterpret_cast<const float2*>(&Sufp[(size_t)rowg0 * 64 + d]);
            float2 s1 = *reinterpret_cast<const float2*>(&Sufp[(size_t)rowg1 * 64 + d]);
            float2 o0 = make_float2((oc[nt][0] + s0.x) * inv0, (oc[nt][1] + s0.y) * inv0);
            float2 o1 = make_float2((oc[nt][2] + s1.x) * inv1, (oc[nt][3] + s1.y) * inv1);
            *reinterpret_cast<float2*>(&out[((size_t)(b * S_ + rowg0)) * D_ + h * 64 + d]) = o0;
            *reinterpret_cast<float2*>(&out[((size_t)(b * S_ + rowg1)) * D_ + h * 64 + d]) = o1;
        }
    }
}

// ---------------------------------------------------------------------------
extern "C" void kernel_launch(void* const* d_in, const int* in_sizes, int n_in,
                              void* d_out, int out_size)
{
    const float* q  = (const float*)d_in[0];
    const float* k  = (const float*)d_in[1];
    const float* v  = (const float*)d_in[2];
    const float* wq = (const float*)d_in[3];
    const float* wk = (const float*)d_in[4];
    const float* wv = (const float*)d_in[5];
    float* out = (float*)d_out;

    presplit_kernel<<<dim3(256, 6), 256>>>(q, k, v, wq, wk, wv);

    cudaFuncSetAttribute(proj_wmma_kernel,
                         cudaFuncAttributeMaxDynamicSharedMemorySize, PROJ_SMEM);
    proj_wmma_kernel<<<dim3(D_ / 128, (B_ * S_) / 128, 3), 256, PROJ_SMEM>>>();

    suffix_kernel<<<B_ * H_, 1024>>>();

    cudaFuncSetAttribute(attn_mma_kernel,
                         cudaFuncAttributeMaxDynamicSharedMemorySize, ATT_SMEM);
    attn_mma_kernel<<<dim3(S_ / 256, B_ * H_), 256, ATT_SMEM>>>(out);
}

// round 15
// speedup vs baseline: 2.3462x; 1.0176x over previous
#include <cuda_runtime.h>
#include <cuda_bf16.h>
#include <mma.h>
#include <cstdint>
#include <math.h>

using namespace nvcuda;

#define B_  2
#define S_  2048
#define D_  1024
#define H_  16
#define HD_ 64
#define NQ (B_*S_*D_)
#define NW (D_*D_)
#define NP (B_*H_*S_*HD_)

__device__ __nv_bfloat16 g_Ih[3*NQ + 3*NW];
__device__ __nv_bfloat16 g_Il[3*NQ + 3*NW];
__device__ __nv_bfloat16 g_Qh[NP], g_Ql[NP];
__device__ __nv_bfloat16 g_Kh[NP], g_Kl[NP];
__device__ __nv_bfloat16 g_Vh[NP], g_Vl[NP];
__device__ float g_TVp[32*4*64];   // per-(bh, seg-of-512) V column partial sums

// ---------------------------------------------------------------------------
__device__ __forceinline__ uint32_t smem_u32(const void* p) {
    uint32_t a;
    asm("{ .reg .u64 t; cvta.to.shared.u64 t, %1; cvt.u32.u64 %0, t; }"
        : "=r"(a) : "l"(p));
    return a;
}
#define CP_ASYNC16(dst, src) \
    asm volatile("cp.async.cg.shared.global [%0], [%1], 16;" :: "r"(dst), "l"(src))
#define CP_COMMIT() asm volatile("cp.async.commit_group;")
#define CP_WAIT(n)  asm volatile("cp.async.wait_group %0;" :: "n"(n))

#define LDSM_X4(r0,r1,r2,r3, addr) \
    asm volatile("ldmatrix.sync.aligned.m8n8.x4.shared.b16 {%0,%1,%2,%3}, [%4];" \
        : "=r"(r0),"=r"(r1),"=r"(r2),"=r"(r3) : "r"(addr))
#define LDSM_X4_T(r0,r1,r2,r3, addr) \
    asm volatile("ldmatrix.sync.aligned.m8n8.x4.trans.shared.b16 {%0,%1,%2,%3}, [%4];" \
        : "=r"(r0),"=r"(r1),"=r"(r2),"=r"(r3) : "r"(addr))
#define MMA16816(c, a, b0, b1) \
    asm volatile("mma.sync.aligned.m16n8k16.row.col.f32.bf16.bf16.f32 " \
        "{%0,%1,%2,%3},{%4,%5,%6,%7},{%8,%9},{%0,%1,%2,%3};" \
        : "+f"((c)[0]),"+f"((c)[1]),"+f"((c)[2]),"+f"((c)[3]) \
        : "r"((a)[0]),"r"((a)[1]),"r"((a)[2]),"r"((a)[3]),"r"(b0),"r"(b1))

__device__ __forceinline__ uint32_t pack_bf16x2(float lo, float hi) {
    __nv_bfloat162 t = __floats2bfloat162_rn(lo, hi);
    return *reinterpret_cast<uint32_t*>(&t);
}

__device__ __forceinline__ void split4(float4 a, uint2& hv, uint2& lv) {
    __nv_bfloat16 h0 = __float2bfloat16(a.x);
    __nv_bfloat16 h1 = __float2bfloat16(a.y);
    __nv_bfloat16 h2 = __float2bfloat16(a.z);
    __nv_bfloat16 h3 = __float2bfloat16(a.w);
    __nv_bfloat16 l0 = __float2bfloat16(a.x - __bfloat162float(h0));
    __nv_bfloat16 l1 = __float2bfloat16(a.y - __bfloat162float(h1));
    __nv_bfloat16 l2 = __float2bfloat16(a.z - __bfloat162float(h2));
    __nv_bfloat16 l3 = __float2bfloat16(a.w - __bfloat162float(h3));
    hv = make_uint2(((uint32_t)__bfloat16_as_ushort(h1) << 16) | __bfloat16_as_ushort(h0),
                    ((uint32_t)__bfloat16_as_ushort(h3) << 16) | __bfloat16_as_ushort(h2));
    lv = make_uint2(((uint32_t)__bfloat16_as_ushort(l1) << 16) | __bfloat16_as_ushort(l0),
                    ((uint32_t)__bfloat16_as_ushort(l3) << 16) | __bfloat16_as_ushort(l2));
}

__device__ __forceinline__ float fexp(float s) {
    float x = s * 1.4426950408889634f;
    float j = x + 12582912.0f;
    float xi = j - 12582912.0f;
    float f = x - xi;
    int e = __float_as_int(j) - 0x4B400000;
    float p = 1.3333558e-3f;
    p = fmaf(p, f, 9.6181291e-3f);
    p = fmaf(p, f, 5.5504109e-2f);
    p = fmaf(p, f, 2.4022651e-1f);
    p = fmaf(p, f, 6.9314718e-1f);
    p = fmaf(p, f, 1.0f);
    return p * __int_as_float((e + 127) << 23);
}

// ---------------------------------------------------------------------------
__global__ __launch_bounds__(256) void presplit_kernel(
    const float* __restrict__ q, const float* __restrict__ k,
    const float* __restrict__ v, const float* __restrict__ wq,
    const float* __restrict__ wk, const float* __restrict__ wv)
{
    const int t = blockIdx.y;
    const float* src = (t == 0) ? q : (t == 1) ? k : (t == 2) ? v
                     : (t == 3) ? wq : (t == 4) ? wk : wv;
    const size_t off = (t < 3) ? (size_t)t * NQ : 3 * (size_t)NQ + (size_t)(t - 3) * NW;
    const int n4 = ((t < 3) ? NQ : NW) >> 2;
    uint2* dh = (uint2*)(g_Ih + off);
    uint2* dl = (uint2*)(g_Il + off);
    for (int i = blockIdx.x * blockDim.x + threadIdx.x; i < n4;
         i += gridDim.x * blockDim.x) {
        float4 a = ((const float4*)src)[i];
        uint2 hv, lv; split4(a, hv, lv);
        dh[i] = hv; dl[i] = lv;
    }
}

// ===========================================================================
// Projection GEMM (R14): wmma bf16 split, cp.async double-buffered, 2 CTAs/SM,
// 2 b-frag pairs live -> 4 interleaved accumulator chains.
// ===========================================================================
#define BK 32
#define LDA 40
#define ARR_B (128 * LDA * 2)
#define STAGE_B (4 * ARR_B)
#define PROJ_SMEM (2 * STAGE_B)

__global__ __launch_bounds__(256, 2) void proj_wmma_kernel()
{
    extern __shared__ char smem[];
    const int z = blockIdx.z;
    const __nv_bfloat16* Ah_g = g_Ih + (size_t)z * NQ;
    const __nv_bfloat16* Al_g = g_Il + (size_t)z * NQ;
    const __nv_bfloat16* Wh_g = g_Ih + 3 * (size_t)NQ + (size_t)z * NW;
    const __nv_bfloat16* Wl_g = g_Il + 3 * (size_t)NQ + (size_t)z * NW;

    const int tid = threadIdx.x;
    const int wid = tid >> 5;
    const int warp_m = wid >> 1;
    const int warp_n = wid & 1;
    const int m0 = blockIdx.y * 128;
    const int n0 = blockIdx.x * 128;
    const uint32_t sbase = smem_u32(smem);

    const int r0 = tid >> 2, c0 = tid & 3;
    const int r1 = (tid + 256) >> 2, c1 = (tid + 256) & 3;

    auto issue = [&](int stage, int c) {
        const int k0 = c * BK;
        uint32_t sb = sbase + stage * STAGE_B;
        const __nv_bfloat16* gp[4] = {
            Ah_g + (size_t)m0 * D_ + k0, Al_g + (size_t)m0 * D_ + k0,
            Wh_g + (size_t)n0 * D_ + k0, Wl_g + (size_t)n0 * D_ + k0 };
        #pragma unroll
        for (int a = 0; a < 4; a++) {
            CP_ASYNC16(sb + a * ARR_B + r0 * 80 + c0 * 16,
                       gp[a] + (size_t)r0 * D_ + c0 * 8);
            CP_ASYNC16(sb + a * ARR_B + r1 * 80 + c1 * 16,
                       gp[a] + (size_t)r1 * D_ + c1 * 8);
        }
        CP_COMMIT();
    };

    wmma::fragment<wmma::accumulator, 16, 16, 16, float> acc[2][4];
    #pragma unroll
    for (int i = 0; i < 2; i++)
        #pragma unroll
        for (int j = 0; j < 4; j++) wmma::fill_fragment(acc[i][j], 0.0f);

    issue(0, 0);

    for (int c = 0; c < D_ / BK; c++) {
        if (c < D_ / BK - 1) { issue((c + 1) & 1, c + 1); CP_WAIT(1); }
        else                 { CP_WAIT(0); }
        __syncthreads();

        const char* st = smem + (c & 1) * STAGE_B;
        const __nv_bfloat16* Ahs = (const __nv_bfloat16*)(st);
        const __nv_bfloat16* Als = (const __nv_bfloat16*)(st + ARR_B);
        const __nv_bfloat16* Whs = (const __nv_bfloat16*)(st + 2 * ARR_B);
        const __nv_bfloat16* Wls = (const __nv_bfloat16*)(st + 3 * ARR_B);

        #pragma unroll
        for (int kk = 0; kk < BK; kk += 16) {
            wmma::fragment<wmma::matrix_a, 16, 16, 16, __nv_bfloat16, wmma::row_major> aH[2], aL[2];
            #pragma unroll
            for (int i = 0; i < 2; i++) {
                wmma::load_matrix_sync(aH[i], &Ahs[(warp_m * 32 + i * 16) * LDA + kk], LDA);
                wmma::load_matrix_sync(aL[i], &Als[(warp_m * 32 + i * 16) * LDA + kk], LDA);
            }
            #pragma unroll
            for (int jp = 0; jp < 2; jp++) {
                wmma::fragment<wmma::matrix_b, 16, 16, 16, __nv_bfloat16, wmma::col_major> bH0, bL0, bH1, bL1;
                wmma::load_matrix_sync(bH0, &Whs[(warp_n * 64 + (2*jp+0) * 16) * LDA + kk], LDA);
                wmma::load_matrix_sync(bL0, &Wls[(warp_n * 64 + (2*jp+0) * 16) * LDA + kk], LDA);
                wmma::load_matrix_sync(bH1, &Whs[(warp_n * 64 + (2*jp+1) * 16) * LDA + kk], LDA);
                wmma::load_matrix_sync(bL1, &Wls[(warp_n * 64 + (2*jp+1) * 16) * LDA + kk], LDA);
                #pragma unroll
                for (int i = 0; i < 2; i++) {
                    wmma::mma_sync(acc[i][2*jp+0], aH[i], bH0, acc[i][2*jp+0]);
                    wmma::mma_sync(acc[i][2*jp+1], aH[i], bH1, acc[i][2*jp+1]);
                    wmma::mma_sync(acc[i][2*jp+0], aH[i], bL0, acc[i][2*jp+0]);
                    wmma::mma_sync(acc[i][2*jp+1], aH[i], bL1, acc[i][2*jp+1]);
                    wmma::mma_sync(acc[i][2*jp+0], aL[i], bH0, acc[i][2*jp+0]);
                    wmma::mma_sync(acc[i][2*jp+1], aL[i], bH1, acc[i][2*jp+1]);
                }
            }
        }
        __syncthreads();
    }

    float* st = (float*)smem;
    #pragma unroll
    for (int i = 0; i < 2; i++)
        #pragma unroll
        for (int j = 0; j < 4; j++)
            wmma::store_matrix_sync(&st[(warp_m * 32 + i * 16) * 132 + warp_n * 64 + j * 16],
                                    acc[i][j], 132, wmma::mem_row_major);
    __syncthreads();

    __nv_bfloat16* outh = (z == 0) ? g_Qh : (z == 1) ? g_Kh : g_Vh;
    __nv_bfloat16* outl = (z == 0) ? g_Ql : (z == 1) ? g_Kl : g_Vl;
    const int b = m0 >> 11;
    #pragma unroll
    for (int it = 0; it < 16; it++) {
        int idx = it * 256 + tid;
        int r = idx >> 5, c4 = idx & 31;
        float4 val = *reinterpret_cast<const float4*>(&st[r * 132 + c4 * 4]);
        uint2 hv, lv; split4(val, hv, lv);
        int m = m0 + r;
        int s = m & (S_ - 1);
        int n = n0 + c4 * 4;
        int h = n >> 6, d0 = n & 63;
        size_t o = ((size_t)(b * H_ + h) * S_ + s) * HD_ + d0;
        *reinterpret_cast<uint2*>(outh + o) = hv;
        *reinterpret_cast<uint2*>(outl + o) = lv;
    }
}

// ---------------------------------------------------------------------------
// Partial column sums of V: TVp[bh][seg][d] = sum of 512 rows (from Vh+Vl).
// ---------------------------------------------------------------------------
__global__ __launch_bounds__(64) void colsum_kernel()
{
    const int seg = blockIdx.x, bh = blockIdx.y, d = threadIdx.x;
    const size_t base = (size_t)bh * S_ * HD_ + (size_t)seg * 512 * HD_ + d;
    float acc = 0.f;
    #pragma unroll 8
    for (int s = 0; s < 512; s++) {
        acc += __bfloat162float(g_Vh[base + (size_t)s * HD_])
             + __bfloat162float(g_Vl[base + (size_t)s * HD_]);
    }
    g_TVp[(bh * 4 + seg) * 64 + d] = acc;
}

// ===========================================================================
// Register-resident flash attention (R14 WIN) with the p' = p-1 identity:
//   O = (P'.V + TotalV) / Z,  Z = sum(p') + S   (masked entries p' = 0).
// No suffix sums needed; TotalV read from 4 partials into smem once.
// ===========================================================================
#define ROWB 144
#define KTILE_B (64 * ROWB)
#define Q_B (128 * ROWB)
#define STG_B (4 * KTILE_B)
#define ATT_SMEM (2 * Q_B + 2 * STG_B)

__global__ __launch_bounds__(256, 2) void attn_mma_kernel(float* __restrict__ out)
{
    extern __shared__ char smem_raw[];
    __shared__ float sTV[64];
    const uint32_t sb = smem_u32(smem_raw);
    const uint32_t sQh = sb, sQl = sb + Q_B;
    const uint32_t sStage0 = sb + 2 * Q_B;

    const int tid = threadIdx.x;
    const int wid = tid >> 5;
    const int lane = tid & 31;
    const int pair = blockIdx.x;
    const int bh = blockIdx.y;
    const size_t bho = (size_t)bh * S_ * HD_;
    const int m0 = wid * 16;
    const int NT = S_ / 128;

    const int rA = ((lane >> 3) & 1) * 8 + (lane & 7);
    const int cA = ((lane >> 4) & 1) * 8;
    const int rK = ((lane >> 4) & 1) * 8 + (lane & 7);
    const int cK = ((lane >> 3) & 1) * 8;

    if (tid < 64) {
        sTV[tid] = g_TVp[(bh * 4 + 0) * 64 + tid] + g_TVp[(bh * 4 + 1) * 64 + tid]
                 + g_TVp[(bh * 4 + 2) * 64 + tid] + g_TVp[(bh * 4 + 3) * 64 + tid];
    }

    auto issue_kv = [&](int stage, int kt) {
        uint32_t st = sStage0 + stage * STG_B;
        const size_t to = bho + (size_t)kt * 64 * HD_;
        const __nv_bfloat16* gp[4] = { g_Kh + to, g_Kl + to, g_Vh + to, g_Vl + to };
        #pragma unroll
        for (int i = 0; i < 8; i++) {
            int id = i * 256 + tid;
            int arr = id >> 9;
            int rem = id & 511;
            int r = rem >> 3, c = rem & 7;
            CP_ASYNC16(st + arr * KTILE_B + r * ROWB + c * 16, gp[arr] + (size_t)r * 64 + c * 8);
        }
        CP_COMMIT();
    };

    const int b = bh / H_, h = bh % H_;

    #pragma unroll 1
    for (int seg = 0; seg < 2; seg++) {
        const int qt = seg ? pair : (NT - 1 - pair);
        const int qbase = qt * 128;

        __syncthreads();

        #pragma unroll
        for (int i = 0; i < 8; i++) {
            int id = i * 256 + tid;
            int arr = id >> 10;
            int rem = id & 1023;
            int r = rem >> 3, c = rem & 7;
            const __nv_bfloat16* g = (arr ? g_Ql : g_Qh) + bho + (size_t)(qbase + r) * 64 + c * 8;
            CP_ASYNC16((arr ? sQl : sQh) + r * ROWB + c * 16, g);
        }
        CP_COMMIT();
        issue_kv(0, 0);

        CP_WAIT(1);
        __syncthreads();

        uint32_t qh[4][4];
        #pragma unroll
        for (int kc = 0; kc < 4; kc++)
            LDSM_X4(qh[kc][0], qh[kc][1], qh[kc][2], qh[kc][3],
                    sQh + (m0 + rA) * ROWB + (kc * 16 + cA) * 2);

        float oc[8][4];
        #pragma unroll
        for (int i = 0; i < 8; i++)
            #pragma unroll
            for (int j = 0; j < 4; j++) oc[i][j] = 0.f;
        float z0 = 0.f, z1 = 0.f;

        const int rowg0 = qbase + m0 + (lane >> 2);
        const int rowg1 = rowg0 + 8;
        const int ktmax = 2 * qt + 1;

        for (int kt = 0; kt <= ktmax; kt++) {
            CP_WAIT(0);
            __syncthreads();
            if (kt < ktmax) issue_kv((kt + 1) & 1, kt + 1);

            const uint32_t st = sStage0 + (kt & 1) * STG_B;
            const uint32_t stKh = st, stKl = st + KTILE_B;
            const uint32_t stVh = st + 2 * KTILE_B, stVl = st + 3 * KTILE_B;

            uint32_t pah[4][4], pal[4][4];
            const bool nomask = (kt * 64 + 63 <= qbase + m0);

            #pragma unroll
            for (int hhf = 0; hhf < 2; hhf++) {
                float sc[4][4];
                #pragma unroll
                for (int i = 0; i < 4; i++)
                    #pragma unroll
                    for (int j = 0; j < 4; j++) sc[i][j] = 0.f;

                #pragma unroll
                for (int kc = 0; kc < 4; kc++) {
                    uint32_t ql_[4];
                    LDSM_X4(ql_[0], ql_[1], ql_[2], ql_[3],
                            sQl + (m0 + rA) * ROWB + (kc * 16 + cA) * 2);
                    uint32_t b00, b01, b02, b03, b10, b11, b12, b13;
                    int ng0 = 2 * hhf;
                    LDSM_X4(b00, b01, b02, b03, stKh + (ng0 * 16 + rK) * ROWB + (kc * 16 + cK) * 2);
                    LDSM_X4(b10, b11, b12, b13, stKl + (ng0 * 16 + rK) * ROWB + (kc * 16 + cK) * 2);
                    MMA16816(sc[0], qh[kc], b00, b01);
                    MMA16816(sc[1], qh[kc], b02, b03);
                    MMA16816(sc[0], qh[kc], b10, b11);
                    MMA16816(sc[1], qh[kc], b12, b13);
                    MMA16816(sc[0], ql_,    b00, b01);
                    MMA16816(sc[1], ql_,    b02, b03);
                    int ng1 = 2 * hhf + 1;
                    LDSM_X4(b00, b01, b02, b03, stKh + (ng1 * 16 + rK) * ROWB + (kc * 16 + cK) * 2);
                    LDSM_X4(b10, b11, b12, b13, stKl + (ng1 * 16 + rK) * ROWB + (kc * 16 + cK) * 2);
                    MMA16816(sc[2], qh[kc], b00, b01);
                    MMA16816(sc[3], qh[kc], b02, b03);
                    MMA16816(sc[2], qh[kc], b10, b11);
                    MMA16816(sc[3], qh[kc], b12, b13);
                    MMA16816(sc[2], ql_,    b00, b01);
                    MMA16816(sc[3], ql_,    b02, b03);
                }

                const int colb = kt * 64 + 2 * (lane & 3);
                #pragma unroll
                for (int j = 0; j < 4; j++) {
                    int nt = 4 * hhf + j;
                    int col0 = colb + nt * 8;
                    float p00, p01, p10, p11;
                    if (nomask) {
                        p00 = fexp(sc[j][0] * 0.125f) - 1.0f;
                        p01 = fexp(sc[j][1] * 0.125f) - 1.0f;
                        p10 = fexp(sc[j][2] * 0.125f) - 1.0f;
                        p11 = fexp(sc[j][3] * 0.125f) - 1.0f;
                    } else {
                        p00 = (col0     <= rowg0) ? fexp(sc[j][0] * 0.125f) - 1.0f : 0.f;
                        p01 = (col0 + 1 <= rowg0) ? fexp(sc[j][1] * 0.125f) - 1.0f : 0.f;
                        p10 = (col0     <= rowg1) ? fexp(sc[j][2] * 0.125f) - 1.0f : 0.f;
                        p11 = (col0 + 1 <= rowg1) ? fexp(sc[j][3] * 0.125f) - 1.0f : 0.f;
                    }
                    z0 += p00 + p01;
                    z1 += p10 + p11;
                    uint32_t hiw0 = pack_bf16x2(p00, p01);
                    uint32_t hiw1 = pack_bf16x2(p10, p11);
                    float f00 = __uint_as_float(hiw0 << 16);
                    float f01 = __uint_as_float(hiw0 & 0xFFFF0000u);
                    float f10 = __uint_as_float(hiw1 << 16);
                    float f11 = __uint_as_float(hiw1 & 0xFFFF0000u);
                    int kcp = 2 * hhf + (j >> 1), hf = (j & 1) * 2;
                    pah[kcp][hf + 0] = hiw0;
                    pah[kcp][hf + 1] = hiw1;
                    pal[kcp][hf + 0] = pack_bf16x2(p00 - f00, p01 - f01);
                    pal[kcp][hf + 1] = pack_bf16x2(p10 - f10, p11 - f11);
                }
            }

            #pragma unroll
            for (int kc = 0; kc < 4; kc++) {
                #pragma unroll
                for (int dp = 0; dp < 2; dp++) {
                    uint32_t a00, a01, a02, a03, a10, a11, a12, a13;
                    uint32_t c00, c01, c02, c03, c10, c11, c12, c13;
                    int dg0 = 2 * dp, dg1 = 2 * dp + 1;
                    LDSM_X4_T(a00, a01, a02, a03, stVh + (kc * 16 + rA) * ROWB + (dg0 * 16 + cA) * 2);
                    LDSM_X4_T(a10, a11, a12, a13, stVl + (kc * 16 + rA) * ROWB + (dg0 * 16 + cA) * 2);
                    LDSM_X4_T(c00, c01, c02, c03, stVh + (kc * 16 + rA) * ROWB + (dg1 * 16 + cA) * 2);
                    LDSM_X4_T(c10, c11, c12, c13, stVl + (kc * 16 + rA) * ROWB + (dg1 * 16 + cA) * 2);
                    MMA16816(oc[2 * dg0],     pah[kc], a00, a01);
                    MMA16816(oc[2 * dg1],     pah[kc], c00, c01);
                    MMA16816(oc[2 * dg0 + 1], pah[kc], a02, a03);
                    MMA16816(oc[2 * dg1 + 1], pah[kc], c02, c03);
                    MMA16816(oc[2 * dg0],     pah[kc], a10, a11);
                    MMA16816(oc[2 * dg1],     pah[kc], c10, c11);
                    MMA16816(oc[2 * dg0 + 1], pah[kc], a12, a13);
                    MMA16816(oc[2 * dg1 + 1], pah[kc], c12, c13);
                    MMA16816(oc[2 * dg0],     pal[kc], a00, a01);
                    MMA16816(oc[2 * dg1],     pal[kc], c00, c01);
                    MMA16816(oc[2 * dg0 + 1], pal[kc], a02, a03);
                    MMA16816(oc[2 * dg1 + 1], pal[kc], c02, c03);
                }
            }
        }

        z0 += __shfl_xor_sync(0xffffffffu, z0, 1);
        z0 += __shfl_xor_sync(0xffffffffu, z0, 2);
        z1 += __shfl_xor_sync(0xffffffffu, z1, 1);
        z1 += __shfl_xor_sync(0xffffffffu, z1, 2);
        float inv0 = 1.f / (z0 + (float)S_);
        float inv1 = 1.f / (z1 + (float)S_);

        #pragma unroll
        for (int nt = 0; nt < 8; nt++) {
            int d = nt * 8 + 2 * (lane & 3);
            float2 tv = *reinterpret_cast<const float2*>(&sTV[d]);
            float2 o0 = make_float2((oc[nt][0] + tv.x) * inv0, (oc[nt][1] + tv.y) * inv0);
            float2 o1 = make_float2((oc[nt][2] + tv.x) * inv1, (oc[nt][3] + tv.y) * inv1);
            *reinterpret_cast<float2*>(&out[((size_t)(b * S_ + rowg0)) * D_ + h * 64 + d]) = o0;
            *reinterpret_cast<float2*>(&out[((size_t)(b * S_ + rowg1)) * D_ + h * 64 + d]) = o1;
        }
    }
}

// ---------------------------------------------------------------------------
extern "C" void kernel_launch(void* const* d_in, const int* in_sizes, int n_in,
                              void* d_out, int out_size)
{
    const float* q  = (const float*)d_in[0];
    const float* k  = (const float*)d_in[1];
    const float* v  = (const float*)d_in[2];
    const float* wq = (const float*)d_in[3];
    const float* wk = (const float*)d_in[4];
    const float* wv = (const float*)d_in[5];
    float* out = (float*)d_out;

    presplit_kernel<<<dim3(256, 6), 256>>>(q, k, v, wq, wk, wv);

    cudaFuncSetAttribute(proj_wmma_kernel,
                         cudaFuncAttributeMaxDynamicSharedMemorySize, PROJ_SMEM);
    proj_wmma_kernel<<<dim3(D_ / 128, (B_ * S_) / 128, 3), 256, PROJ_SMEM>>>();

    colsum_kernel<<<dim3(4, B_ * H_), 64>>>();

    cudaFuncSetAttribute(attn_mma_kernel,
                         cudaFuncAttributeMaxDynamicSharedMemorySize, ATT_SMEM);
    attn_mma_kernel<<<dim3(S_ / 256, B_ * H_), 256, ATT_SMEM>>>(out);
}

// round 16
// speedup vs baseline: 2.6983x; 1.1501x over previous
#include <cuda_runtime.h>
#include <cuda_bf16.h>
#include <cuda_fp16.h>
#include <mma.h>
#include <cstdint>
#include <math.h>

using namespace nvcuda;

#define B_  2
#define S_  2048
#define D_  1024
#define H_  16
#define HD_ 64
#define NQ (B_*S_*D_)
#define NW (D_*D_)
#define NP (B_*H_*S_*HD_)

__device__ __nv_bfloat16 g_Ih[3*NQ + 3*NW];
__device__ __nv_bfloat16 g_Il[3*NQ + 3*NW];
__device__ __nv_bfloat16 g_Qh[NP], g_Ql[NP];
__device__ __nv_bfloat16 g_Kh[NP], g_Kl[NP];
__device__ __half g_Vh[NP], g_Vl[NP];       // V split in fp16 (PV uses hi only)
__device__ float g_TVp[32*16*64];           // per-(bh, seg-of-128) V col partials

// ---------------------------------------------------------------------------
__device__ __forceinline__ uint32_t smem_u32(const void* p) {
    uint32_t a;
    asm("{ .reg .u64 t; cvta.to.shared.u64 t, %1; cvt.u32.u64 %0, t; }"
        : "=r"(a) : "l"(p));
    return a;
}
#define CP_ASYNC16(dst, src) \
    asm volatile("cp.async.cg.shared.global [%0], [%1], 16;" :: "r"(dst), "l"(src))
#define CP_COMMIT() asm volatile("cp.async.commit_group;")
#define CP_WAIT(n)  asm volatile("cp.async.wait_group %0;" :: "n"(n))

#define LDSM_X4(r0,r1,r2,r3, addr) \
    asm volatile("ldmatrix.sync.aligned.m8n8.x4.shared.b16 {%0,%1,%2,%3}, [%4];" \
        : "=r"(r0),"=r"(r1),"=r"(r2),"=r"(r3) : "r"(addr))
#define LDSM_X4_T(r0,r1,r2,r3, addr) \
    asm volatile("ldmatrix.sync.aligned.m8n8.x4.trans.shared.b16 {%0,%1,%2,%3}, [%4];" \
        : "=r"(r0),"=r"(r1),"=r"(r2),"=r"(r3) : "r"(addr))
#define MMA16816(c, a, b0, b1) \
    asm volatile("mma.sync.aligned.m16n8k16.row.col.f32.bf16.bf16.f32 " \
        "{%0,%1,%2,%3},{%4,%5,%6,%7},{%8,%9},{%0,%1,%2,%3};" \
        : "+f"((c)[0]),"+f"((c)[1]),"+f"((c)[2]),"+f"((c)[3]) \
        : "r"((a)[0]),"r"((a)[1]),"r"((a)[2]),"r"((a)[3]),"r"(b0),"r"(b1))
#define MMA16816H(c, a, b0, b1) \
    asm volatile("mma.sync.aligned.m16n8k16.row.col.f32.f16.f16.f32 " \
        "{%0,%1,%2,%3},{%4,%5,%6,%7},{%8,%9},{%0,%1,%2,%3};" \
        : "+f"((c)[0]),"+f"((c)[1]),"+f"((c)[2]),"+f"((c)[3]) \
        : "r"((a)[0]),"r"((a)[1]),"r"((a)[2]),"r"((a)[3]),"r"(b0),"r"(b1))

__device__ __forceinline__ uint32_t pack_half2(float lo, float hi) {
    __half2 t = __floats2half2_rn(lo, hi);
    return *reinterpret_cast<uint32_t*>(&t);
}

__device__ __forceinline__ void split4(float4 a, uint2& hv, uint2& lv) {
    __nv_bfloat16 h0 = __float2bfloat16(a.x);
    __nv_bfloat16 h1 = __float2bfloat16(a.y);
    __nv_bfloat16 h2 = __float2bfloat16(a.z);
    __nv_bfloat16 h3 = __float2bfloat16(a.w);
    __nv_bfloat16 l0 = __float2bfloat16(a.x - __bfloat162float(h0));
    __nv_bfloat16 l1 = __float2bfloat16(a.y - __bfloat162float(h1));
    __nv_bfloat16 l2 = __float2bfloat16(a.z - __bfloat162float(h2));
    __nv_bfloat16 l3 = __float2bfloat16(a.w - __bfloat162float(h3));
    hv = make_uint2(((uint32_t)__bfloat16_as_ushort(h1) << 16) | __bfloat16_as_ushort(h0),
                    ((uint32_t)__bfloat16_as_ushort(h3) << 16) | __bfloat16_as_ushort(h2));
    lv = make_uint2(((uint32_t)__bfloat16_as_ushort(l1) << 16) | __bfloat16_as_ushort(l0),
                    ((uint32_t)__bfloat16_as_ushort(l3) << 16) | __bfloat16_as_ushort(l2));
}
__device__ __forceinline__ void split4h(float4 a, uint2& hv, uint2& lv) {
    __half h0 = __float2half_rn(a.x);
    __half h1 = __float2half_rn(a.y);
    __half h2 = __float2half_rn(a.z);
    __half h3 = __float2half_rn(a.w);
    __half l0 = __float2half_rn(a.x - __half2float(h0));
    __half l1 = __float2half_rn(a.y - __half2float(h1));
    __half l2 = __float2half_rn(a.z - __half2float(h2));
    __half l3 = __float2half_rn(a.w - __half2float(h3));
    hv = make_uint2(((uint32_t)__half_as_ushort(h1) << 16) | __half_as_ushort(h0),
                    ((uint32_t)__half_as_ushort(h3) << 16) | __half_as_ushort(h2));
    lv = make_uint2(((uint32_t)__half_as_ushort(l1) << 16) | __half_as_ushort(l0),
                    ((uint32_t)__half_as_ushort(l3) << 16) | __half_as_ushort(l2));
}

__device__ __forceinline__ float fexp(float s) {
    float x = s * 1.4426950408889634f;
    float j = x + 12582912.0f;
    float xi = j - 12582912.0f;
    float f = x - xi;
    int e = __float_as_int(j) - 0x4B400000;
    float p = 1.3333558e-3f;
    p = fmaf(p, f, 9.6181291e-3f);
    p = fmaf(p, f, 5.5504109e-2f);
    p = fmaf(p, f, 2.4022651e-1f);
    p = fmaf(p, f, 6.9314718e-1f);
    p = fmaf(p, f, 1.0f);
    return p * __int_as_float((e + 127) << 23);
}

// ---------------------------------------------------------------------------
__global__ __launch_bounds__(256) void presplit_kernel(
    const float* __restrict__ q, const float* __restrict__ k,
    const float* __restrict__ v, const float* __restrict__ wq,
    const float* __restrict__ wk, const float* __restrict__ wv)
{
    const int t = blockIdx.y;
    const float* src = (t == 0) ? q : (t == 1) ? k : (t == 2) ? v
                     : (t == 3) ? wq : (t == 4) ? wk : wv;
    const size_t off = (t < 3) ? (size_t)t * NQ : 3 * (size_t)NQ + (size_t)(t - 3) * NW;
    const int n4 = ((t < 3) ? NQ : NW) >> 2;
    uint2* dh = (uint2*)(g_Ih + off);
    uint2* dl = (uint2*)(g_Il + off);
    for (int i = blockIdx.x * blockDim.x + threadIdx.x; i < n4;
         i += gridDim.x * blockDim.x) {
        float4 a = ((const float4*)src)[i];
        uint2 hv, lv; split4(a, hv, lv);
        dh[i] = hv; dl[i] = lv;
    }
}

// ===========================================================================
// Projection GEMM (R14 mainloop). Epilogue: Q/K split bf16; V split fp16.
// ===========================================================================
#define BK 32
#define LDA 40
#define ARR_B (128 * LDA * 2)
#define STAGE_B (4 * ARR_B)
#define PROJ_SMEM (2 * STAGE_B)

__global__ __launch_bounds__(256, 2) void proj_wmma_kernel()
{
    extern __shared__ char smem[];
    const int z = blockIdx.z;
    const __nv_bfloat16* Ah_g = g_Ih + (size_t)z * NQ;
    const __nv_bfloat16* Al_g = g_Il + (size_t)z * NQ;
    const __nv_bfloat16* Wh_g = g_Ih + 3 * (size_t)NQ + (size_t)z * NW;
    const __nv_bfloat16* Wl_g = g_Il + 3 * (size_t)NQ + (size_t)z * NW;

    const int tid = threadIdx.x;
    const int wid = tid >> 5;
    const int warp_m = wid >> 1;
    const int warp_n = wid & 1;
    const int m0 = blockIdx.y * 128;
    const int n0 = blockIdx.x * 128;
    const uint32_t sbase = smem_u32(smem);

    const int r0 = tid >> 2, c0 = tid & 3;
    const int r1 = (tid + 256) >> 2, c1 = (tid + 256) & 3;

    auto issue = [&](int stage, int c) {
        const int k0 = c * BK;
        uint32_t sb = sbase + stage * STAGE_B;
        const __nv_bfloat16* gp[4] = {
            Ah_g + (size_t)m0 * D_ + k0, Al_g + (size_t)m0 * D_ + k0,
            Wh_g + (size_t)n0 * D_ + k0, Wl_g + (size_t)n0 * D_ + k0 };
        #pragma unroll
        for (int a = 0; a < 4; a++) {
            CP_ASYNC16(sb + a * ARR_B + r0 * 80 + c0 * 16,
                       gp[a] + (size_t)r0 * D_ + c0 * 8);
            CP_ASYNC16(sb + a * ARR_B + r1 * 80 + c1 * 16,
                       gp[a] + (size_t)r1 * D_ + c1 * 8);
        }
        CP_COMMIT();
    };

    wmma::fragment<wmma::accumulator, 16, 16, 16, float> acc[2][4];
    #pragma unroll
    for (int i = 0; i < 2; i++)
        #pragma unroll
        for (int j = 0; j < 4; j++) wmma::fill_fragment(acc[i][j], 0.0f);

    issue(0, 0);

    for (int c = 0; c < D_ / BK; c++) {
        if (c < D_ / BK - 1) { issue((c + 1) & 1, c + 1); CP_WAIT(1); }
        else                 { CP_WAIT(0); }
        __syncthreads();

        const char* st = smem + (c & 1) * STAGE_B;
        const __nv_bfloat16* Ahs = (const __nv_bfloat16*)(st);
        const __nv_bfloat16* Als = (const __nv_bfloat16*)(st + ARR_B);
        const __nv_bfloat16* Whs = (const __nv_bfloat16*)(st + 2 * ARR_B);
        const __nv_bfloat16* Wls = (const __nv_bfloat16*)(st + 3 * ARR_B);

        #pragma unroll
        for (int kk = 0; kk < BK; kk += 16) {
            wmma::fragment<wmma::matrix_a, 16, 16, 16, __nv_bfloat16, wmma::row_major> aH[2], aL[2];
            #pragma unroll
            for (int i = 0; i < 2; i++) {
                wmma::load_matrix_sync(aH[i], &Ahs[(warp_m * 32 + i * 16) * LDA + kk], LDA);
                wmma::load_matrix_sync(aL[i], &Als[(warp_m * 32 + i * 16) * LDA + kk], LDA);
            }
            #pragma unroll
            for (int jp = 0; jp < 2; jp++) {
                wmma::fragment<wmma::matrix_b, 16, 16, 16, __nv_bfloat16, wmma::col_major> bH0, bL0, bH1, bL1;
                wmma::load_matrix_sync(bH0, &Whs[(warp_n * 64 + (2*jp+0) * 16) * LDA + kk], LDA);
                wmma::load_matrix_sync(bL0, &Wls[(warp_n * 64 + (2*jp+0) * 16) * LDA + kk], LDA);
                wmma::load_matrix_sync(bH1, &Whs[(warp_n * 64 + (2*jp+1) * 16) * LDA + kk], LDA);
                wmma::load_matrix_sync(bL1, &Wls[(warp_n * 64 + (2*jp+1) * 16) * LDA + kk], LDA);
                #pragma unroll
                for (int i = 0; i < 2; i++) {
                    wmma::mma_sync(acc[i][2*jp+0], aH[i], bH0, acc[i][2*jp+0]);
                    wmma::mma_sync(acc[i][2*jp+1], aH[i], bH1, acc[i][2*jp+1]);
                    wmma::mma_sync(acc[i][2*jp+0], aH[i], bL0, acc[i][2*jp+0]);
                    wmma::mma_sync(acc[i][2*jp+1], aH[i], bL1, acc[i][2*jp+1]);
                    wmma::mma_sync(acc[i][2*jp+0], aL[i], bH0, acc[i][2*jp+0]);
                    wmma::mma_sync(acc[i][2*jp+1], aL[i], bH1, acc[i][2*jp+1]);
                }
            }
        }
        __syncthreads();
    }

    float* st = (float*)smem;
    #pragma unroll
    for (int i = 0; i < 2; i++)
        #pragma unroll
        for (int j = 0; j < 4; j++)
            wmma::store_matrix_sync(&st[(warp_m * 32 + i * 16) * 132 + warp_n * 64 + j * 16],
                                    acc[i][j], 132, wmma::mem_row_major);
    __syncthreads();

    const int b = m0 >> 11;
    #pragma unroll
    for (int it = 0; it < 16; it++) {
        int idx = it * 256 + tid;
        int r = idx >> 5, c4 = idx & 31;
        float4 val = *reinterpret_cast<const float4*>(&st[r * 132 + c4 * 4]);
        int m = m0 + r;
        int s = m & (S_ - 1);
        int n = n0 + c4 * 4;
        int h = n >> 6, d0 = n & 63;
        size_t o = ((size_t)(b * H_ + h) * S_ + s) * HD_ + d0;
        if (z == 2) {
            uint2 hv, lv; split4h(val, hv, lv);
            *reinterpret_cast<uint2*>(g_Vh + o) = hv;
            *reinterpret_cast<uint2*>(g_Vl + o) = lv;
        } else {
            uint2 hv, lv; split4(val, hv, lv);
            __nv_bfloat16* outh = (z == 0) ? g_Qh : g_Kh;
            __nv_bfloat16* outl = (z == 0) ? g_Ql : g_Kl;
            *reinterpret_cast<uint2*>(outh + o) = hv;
            *reinterpret_cast<uint2*>(outl + o) = lv;
        }
    }
}

// ---------------------------------------------------------------------------
// Partial V column sums (fp16 hi+lo -> near-exact), 128 rows per block.
// ---------------------------------------------------------------------------
__global__ __launch_bounds__(64) void colsum_kernel()
{
    const int seg = blockIdx.x, bh = blockIdx.y, d = threadIdx.x;
    const size_t base = (size_t)bh * S_ * HD_ + (size_t)seg * 128 * HD_ + d;
    float acc = 0.f;
    #pragma unroll 8
    for (int s = 0; s < 128; s++) {
        acc += __half2float(g_Vh[base + (size_t)s * HD_])
             + __half2float(g_Vl[base + (size_t)s * HD_]);
    }
    g_TVp[(bh * 16 + seg) * 64 + d] = acc;
}

// ===========================================================================
// Register-resident flash attention. QK: bf16 3-term split (exact scores).
// PV: single fp16 (P and V), p' = exp(s)-1 identity:
//   O = (P'.V + TotalV)/Z,  Z = sum(p') + S.
// KV stage = {Kh, Kl (bf16), Vh (fp16)}: 3 arrays.
// ===========================================================================
#define ROWB 144
#define KTILE_B (64 * ROWB)
#define Q_B (128 * ROWB)
#define STG_B (3 * KTILE_B)
#define ATT_SMEM (2 * Q_B + 2 * STG_B)

__global__ __launch_bounds__(256, 2) void attn_mma_kernel(float* __restrict__ out)
{
    extern __shared__ char smem_raw[];
    __shared__ float sTV[64];
    const uint32_t sb = smem_u32(smem_raw);
    const uint32_t sQh = sb, sQl = sb + Q_B;
    const uint32_t sStage0 = sb + 2 * Q_B;

    const int tid = threadIdx.x;
    const int wid = tid >> 5;
    const int lane = tid & 31;
    const int pair = blockIdx.x;
    const int bh = blockIdx.y;
    const size_t bho = (size_t)bh * S_ * HD_;
    const int m0 = wid * 16;
    const int NT = S_ / 128;

    const int rA = ((lane >> 3) & 1) * 8 + (lane & 7);
    const int cA = ((lane >> 4) & 1) * 8;
    const int rK = ((lane >> 4) & 1) * 8 + (lane & 7);
    const int cK = ((lane >> 3) & 1) * 8;

    if (tid < 64) {
        float s = 0.f;
        #pragma unroll
        for (int g = 0; g < 16; g++) s += g_TVp[(bh * 16 + g) * 64 + tid];
        sTV[tid] = s;
    }

    auto issue_kv = [&](int stage, int kt) {
        uint32_t st = sStage0 + stage * STG_B;
        const size_t to = bho + (size_t)kt * 64 * HD_;
        const char* gp[3] = { (const char*)(g_Kh + to), (const char*)(g_Kl + to),
                              (const char*)(g_Vh + to) };
        #pragma unroll
        for (int i = 0; i < 6; i++) {
            int id = i * 256 + tid;            // 0..1535
            int arr = id >> 9;                 // 0..2
            int rem = id & 511;
            int r = rem >> 3, c = rem & 7;
            CP_ASYNC16(st + arr * KTILE_B + r * ROWB + c * 16, gp[arr] + (size_t)r * 128 + c * 16);
        }
        CP_COMMIT();
    };

    const int b = bh / H_, h = bh % H_;

    #pragma unroll 1
    for (int seg = 0; seg < 2; seg++) {
        const int qt = seg ? pair : (NT - 1 - pair);
        const int qbase = qt * 128;

        __syncthreads();

        #pragma unroll
        for (int i = 0; i < 8; i++) {
            int id = i * 256 + tid;
            int arr = id >> 10;
            int rem = id & 1023;
            int r = rem >> 3, c = rem & 7;
            const __nv_bfloat16* g = (arr ? g_Ql : g_Qh) + bho + (size_t)(qbase + r) * 64 + c * 8;
            CP_ASYNC16((arr ? sQl : sQh) + r * ROWB + c * 16, g);
        }
        CP_COMMIT();
        issue_kv(0, 0);

        CP_WAIT(1);
        __syncthreads();

        uint32_t qh[4][4];
        #pragma unroll
        for (int kc = 0; kc < 4; kc++)
            LDSM_X4(qh[kc][0], qh[kc][1], qh[kc][2], qh[kc][3],
                    sQh + (m0 + rA) * ROWB + (kc * 16 + cA) * 2);

        float oc[8][4];
        #pragma unroll
        for (int i = 0; i < 8; i++)
            #pragma unroll
            for (int j = 0; j < 4; j++) oc[i][j] = 0.f;
        float z0 = 0.f, z1 = 0.f;

        const int rowg0 = qbase + m0 + (lane >> 2);
        const int rowg1 = rowg0 + 8;
        const int ktmax = 2 * qt + 1;

        for (int kt = 0; kt <= ktmax; kt++) {
            CP_WAIT(0);
            __syncthreads();
            if (kt < ktmax) issue_kv((kt + 1) & 1, kt + 1);

            const uint32_t st = sStage0 + (kt & 1) * STG_B;
            const uint32_t stKh = st, stKl = st + KTILE_B;
            const uint32_t stVh = st + 2 * KTILE_B;

            uint32_t pah[4][4];
            const bool nomask = (kt * 64 + 63 <= qbase + m0);

            #pragma unroll
            for (int hhf = 0; hhf < 2; hhf++) {
                float sc[4][4];
                #pragma unroll
                for (int i = 0; i < 4; i++)
                    #pragma unroll
                    for (int j = 0; j < 4; j++) sc[i][j] = 0.f;

                #pragma unroll
                for (int kc = 0; kc < 4; kc++) {
                    uint32_t ql_[4];
                    LDSM_X4(ql_[0], ql_[1], ql_[2], ql_[3],
                            sQl + (m0 + rA) * ROWB + (kc * 16 + cA) * 2);
                    uint32_t b00, b01, b02, b03, b10, b11, b12, b13;
                    int ng0 = 2 * hhf;
                    LDSM_X4(b00, b01, b02, b03, stKh + (ng0 * 16 + rK) * ROWB + (kc * 16 + cK) * 2);
                    LDSM_X4(b10, b11, b12, b13, stKl + (ng0 * 16 + rK) * ROWB + (kc * 16 + cK) * 2);
                    MMA16816(sc[0], qh[kc], b00, b01);
                    MMA16816(sc[1], qh[kc], b02, b03);
                    MMA16816(sc[0], qh[kc], b10, b11);
                    MMA16816(sc[1], qh[kc], b12, b13);
                    MMA16816(sc[0], ql_,    b00, b01);
                    MMA16816(sc[1], ql_,    b02, b03);
                    int ng1 = 2 * hhf + 1;
                    LDSM_X4(b00, b01, b02, b03, stKh + (ng1 * 16 + rK) * ROWB + (kc * 16 + cK) * 2);
                    LDSM_X4(b10, b11, b12, b13, stKl + (ng1 * 16 + rK) * ROWB + (kc * 16 + cK) * 2);
                    MMA16816(sc[2], qh[kc], b00, b01);
                    MMA16816(sc[3], qh[kc], b02, b03);
                    MMA16816(sc[2], qh[kc], b10, b11);
                    MMA16816(sc[3], qh[kc], b12, b13);
                    MMA16816(sc[2], ql_,    b00, b01);
                    MMA16816(sc[3], ql_,    b02, b03);
                }

                const int colb = kt * 64 + 2 * (lane & 3);
                #pragma unroll
                for (int j = 0; j < 4; j++) {
                    int nt = 4 * hhf + j;
                    int col0 = colb + nt * 8;
                    float p00, p01, p10, p11;
                    if (nomask) {
                        p00 = fexp(sc[j][0] * 0.125f) - 1.0f;
                        p01 = fexp(sc[j][1] * 0.125f) - 1.0f;
                        p10 = fexp(sc[j][2] * 0.125f) - 1.0f;
                        p11 = fexp(sc[j][3] * 0.125f) - 1.0f;
                    } else {
                        p00 = (col0     <= rowg0) ? fexp(sc[j][0] * 0.125f) - 1.0f : 0.f;
                        p01 = (col0 + 1 <= rowg0) ? fexp(sc[j][1] * 0.125f) - 1.0f : 0.f;
                        p10 = (col0     <= rowg1) ? fexp(sc[j][2] * 0.125f) - 1.0f : 0.f;
                        p11 = (col0 + 1 <= rowg1) ? fexp(sc[j][3] * 0.125f) - 1.0f : 0.f;
                    }
                    z0 += p00 + p01;
                    z1 += p10 + p11;
                    int kcp = 2 * hhf + (j >> 1), hf = (j & 1) * 2;
                    pah[kcp][hf + 0] = pack_half2(p00, p01);
                    pah[kcp][hf + 1] = pack_half2(p10, p11);
                }
            }

            // ---- O += P.V, single fp16 term, interleaved dg pair ----
            #pragma unroll
            for (int kc = 0; kc < 4; kc++) {
                #pragma unroll
                for (int dp = 0; dp < 2; dp++) {
                    uint32_t a00, a01, a02, a03, c00, c01, c02, c03;
                    int dg0 = 2 * dp, dg1 = 2 * dp + 1;
                    LDSM_X4_T(a00, a01, a02, a03, stVh + (kc * 16 + rA) * ROWB + (dg0 * 16 + cA) * 2);
                    LDSM_X4_T(c00, c01, c02, c03, stVh + (kc * 16 + rA) * ROWB + (dg1 * 16 + cA) * 2);
                    MMA16816H(oc[2 * dg0],     pah[kc], a00, a01);
                    MMA16816H(oc[2 * dg1],     pah[kc], c00, c01);
                    MMA16816H(oc[2 * dg0 + 1], pah[kc], a02, a03);
                    MMA16816H(oc[2 * dg1 + 1], pah[kc], c02, c03);
                }
            }
        }

        z0 += __shfl_xor_sync(0xffffffffu, z0, 1);
        z0 += __shfl_xor_sync(0xffffffffu, z0, 2);
        z1 += __shfl_xor_sync(0xffffffffu, z1, 1);
        z1 += __shfl_xor_sync(0xffffffffu, z1, 2);
        float inv0 = 1.f / (z0 + (float)S_);
        float inv1 = 1.f / (z1 + (float)S_);

        #pragma unroll
        for (int nt = 0; nt < 8; nt++) {
            int d = nt * 8 + 2 * (lane & 3);
            float2 tv = *reinterpret_cast<const float2*>(&sTV[d]);
            float2 o0 = make_float2((oc[nt][0] + tv.x) * inv0, (oc[nt][1] + tv.y) * inv0);
            float2 o1 = make_float2((oc[nt][2] + tv.x) * inv1, (oc[nt][3] + tv.y) * inv1);
            *reinterpret_cast<float2*>(&out[((size_t)(b * S_ + rowg0)) * D_ + h * 64 + d]) = o0;
            *reinterpret_cast<float2*>(&out[((size_t)(b * S_ + rowg1)) * D_ + h * 64 + d]) = o1;
        }
    }
}

// ---------------------------------------------------------------------------
extern "C" void kernel_launch(void* const* d_in, const int* in_sizes, int n_in,
                              void* d_out, int out_size)
{
    const float* q  = (const float*)d_in[0];
    const float* k  = (const float*)d_in[1];
    const float* v  = (const float*)d_in[2];
    const float* wq = (const float*)d_in[3];
    const float* wk = (const float*)d_in[4];
    const float* wv = (const float*)d_in[5];
    float* out = (float*)d_out;

    presplit_kernel<<<dim3(256, 6), 256>>>(q, k, v, wq, wk, wv);

    cudaFuncSetAttribute(proj_wmma_kernel,
                         cudaFuncAttributeMaxDynamicSharedMemorySize, PROJ_SMEM);
    proj_wmma_kernel<<<dim3(D_ / 128, (B_ * S_) / 128, 3), 256, PROJ_SMEM>>>();

    colsum_kernel<<<dim3(16, B_ * H_), 64>>>();

    cudaFuncSetAttribute(attn_mma_kernel,
                         cudaFuncAttributeMaxDynamicSharedMemorySize, ATT_SMEM);
    attn_mma_kernel<<<dim3(S_ / 256, B_ * H_), 256, ATT_SMEM>>>(out);
}

// round 17
// speedup vs baseline: 2.8127x; 1.0424x over previous
#include <cuda_runtime.h>
#include <cuda_bf16.h>
#include <cuda_fp16.h>
#include <mma.h>
#include <cstdint>
#include <math.h>

using namespace nvcuda;

#define B_  2
#define S_  2048
#define D_  1024
#define H_  16
#define HD_ 64
#define NQ (B_*S_*D_)
#define NW (D_*D_)
#define NP (B_*H_*S_*HD_)

__device__ __nv_bfloat16 g_Ih[3*NQ + 3*NW];
__device__ __nv_bfloat16 g_Il[3*NQ + 3*NW];
__device__ __half g_Qh[NP];                 // Q' single fp16
__device__ __half g_Kh[NP], g_Kl[NP];       // K' split fp16
__device__ __half g_Vh[NP], g_Vl[NP];       // V' split fp16 (PV uses hi only)
__device__ float g_TVp[32*16*64];           // per-(bh, seg-of-128) V col partials

// ---------------------------------------------------------------------------
__device__ __forceinline__ uint32_t smem_u32(const void* p) {
    uint32_t a;
    asm("{ .reg .u64 t; cvta.to.shared.u64 t, %1; cvt.u32.u64 %0, t; }"
        : "=r"(a) : "l"(p));
    return a;
}
#define CP_ASYNC16(dst, src) \
    asm volatile("cp.async.cg.shared.global [%0], [%1], 16;" :: "r"(dst), "l"(src))
#define CP_COMMIT() asm volatile("cp.async.commit_group;")
#define CP_WAIT(n)  asm volatile("cp.async.wait_group %0;" :: "n"(n))

#define LDSM_X4(r0,r1,r2,r3, addr) \
    asm volatile("ldmatrix.sync.aligned.m8n8.x4.shared.b16 {%0,%1,%2,%3}, [%4];" \
        : "=r"(r0),"=r"(r1),"=r"(r2),"=r"(r3) : "r"(addr))
#define LDSM_X4_T(r0,r1,r2,r3, addr) \
    asm volatile("ldmatrix.sync.aligned.m8n8.x4.trans.shared.b16 {%0,%1,%2,%3}, [%4];" \
        : "=r"(r0),"=r"(r1),"=r"(r2),"=r"(r3) : "r"(addr))
#define MMA16816(c, a, b0, b1) \
    asm volatile("mma.sync.aligned.m16n8k16.row.col.f32.bf16.bf16.f32 " \
        "{%0,%1,%2,%3},{%4,%5,%6,%7},{%8,%9},{%0,%1,%2,%3};" \
        : "+f"((c)[0]),"+f"((c)[1]),"+f"((c)[2]),"+f"((c)[3]) \
        : "r"((a)[0]),"r"((a)[1]),"r"((a)[2]),"r"((a)[3]),"r"(b0),"r"(b1))
#define MMA16816H(c, a, b0, b1) \
    asm volatile("mma.sync.aligned.m16n8k16.row.col.f32.f16.f16.f32 " \
        "{%0,%1,%2,%3},{%4,%5,%6,%7},{%8,%9},{%0,%1,%2,%3};" \
        : "+f"((c)[0]),"+f"((c)[1]),"+f"((c)[2]),"+f"((c)[3]) \
        : "r"((a)[0]),"r"((a)[1]),"r"((a)[2]),"r"((a)[3]),"r"(b0),"r"(b1))

__device__ __forceinline__ uint32_t pack_half2(float lo, float hi) {
    __half2 t = __floats2half2_rn(lo, hi);
    return *reinterpret_cast<uint32_t*>(&t);
}

__device__ __forceinline__ void split4(float4 a, uint2& hv, uint2& lv) {
    __nv_bfloat16 h0 = __float2bfloat16(a.x);
    __nv_bfloat16 h1 = __float2bfloat16(a.y);
    __nv_bfloat16 h2 = __float2bfloat16(a.z);
    __nv_bfloat16 h3 = __float2bfloat16(a.w);
    __nv_bfloat16 l0 = __float2bfloat16(a.x - __bfloat162float(h0));
    __nv_bfloat16 l1 = __float2bfloat16(a.y - __bfloat162float(h1));
    __nv_bfloat16 l2 = __float2bfloat16(a.z - __bfloat162float(h2));
    __nv_bfloat16 l3 = __float2bfloat16(a.w - __bfloat162float(h3));
    hv = make_uint2(((uint32_t)__bfloat16_as_ushort(h1) << 16) | __bfloat16_as_ushort(h0),
                    ((uint32_t)__bfloat16_as_ushort(h3) << 16) | __bfloat16_as_ushort(h2));
    lv = make_uint2(((uint32_t)__bfloat16_as_ushort(l1) << 16) | __bfloat16_as_ushort(l0),
                    ((uint32_t)__bfloat16_as_ushort(l3) << 16) | __bfloat16_as_ushort(l2));
}
__device__ __forceinline__ void split4h(float4 a, uint2& hv, uint2& lv) {
    __half h0 = __float2half_rn(a.x);
    __half h1 = __float2half_rn(a.y);
    __half h2 = __float2half_rn(a.z);
    __half h3 = __float2half_rn(a.w);
    __half l0 = __float2half_rn(a.x - __half2float(h0));
    __half l1 = __float2half_rn(a.y - __half2float(h1));
    __half l2 = __float2half_rn(a.z - __half2float(h2));
    __half l3 = __float2half_rn(a.w - __half2float(h3));
    hv = make_uint2(((uint32_t)__half_as_ushort(h1) << 16) | __half_as_ushort(h0),
                    ((uint32_t)__half_as_ushort(h3) << 16) | __half_as_ushort(h2));
    lv = make_uint2(((uint32_t)__half_as_ushort(l1) << 16) | __half_as_ushort(l0),
                    ((uint32_t)__half_as_ushort(l3) << 16) | __half_as_ushort(l2));
}

__device__ __forceinline__ float fexp(float s) {
    float x = s * 1.4426950408889634f;
    float j = x + 12582912.0f;
    float xi = j - 12582912.0f;
    float f = x - xi;
    int e = __float_as_int(j) - 0x4B400000;
    float p = 1.3333558e-3f;
    p = fmaf(p, f, 9.6181291e-3f);
    p = fmaf(p, f, 5.5504109e-2f);
    p = fmaf(p, f, 2.4022651e-1f);
    p = fmaf(p, f, 6.9314718e-1f);
    p = fmaf(p, f, 1.0f);
    return p * __int_as_float((e + 127) << 23);
}

// ---------------------------------------------------------------------------
__global__ __launch_bounds__(256) void presplit_kernel(
    const float* __restrict__ q, const float* __restrict__ k,
    const float* __restrict__ v, const float* __restrict__ wq,
    const float* __restrict__ wk, const float* __restrict__ wv)
{
    const int t = blockIdx.y;
    const float* src = (t == 0) ? q : (t == 1) ? k : (t == 2) ? v
                     : (t == 3) ? wq : (t == 4) ? wk : wv;
    const size_t off = (t < 3) ? (size_t)t * NQ : 3 * (size_t)NQ + (size_t)(t - 3) * NW;
    const int n4 = ((t < 3) ? NQ : NW) >> 2;
    uint2* dh = (uint2*)(g_Ih + off);
    uint2* dl = (uint2*)(g_Il + off);
    for (int i = blockIdx.x * blockDim.x + threadIdx.x; i < n4;
         i += gridDim.x * blockDim.x) {
        float4 a = ((const float4*)src)[i];
        uint2 hv, lv; split4(a, hv, lv);
        dh[i] = hv; dl[i] = lv;
    }
}

// ===========================================================================
// Projection GEMM (R14 mainloop, exact bf16 3-term split).
// Epilogue: Q -> single fp16; K,V -> fp16 hi/lo split.
// ===========================================================================
#define BK 32
#define LDA 40
#define ARR_B (128 * LDA * 2)
#define STAGE_B (4 * ARR_B)
#define PROJ_SMEM (2 * STAGE_B)

__global__ __launch_bounds__(256, 2) void proj_wmma_kernel()
{
    extern __shared__ char smem[];
    const int z = blockIdx.z;
    const __nv_bfloat16* Ah_g = g_Ih + (size_t)z * NQ;
    const __nv_bfloat16* Al_g = g_Il + (size_t)z * NQ;
    const __nv_bfloat16* Wh_g = g_Ih + 3 * (size_t)NQ + (size_t)z * NW;
    const __nv_bfloat16* Wl_g = g_Il + 3 * (size_t)NQ + (size_t)z * NW;

    const int tid = threadIdx.x;
    const int wid = tid >> 5;
    const int warp_m = wid >> 1;
    const int warp_n = wid & 1;
    const int m0 = blockIdx.y * 128;
    const int n0 = blockIdx.x * 128;
    const uint32_t sbase = smem_u32(smem);

    const int r0 = tid >> 2, c0 = tid & 3;
    const int r1 = (tid + 256) >> 2, c1 = (tid + 256) & 3;

    auto issue = [&](int stage, int c) {
        const int k0 = c * BK;
        uint32_t sb = sbase + stage * STAGE_B;
        const __nv_bfloat16* gp[4] = {
            Ah_g + (size_t)m0 * D_ + k0, Al_g + (size_t)m0 * D_ + k0,
            Wh_g + (size_t)n0 * D_ + k0, Wl_g + (size_t)n0 * D_ + k0 };
        #pragma unroll
        for (int a = 0; a < 4; a++) {
            CP_ASYNC16(sb + a * ARR_B + r0 * 80 + c0 * 16,
                       gp[a] + (size_t)r0 * D_ + c0 * 8);
            CP_ASYNC16(sb + a * ARR_B + r1 * 80 + c1 * 16,
                       gp[a] + (size_t)r1 * D_ + c1 * 8);
        }
        CP_COMMIT();
    };

    wmma::fragment<wmma::accumulator, 16, 16, 16, float> acc[2][4];
    #pragma unroll
    for (int i = 0; i < 2; i++)
        #pragma unroll
        for (int j = 0; j < 4; j++) wmma::fill_fragment(acc[i][j], 0.0f);

    issue(0, 0);

    for (int c = 0; c < D_ / BK; c++) {
        if (c < D_ / BK - 1) { issue((c + 1) & 1, c + 1); CP_WAIT(1); }
        else                 { CP_WAIT(0); }
        __syncthreads();

        const char* st = smem + (c & 1) * STAGE_B;
        const __nv_bfloat16* Ahs = (const __nv_bfloat16*)(st);
        const __nv_bfloat16* Als = (const __nv_bfloat16*)(st + ARR_B);
        const __nv_bfloat16* Whs = (const __nv_bfloat16*)(st + 2 * ARR_B);
        const __nv_bfloat16* Wls = (const __nv_bfloat16*)(st + 3 * ARR_B);

        #pragma unroll
        for (int kk = 0; kk < BK; kk += 16) {
            wmma::fragment<wmma::matrix_a, 16, 16, 16, __nv_bfloat16, wmma::row_major> aH[2], aL[2];
            #pragma unroll
            for (int i = 0; i < 2; i++) {
                wmma::load_matrix_sync(aH[i], &Ahs[(warp_m * 32 + i * 16) * LDA + kk], LDA);
                wmma::load_matrix_sync(aL[i], &Als[(warp_m * 32 + i * 16) * LDA + kk], LDA);
            }
            #pragma unroll
            for (int jp = 0; jp < 2; jp++) {
                wmma::fragment<wmma::matrix_b, 16, 16, 16, __nv_bfloat16, wmma::col_major> bH0, bL0, bH1, bL1;
                wmma::load_matrix_sync(bH0, &Whs[(warp_n * 64 + (2*jp+0) * 16) * LDA + kk], LDA);
                wmma::load_matrix_sync(bL0, &Wls[(warp_n * 64 + (2*jp+0) * 16) * LDA + kk], LDA);
                wmma::load_matrix_sync(bH1, &Whs[(warp_n * 64 + (2*jp+1) * 16) * LDA + kk], LDA);
                wmma::load_matrix_sync(bL1, &Wls[(warp_n * 64 + (2*jp+1) * 16) * LDA + kk], LDA);
                #pragma unroll
                for (int i = 0; i < 2; i++) {
                    wmma::mma_sync(acc[i][2*jp+0], aH[i], bH0, acc[i][2*jp+0]);
                    wmma::mma_sync(acc[i][2*jp+1], aH[i], bH1, acc[i][2*jp+1]);
                    wmma::mma_sync(acc[i][2*jp+0], aH[i], bL0, acc[i][2*jp+0]);
                    wmma::mma_sync(acc[i][2*jp+1], aH[i], bL1, acc[i][2*jp+1]);
                    wmma::mma_sync(acc[i][2*jp+0], aL[i], bH0, acc[i][2*jp+0]);
                    wmma::mma_sync(acc[i][2*jp+1], aL[i], bH1, acc[i][2*jp+1]);
                }
            }
        }
        __syncthreads();
    }

    float* st = (float*)smem;
    #pragma unroll
    for (int i = 0; i < 2; i++)
        #pragma unroll
        for (int j = 0; j < 4; j++)
            wmma::store_matrix_sync(&st[(warp_m * 32 + i * 16) * 132 + warp_n * 64 + j * 16],
                                    acc[i][j], 132, wmma::mem_row_major);
    __syncthreads();

    const int b = m0 >> 11;
    #pragma unroll
    for (int it = 0; it < 16; it++) {
        int idx = it * 256 + tid;
        int r = idx >> 5, c4 = idx & 31;
        float4 val = *reinterpret_cast<const float4*>(&st[r * 132 + c4 * 4]);
        int m = m0 + r;
        int s = m & (S_ - 1);
        int n = n0 + c4 * 4;
        int h = n >> 6, d0 = n & 63;
        size_t o = ((size_t)(b * H_ + h) * S_ + s) * HD_ + d0;
        if (z == 0) {
            __half2 a = __floats2half2_rn(val.x, val.y);
            __half2 bq = __floats2half2_rn(val.z, val.w);
            uint2 hv = make_uint2(*reinterpret_cast<uint32_t*>(&a),
                                  *reinterpret_cast<uint32_t*>(&bq));
            *reinterpret_cast<uint2*>(g_Qh + o) = hv;
        } else {
            uint2 hv, lv; split4h(val, hv, lv);
            __half* outh = (z == 1) ? g_Kh : g_Vh;
            __half* outl = (z == 1) ? g_Kl : g_Vl;
            *reinterpret_cast<uint2*>(outh + o) = hv;
            *reinterpret_cast<uint2*>(outl + o) = lv;
        }
    }
}

// ---------------------------------------------------------------------------
// Partial V column sums (fp16 hi+lo -> near-exact), 128 rows per block.
// ---------------------------------------------------------------------------
__global__ __launch_bounds__(64) void colsum_kernel()
{
    const int seg = blockIdx.x, bh = blockIdx.y, d = threadIdx.x;
    const size_t base = (size_t)bh * S_ * HD_ + (size_t)seg * 128 * HD_ + d;
    float acc = 0.f;
    #pragma unroll 8
    for (int s = 0; s < 128; s++) {
        acc += __half2float(g_Vh[base + (size_t)s * HD_])
             + __half2float(g_Vl[base + (size_t)s * HD_]);
    }
    g_TVp[(bh * 16 + seg) * 64 + d] = acc;
}

// ===========================================================================
// Register-resident flash attention.
// QK: Q single fp16 (in regs, persistent), K fp16 hi/lo split -> 2 fp16 MMAs.
// PV: single fp16. p' = exp(s)-1 identity: O = (P'.V + TotalV)/Z, Z = z'+S.
// Stage = {Kh, Kl, Vh} fp16.
// ===========================================================================
#define ROWB 144
#define KTILE_B (64 * ROWB)
#define Q_B (128 * ROWB)
#define STG_B (3 * KTILE_B)
#define ATT_SMEM (Q_B + 2 * STG_B)

__global__ __launch_bounds__(256, 2) void attn_mma_kernel(float* __restrict__ out)
{
    extern __shared__ char smem_raw[];
    __shared__ float sTV[64];
    const uint32_t sb = smem_u32(smem_raw);
    const uint32_t sQ = sb;
    const uint32_t sStage0 = sb + Q_B;

    const int tid = threadIdx.x;
    const int wid = tid >> 5;
    const int lane = tid & 31;
    const int pair = blockIdx.x;
    const int bh = blockIdx.y;
    const size_t bho = (size_t)bh * S_ * HD_;
    const int m0 = wid * 16;
    const int NT = S_ / 128;

    const int rA = ((lane >> 3) & 1) * 8 + (lane & 7);
    const int cA = ((lane >> 4) & 1) * 8;
    const int rK = ((lane >> 4) & 1) * 8 + (lane & 7);
    const int cK = ((lane >> 3) & 1) * 8;

    if (tid < 64) {
        float s = 0.f;
        #pragma unroll
        for (int g = 0; g < 16; g++) s += g_TVp[(bh * 16 + g) * 64 + tid];
        sTV[tid] = s;
    }

    auto issue_kv = [&](int stage, int kt) {
        uint32_t st = sStage0 + stage * STG_B;
        const size_t to = bho + (size_t)kt * 64 * HD_;
        const char* gp[3] = { (const char*)(g_Kh + to), (const char*)(g_Kl + to),
                              (const char*)(g_Vh + to) };
        #pragma unroll
        for (int i = 0; i < 6; i++) {
            int id = i * 256 + tid;
            int arr = id >> 9;
            int rem = id & 511;
            int r = rem >> 3, c = rem & 7;
            CP_ASYNC16(st + arr * KTILE_B + r * ROWB + c * 16, gp[arr] + (size_t)r * 128 + c * 16);
        }
        CP_COMMIT();
    };

    const int b = bh / H_, h = bh % H_;

    #pragma unroll 1
    for (int seg = 0; seg < 2; seg++) {
        const int qt = seg ? pair : (NT - 1 - pair);
        const int qbase = qt * 128;

        __syncthreads();

        // Q: single fp16 array, 1024 chunks, 4 per thread.
        #pragma unroll
        for (int i = 0; i < 4; i++) {
            int id = i * 256 + tid;
            int r = id >> 3, c = id & 7;
            CP_ASYNC16(sQ + r * ROWB + c * 16,
                       (const char*)(g_Qh + bho + (size_t)(qbase + r) * 64) + c * 16);
        }
        CP_COMMIT();
        issue_kv(0, 0);

        CP_WAIT(1);
        __syncthreads();

        uint32_t qh[4][4];
        #pragma unroll
        for (int kc = 0; kc < 4; kc++)
            LDSM_X4(qh[kc][0], qh[kc][1], qh[kc][2], qh[kc][3],
                    sQ + (m0 + rA) * ROWB + (kc * 16 + cA) * 2);

        float oc[8][4];
        #pragma unroll
        for (int i = 0; i < 8; i++)
            #pragma unroll
            for (int j = 0; j < 4; j++) oc[i][j] = 0.f;
        float z0 = 0.f, z1 = 0.f;

        const int rowg0 = qbase + m0 + (lane >> 2);
        const int rowg1 = rowg0 + 8;
        const int ktmax = 2 * qt + 1;

        for (int kt = 0; kt <= ktmax; kt++) {
            CP_WAIT(0);
            __syncthreads();
            if (kt < ktmax) issue_kv((kt + 1) & 1, kt + 1);

            const uint32_t st = sStage0 + (kt & 1) * STG_B;
            const uint32_t stKh = st, stKl = st + KTILE_B;
            const uint32_t stVh = st + 2 * KTILE_B;

            // ---- S = Q.K^T : 2 fp16 terms (Q.Kh + Q.Kl) ----
            float sc[8][4];
            #pragma unroll
            for (int i = 0; i < 8; i++)
                #pragma unroll
                for (int j = 0; j < 4; j++) sc[i][j] = 0.f;

            #pragma unroll
            for (int kc = 0; kc < 4; kc++) {
                #pragma unroll
                for (int ng = 0; ng < 4; ng++) {
                    uint32_t b00, b01, b02, b03, b10, b11, b12, b13;
                    LDSM_X4(b00, b01, b02, b03, stKh + (ng * 16 + rK) * ROWB + (kc * 16 + cK) * 2);
                    LDSM_X4(b10, b11, b12, b13, stKl + (ng * 16 + rK) * ROWB + (kc * 16 + cK) * 2);
                    MMA16816H(sc[2 * ng],     qh[kc], b00, b01);
                    MMA16816H(sc[2 * ng + 1], qh[kc], b02, b03);
                    MMA16816H(sc[2 * ng],     qh[kc], b10, b11);
                    MMA16816H(sc[2 * ng + 1], qh[kc], b12, b13);
                }
            }

            // ---- exp/mask/Z; pack P fp16 ----
            uint32_t pah[4][4];
            const bool nomask = (kt * 64 + 63 <= qbase + m0);
            const int colb = kt * 64 + 2 * (lane & 3);
            #pragma unroll
            for (int nt = 0; nt < 8; nt++) {
                int col0 = colb + nt * 8;
                float p00, p01, p10, p11;
                if (nomask) {
                    p00 = fexp(sc[nt][0] * 0.125f) - 1.0f;
                    p01 = fexp(sc[nt][1] * 0.125f) - 1.0f;
                    p10 = fexp(sc[nt][2] * 0.125f) - 1.0f;
                    p11 = fexp(sc[nt][3] * 0.125f) - 1.0f;
                } else {
                    p00 = (col0     <= rowg0) ? fexp(sc[nt][0] * 0.125f) - 1.0f : 0.f;
                    p01 = (col0 + 1 <= rowg0) ? fexp(sc[nt][1] * 0.125f) - 1.0f : 0.f;
                    p10 = (col0     <= rowg1) ? fexp(sc[nt][2] * 0.125f) - 1.0f : 0.f;
                    p11 = (col0 + 1 <= rowg1) ? fexp(sc[nt][3] * 0.125f) - 1.0f : 0.f;
                }
                z0 += p00 + p01;
                z1 += p10 + p11;
                int kcp = nt >> 1, hf = (nt & 1) * 2;
                pah[kcp][hf + 0] = pack_half2(p00, p01);
                pah[kcp][hf + 1] = pack_half2(p10, p11);
            }

            // ---- O += P.V, single fp16 term, interleaved dg pair ----
            #pragma unroll
            for (int kc = 0; kc < 4; kc++) {
                #pragma unroll
                for (int dp = 0; dp < 2; dp++) {
                    uint32_t a00, a01, a02, a03, c00, c01, c02, c03;
                    int dg0 = 2 * dp, dg1 = 2 * dp + 1;
                    LDSM_X4_T(a00, a01, a02, a03, stVh + (kc * 16 + rA) * ROWB + (dg0 * 16 + cA) * 2);
                    LDSM_X4_T(c00, c01, c02, c03, stVh + (kc * 16 + rA) * ROWB + (dg1 * 16 + cA) * 2);
                    MMA16816H(oc[2 * dg0],     pah[kc], a00, a01);
                    MMA16816H(oc[2 * dg1],     pah[kc], c00, c01);
                    MMA16816H(oc[2 * dg0 + 1], pah[kc], a02, a03);
                    MMA16816H(oc[2 * dg1 + 1], pah[kc], c02, c03);
                }
            }
        }

        z0 += __shfl_xor_sync(0xffffffffu, z0, 1);
        z0 += __shfl_xor_sync(0xffffffffu, z0, 2);
        z1 += __shfl_xor_sync(0xffffffffu, z1, 1);
        z1 += __shfl_xor_sync(0xffffffffu, z1, 2);
        float inv0 = 1.f / (z0 + (float)S_);
        float inv1 = 1.f / (z1 + (float)S_);

        #pragma unroll
        for (int nt = 0; nt < 8; nt++) {
            int d = nt * 8 + 2 * (lane & 3);
            float2 tv = *reinterpret_cast<const float2*>(&sTV[d]);
            float2 o0 = make_float2((oc[nt][0] + tv.x) * inv0, (oc[nt][1] + tv.y) * inv0);
            float2 o1 = make_float2((oc[nt][2] + tv.x) * inv1, (oc[nt][3] + tv.y) * inv1);
            *reinterpret_cast<float2*>(&out[((size_t)(b * S_ + rowg0)) * D_ + h * 64 + d]) = o0;
            *reinterpret_cast<float2*>(&out[((size_t)(b * S_ + rowg1)) * D_ + h * 64 + d]) = o1;
        }
    }
}

// ---------------------------------------------------------------------------
extern "C" void kernel_launch(void* const* d_in, const int* in_sizes, int n_in,
                              void* d_out, int out_size)
{
    const float* q  = (const float*)d_in[0];
    const float* k  = (const float*)d_in[1];
    const float* v  = (const float*)d_in[2];
    const float* wq = (const float*)d_in[3];
    const float* wk = (const float*)d_in[4];
    const float* wv = (const float*)d_in[5];
    float* out = (float*)d_out;

    presplit_kernel<<<dim3(256, 6), 256>>>(q, k, v, wq, wk, wv);

    cudaFuncSetAttribute(proj_wmma_kernel,
                         cudaFuncAttributeMaxDynamicSharedMemorySize, PROJ_SMEM);
    proj_wmma_kernel<<<dim3(D_ / 128, (B_ * S_) / 128, 3), 256, PROJ_SMEM>>>();

    colsum_kernel<<<dim3(16, B_ * H_), 64>>>();

    cudaFuncSetAttribute(attn_mma_kernel,
                         cudaFuncAttributeMaxDynamicSharedMemorySize, ATT_SMEM);
    attn_mma_kernel<<<dim3(S_ / 256, B_ * H_), 256, ATT_SMEM>>>(out);
}